// round 9
// baseline (speedup 1.0000x reference)
#include <cuda_runtime.h>
#include <cuda_fp16.h>
#include <cstdint>
#include <math.h>

// Problem dims
#define BB   4
#define SS   1024
#define DD   1024
#define HH   16
#define DH   64
#define RR   64
#define DFFN 4096
#define NTOK (BB*SS)       // 4096
#define KSEL 204           // int(1024*0.2)

// ---------------- scratch (device globals) ----------------
__device__ __half g_hw_in[(long)3 * DD * DD];
__device__ __half g_hw_out[(long)DD * DD];
__device__ __half g_hw_Vp[(long)DD * DD];
__device__ __half g_hw_f1[(long)DFFN * DD];
__device__ __half g_hw_f2[(long)DD * DFFN];
__device__ __half g_hw_QK[2 * RR * DD];          // packed [Qp_w; Kp_w]
__device__ float  g_bias_QK[2 * RR];
__device__ __half g_src_h[(long)NTOK * DD];
__device__ __half g_qkv_h[(long)NTOK * 3 * DD];
__device__ __half g_ctx_h[(long)NTOK * DD];
__device__ __half g_QKlr_h[(long)NTOK * 2 * RR];
__device__ __half g_Vlr_h[(long)NTOK * DD];
__device__ __half g_Vt_h[(long)NTOK * DD];
__device__ __half g_Ph[(long)BB * SS * SS];
__device__ __half g_x_h[(long)NTOK * DD];
__device__ __half g_h1_h[(long)NTOK * DFFN];
__device__ float g_P[(long)BB * SS * SS];
__device__ float g_dense[(long)NTOK * DD];
__device__ float g_sparse[(long)NTOK * DD];
__device__ float g_x[(long)NTOK * DD];
__device__ float g_ff[(long)NTOK * DD];

// ======================= helpers =======================
__device__ __forceinline__ uint32_t smem_u32(const void* p) {
    uint32_t a;
    asm("{ .reg .u64 t; cvta.to.shared.u64 t, %1; cvt.u32.u64 %0, t; }" : "=r"(a) : "l"(p));
    return a;
}
__device__ __forceinline__ void cp16(uint32_t saddr, const void* g) {
    asm volatile("cp.async.ca.shared.global [%0], [%1], 16;"
                 :: "r"(saddr), "l"(g) : "memory");
}
#define CP_COMMIT() asm volatile("cp.async.commit_group;" ::: "memory")
#define CP_WAIT2()  asm volatile("cp.async.wait_group 2;" ::: "memory")
#define CP_WAIT1()  asm volatile("cp.async.wait_group 1;" ::: "memory")
#define CP_WAIT0()  asm volatile("cp.async.wait_group 0;" ::: "memory")

__device__ __forceinline__ void mma_f16(float* c, const uint32_t* a, const uint32_t* b) {
    asm volatile(
        "mma.sync.aligned.m16n8k16.row.col.f32.f16.f16.f32 "
        "{%0,%1,%2,%3}, {%4,%5,%6,%7}, {%8,%9}, {%0,%1,%2,%3};"
        : "+f"(c[0]), "+f"(c[1]), "+f"(c[2]), "+f"(c[3])
        : "r"(a[0]), "r"(a[1]), "r"(a[2]), "r"(a[3]), "r"(b[0]), "r"(b[1]));
}
__device__ __forceinline__ void ldsm_x4(uint32_t* r, uint32_t saddr) {
    asm volatile("ldmatrix.sync.aligned.m8n8.x4.shared.b16 {%0,%1,%2,%3}, [%4];"
                 : "=r"(r[0]), "=r"(r[1]), "=r"(r[2]), "=r"(r[3]) : "r"(saddr));
}
__device__ __forceinline__ uint32_t h2u(float x, float y) {
    __half2 h = __floats2half2_rn(x, y);
    return *(uint32_t*)&h;
}

// ======================= fused converter =======================
__global__ __launch_bounds__(256) void convert_all(
    const float* in_w, const float* outp_w, const float* Vp_w,
    const float* ff1_w, const float* ff2_w, const float* src,
    const float* Qp_w, const float* Kp_w, const float* Qp_b, const float* Kp_b,
    __half* hw_in, __half* hw_out, __half* hw_Vp, __half* hw_f1, __half* hw_f2,
    __half* src_h, __half* hw_QK, float* bias_QK)
{
    const int bid = blockIdx.x, t = threadIdx.x;
    if (bid == 17536) {
        if (t < RR) bias_QK[t] = Qp_b[t];
        else if (t < 2 * RR) bias_QK[t] = Kp_b[t - RR];
        return;
    }
    const float* in; __half* out; long off;
    if      (bid < 3072)  { in = in_w;  out = hw_in;  off = (long)bid * 1024; }
    else if (bid < 4096)  { in = outp_w; out = hw_out; off = (long)(bid - 3072) * 1024; }
    else if (bid < 5120)  { in = Vp_w;  out = hw_Vp;  off = (long)(bid - 4096) * 1024; }
    else if (bid < 9216)  { in = ff1_w; out = hw_f1;  off = (long)(bid - 5120) * 1024; }
    else if (bid < 13312) { in = ff2_w; out = hw_f2;  off = (long)(bid - 9216) * 1024; }
    else if (bid < 17408) { in = src;   out = src_h;  off = (long)(bid - 13312) * 1024; }
    else if (bid < 17472) { in = Qp_w;  out = hw_QK;  off = (long)(bid - 17408) * 1024; }
    else                  { in = Kp_w;  out = hw_QK + (long)RR * DD; off = (long)(bid - 17472) * 1024; }
    long i = off + t * 4;
    float4 v = *(const float4*)(in + i);
    *(__half2*)(out + i) = __floats2half2_rn(v.x, v.y);
    *(__half2*)(out + i + 2) = __floats2half2_rn(v.z, v.w);
}

// ======================= fp16 warp-MMA GEMM (512 threads, 4 warps/SMSP) =======================
// C = alpha * A(MxK, lda) * B^T(NxK, ldb) + bias
// CTA tile 256x128x32h; 16 warps (4x4); warp tile 64x32; 3-stage cp.async; ldmatrix x4.
#define BM 256
#define BN 128
#define BKH 32
#define KSTRH 20
#define A_B32 (BM * KSTRH)
#define STG_B32 (A_B32 + BN * KSTRH)
#define GEMM_SMEM (3 * STG_B32 * 4)

__global__ __launch_bounds__(512) void hgemm_nt(
    const __half* __restrict__ A, const __half* __restrict__ B,
    const float* __restrict__ bias, void* __restrict__ Cout,
    int N, int K, int lda, int ldb,
    long sA, long sB, long sC, float alpha, int relu, int out_half)
{
    extern __shared__ uint32_t gsm[];

    A += (long)blockIdx.z * sA;
    B += (long)blockIdx.z * sB;

    const int t = threadIdx.x;
    const int wid = t >> 5, l = t & 31;
    const int wm = wid >> 2, wn = wid & 3;     // 4 x 4 warp grid
    const int mbase = wm * 64, nbase = wn * 32;
    const int qr = l >> 2, qc = l & 3;
    const int row0 = blockIdx.y * BM, col0 = blockIdx.x * BN;

    const uint32_t s0 = smem_u32(gsm);

    const int lr = t >> 2;            // 0..127
    const int lc4 = (t & 3) * 4;

    // ldmatrix lane addresses (stage-0 byte offsets)
    const uint32_t a_lm = s0 + (uint32_t)(((mbase + (l & 15)) * KSTRH + (l >> 4) * 4) * 4);
    // B x4: covers 16 n-rows (two n8 fragment pairs)
    const uint32_t b_lm = s0 + (uint32_t)((A_B32 +
        (nbase + (l & 7) + ((l >> 4) << 3)) * KSTRH + (((l >> 3) & 1) * 4)) * 4);

    float acc[4][4][4];
#pragma unroll
    for (int i = 0; i < 4; i++)
#pragma unroll
        for (int j = 0; j < 4; j++)
#pragma unroll
            for (int q = 0; q < 4; q++) acc[i][j][q] = 0.f;

    const int nc = K / BKH;

    auto prefetch = [&](int cc) {
        const int st = cc % 3;
        const int k0 = cc * BKH;
        const uint32_t sAs = s0 + st * STG_B32 * 4;
        const uint32_t sBs = sAs + A_B32 * 4;
#pragma unroll
        for (int j = 0; j < 2; j++) {
            int m = lr + j * 128;
            cp16(sAs + (m * KSTRH + lc4) * 4, &A[(long)(row0 + m) * lda + k0 + lc4 * 2]);
        }
        {
            int n = lr;   // 0..127
            cp16(sBs + (n * KSTRH + lc4) * 4, &B[(long)(col0 + n) * ldb + k0 + lc4 * 2]);
        }
        CP_COMMIT();
    };

    prefetch(0);
    if (nc > 1) prefetch(1);

    for (int c = 0; c < nc; c++) {
        if (c + 2 < nc) { prefetch(c + 2); CP_WAIT2(); }
        else if (c + 1 < nc) { CP_WAIT1(); }
        else { CP_WAIT0(); }
        __syncthreads();

        const uint32_t stoff = (uint32_t)((c % 3) * STG_B32 * 4);
#pragma unroll
        for (int kk = 0; kk < 2; kk++) {
            const uint32_t koff = stoff + kk * 8 * 4;
            uint32_t af[4][4], bf[2][4];
#pragma unroll
            for (int mt = 0; mt < 4; mt++)
                ldsm_x4(af[mt], a_lm + koff + mt * 16 * KSTRH * 4);
#pragma unroll
            for (int np = 0; np < 2; np++)
                ldsm_x4(bf[np], b_lm + koff + np * 16 * KSTRH * 4);
#pragma unroll
            for (int mt = 0; mt < 4; mt++) {
#pragma unroll
                for (int nt = 0; nt < 4; nt++)
                    mma_f16(acc[mt][nt], af[mt], &bf[nt >> 1][(nt & 1) * 2]);
            }
        }
        __syncthreads();
    }

    // ---- epilogue ----
#pragma unroll
    for (int mt = 0; mt < 4; mt++) {
        const int r = row0 + mbase + mt * 16 + qr;
#pragma unroll
        for (int nt = 0; nt < 4; nt++) {
            const int cc = col0 + nbase + nt * 8 + qc * 2;
            float b0 = 0.f, b1 = 0.f;
            if (bias) { b0 = bias[cc]; b1 = bias[cc + 1]; }
            float v0 = acc[mt][nt][0] * alpha + b0;
            float v1 = acc[mt][nt][1] * alpha + b1;
            float v2 = acc[mt][nt][2] * alpha + b0;
            float v3 = acc[mt][nt][3] * alpha + b1;
            if (relu) {
                v0 = fmaxf(v0, 0.f); v1 = fmaxf(v1, 0.f);
                v2 = fmaxf(v2, 0.f); v3 = fmaxf(v3, 0.f);
            }
            if (out_half) {
                __half* C = (__half*)Cout + blockIdx.z * sC;
                *(__half2*)&C[(long)r * N + cc] = __floats2half2_rn(v0, v1);
                *(__half2*)&C[(long)(r + 8) * N + cc] = __floats2half2_rn(v2, v3);
            } else {
                float* C = (float*)Cout + blockIdx.z * sC;
                float2 p0 = {v0, v1}, p1 = {v2, v3};
                *(float2*)&C[(long)r * N + cc] = p0;
                *(float2*)&C[(long)(r + 8) * N + cc] = p1;
            }
        }
    }
}

// ======================= half transpose =======================
__global__ __launch_bounds__(256) void transpose_h_kernel(const __half* __restrict__ V,
                                                          __half* __restrict__ Vt)
{
    __shared__ __half tile[32][33];
    const __half* Vb = V + (long)blockIdx.z * SS * DD;
    __half* Vtb = Vt + (long)blockIdx.z * SS * DD;
    const int s0 = blockIdx.x * 32, d0 = blockIdx.y * 32;
    const int tx = threadIdx.x & 31, ty0 = threadIdx.x >> 5;
#pragma unroll
    for (int i = 0; i < 4; i++) {
        int ty = ty0 + i * 8;
        tile[ty][tx] = Vb[(long)(s0 + ty) * DD + d0 + tx];
    }
    __syncthreads();
#pragma unroll
    for (int i = 0; i < 4; i++) {
        int ty = ty0 + i * 8;
        Vtb[(long)(d0 + ty) * SS + s0 + tx] = tile[tx][ty];
    }
}

// ======================= fp16 tensor-core flash attention =======================
#define FSTR 36

__global__ __launch_bounds__(256) void flash_attn_kernel(const __half* __restrict__ qkv,
                                                         __half* __restrict__ ctx)
{
    __shared__ uint32_t ps[128 * FSTR];
    __shared__ uint32_t ks[64 * FSTR];
    __shared__ uint32_t vs[64 * FSTR];
    __half* vs_h = (__half*)vs;

    const int t = threadIdx.x, w = t >> 5, l = t & 31;
    const int qr = l >> 2, qc = l & 3;
    const int q0 = blockIdx.x * 128, h = blockIdx.y, b = blockIdx.z;
    const int wr = w * 16;

    const __half* Qg = qkv + (long)(b * SS + q0) * (3 * DD) + h * DH;
    const __half* Kg = qkv + (long)(b * SS) * (3 * DD) + DD + h * DH;
    const __half* Vg = qkv + (long)(b * SS) * (3 * DD) + 2 * DD + h * DH;

#pragma unroll
    for (int i = 0; i < 4; i++) {
        int idx = t + i * 256;
        int r = idx >> 3, c16 = idx & 7;
        float4 v = *(const float4*)(Qg + (long)r * (3 * DD) + c16 * 8);
        *(float4*)&ps[r * FSTR + c16 * 4] = v;
    }
    __syncthreads();
    uint32_t qa[4][4];
#pragma unroll
    for (int k = 0; k < 4; k++) {
        qa[k][0] = ps[(wr + qr) * FSTR + k * 8 + qc];
        qa[k][1] = ps[(wr + qr + 8) * FSTR + k * 8 + qc];
        qa[k][2] = ps[(wr + qr) * FSTR + k * 8 + qc + 4];
        qa[k][3] = ps[(wr + qr + 8) * FSTR + k * 8 + qc + 4];
    }
    __syncthreads();

    float m0 = -1e30f, m1 = -1e30f, l0 = 0.f, l1 = 0.f;
    float o[8][4];
#pragma unroll
    for (int n = 0; n < 8; n++)
#pragma unroll
        for (int i = 0; i < 4; i++) o[n][i] = 0.f;

    for (int kt = 0; kt < SS; kt += 64) {
#pragma unroll
        for (int i = 0; i < 2; i++) {
            int idx = t + i * 256;
            int r = idx >> 3, c16 = idx & 7;
            float4 kv = *(const float4*)(Kg + (long)(kt + r) * (3 * DD) + c16 * 8);
            *(float4*)&ks[r * FSTR + c16 * 4] = kv;
            float4 vv = *(const float4*)(Vg + (long)(kt + r) * (3 * DD) + c16 * 8);
            const __half* vh = (const __half*)&vv;
#pragma unroll
            for (int j = 0; j < 8; j++)
                vs_h[(c16 * 8 + j) * (2 * FSTR) + r] = vh[j];
        }
        __syncthreads();

        float sa[8][4];
#pragma unroll
        for (int n = 0; n < 8; n++)
#pragma unroll
            for (int i = 0; i < 4; i++) sa[n][i] = 0.f;
#pragma unroll
        for (int k = 0; k < 4; k++) {
#pragma unroll
            for (int n = 0; n < 8; n++) {
                uint32_t bf[2];
                bf[0] = ks[(n * 8 + qr) * FSTR + k * 8 + qc];
                bf[1] = ks[(n * 8 + qr) * FSTR + k * 8 + qc + 4];
                mma_f16(sa[n], qa[k], bf);
            }
        }

        float rm0 = -1e30f, rm1 = -1e30f;
#pragma unroll
        for (int n = 0; n < 8; n++) {
            sa[n][0] *= 0.125f; sa[n][1] *= 0.125f;
            sa[n][2] *= 0.125f; sa[n][3] *= 0.125f;
            rm0 = fmaxf(rm0, fmaxf(sa[n][0], sa[n][1]));
            rm1 = fmaxf(rm1, fmaxf(sa[n][2], sa[n][3]));
        }
        rm0 = fmaxf(rm0, __shfl_xor_sync(0xffffffffu, rm0, 1));
        rm0 = fmaxf(rm0, __shfl_xor_sync(0xffffffffu, rm0, 2));
        rm1 = fmaxf(rm1, __shfl_xor_sync(0xffffffffu, rm1, 1));
        rm1 = fmaxf(rm1, __shfl_xor_sync(0xffffffffu, rm1, 2));

        const float nm0 = fmaxf(m0, rm0), nm1 = fmaxf(m1, rm1);
        const float c0 = __expf(m0 - nm0), c1 = __expf(m1 - nm1);
        float rs0 = 0.f, rs1 = 0.f;
#pragma unroll
        for (int n = 0; n < 8; n++) {
            float p0 = __expf(sa[n][0] - nm0);
            float p1 = __expf(sa[n][1] - nm0);
            float p2 = __expf(sa[n][2] - nm1);
            float p3 = __expf(sa[n][3] - nm1);
            rs0 += p0 + p1; rs1 += p2 + p3;
            ps[(wr + qr) * FSTR + n * 4 + qc] = h2u(p0, p1);
            ps[(wr + qr + 8) * FSTR + n * 4 + qc] = h2u(p2, p3);
            o[n][0] *= c0; o[n][1] *= c0; o[n][2] *= c1; o[n][3] *= c1;
        }
        rs0 += __shfl_xor_sync(0xffffffffu, rs0, 1);
        rs0 += __shfl_xor_sync(0xffffffffu, rs0, 2);
        rs1 += __shfl_xor_sync(0xffffffffu, rs1, 1);
        rs1 += __shfl_xor_sync(0xffffffffu, rs1, 2);
        l0 = l0 * c0 + rs0; l1 = l1 * c1 + rs1;
        m0 = nm0; m1 = nm1;

        __syncwarp();

#pragma unroll
        for (int k = 0; k < 4; k++) {
            uint32_t pa[4];
            pa[0] = ps[(wr + qr) * FSTR + k * 8 + qc];
            pa[1] = ps[(wr + qr + 8) * FSTR + k * 8 + qc];
            pa[2] = ps[(wr + qr) * FSTR + k * 8 + qc + 4];
            pa[3] = ps[(wr + qr + 8) * FSTR + k * 8 + qc + 4];
#pragma unroll
            for (int n = 0; n < 8; n++) {
                uint32_t bf[2];
                bf[0] = vs[(n * 8 + qr) * FSTR + k * 8 + qc];
                bf[1] = vs[(n * 8 + qr) * FSTR + k * 8 + qc + 4];
                mma_f16(o[n], pa, bf);
            }
        }
        __syncthreads();
    }

    const float i0 = 1.f / l0, i1 = 1.f / l1;
    __half* Og = ctx + (long)(b * SS + q0 + wr) * DD + h * DH;
#pragma unroll
    for (int n = 0; n < 8; n++) {
        *(__half2*)&Og[(long)qr * DD + n * 8 + 2 * qc] = __floats2half2_rn(o[n][0] * i0, o[n][1] * i0);
        *(__half2*)&Og[(long)(qr + 8) * DD + n * 8 + 2 * qc] = __floats2half2_rn(o[n][2] * i1, o[n][3] * i1);
    }
}

// ======================= radix-select top-k + masked softmax -> half P =======================
__global__ __launch_bounds__(256) void topk_softmax_kernel(const float* __restrict__ P,
                                                           __half* __restrict__ Ph)
{
    const long base = (long)blockIdx.x * SS;
    __shared__ float vals[SS];
    __shared__ unsigned keys[SS];
    __shared__ unsigned hist[256];
    __shared__ float redA[8], redB[8];
    __shared__ unsigned s_prefix;
    __shared__ int s_need;

    const int t = threadIdx.x;
    const int w = t >> 5, lane = t & 31;

    float lmax = -1e30f;
#pragma unroll
    for (int i = 0; i < 4; i++) {
        float v = P[base + t + i * 256];
        vals[t + i * 256] = v;
        unsigned u = __float_as_uint(v);
        u ^= (u >> 31) ? 0xFFFFFFFFu : 0x80000000u;
        keys[t + i * 256] = u;
        lmax = fmaxf(lmax, v);
    }
#pragma unroll
    for (int o = 16; o > 0; o >>= 1)
        lmax = fmaxf(lmax, __shfl_xor_sync(0xffffffffu, lmax, o));
    if (lane == 0) redA[w] = lmax;
    __syncthreads();
    float mx = redA[0];
#pragma unroll
    for (int i = 1; i < 8; i++) mx = fmaxf(mx, redA[i]);

    unsigned prefix = 0;
    int need = KSEL;
#pragma unroll
    for (int pass = 0; pass < 4; pass++) {
        const int shift = 24 - 8 * pass;
        const unsigned hmask = pass ? (0xFFFFFFFFu << (shift + 8)) : 0u;
        hist[t] = 0;
        __syncthreads();
#pragma unroll
        for (int i = 0; i < 4; i++) {
            unsigned u = keys[t + i * 256];
            if ((u & hmask) == prefix)
                atomicAdd(&hist[(u >> shift) & 0xFFu], 1u);
        }
        __syncthreads();
        if (t == 0) {
            int cum = 0, bsel = 0;
            for (int bbin = 255; bbin >= 0; bbin--) {
                int hh = (int)hist[bbin];
                if (cum + hh >= need) { bsel = bbin; break; }
                cum += hh;
            }
            s_prefix = prefix | ((unsigned)bsel << shift);
            s_need = need - cum;
        }
        __syncthreads();
        prefix = s_prefix;
        need = s_need;
        __syncthreads();
    }
    const unsigned thr = prefix;

    float e[4];
    float sk = 0.f, sf = 0.f;
#pragma unroll
    for (int i = 0; i < 4; i++) {
        float v = vals[t + i * 256];
        float ef = __expf(v - mx);
        bool kp = keys[t + i * 256] >= thr;
        e[i] = kp ? ef : 0.f;
        sk += e[i];
        sf += ef;
    }
#pragma unroll
    for (int o = 16; o > 0; o >>= 1) {
        sk += __shfl_xor_sync(0xffffffffu, sk, o);
        sf += __shfl_xor_sync(0xffffffffu, sf, o);
    }
    if (lane == 0) { redA[w] = sk; redB[w] = sf; }
    __syncthreads();
    float tk = 0.f, tf = 0.f;
#pragma unroll
    for (int i = 0; i < 8; i++) { tk += redA[i]; tf += redB[i]; }
    const float inv = 1.f / (tk + 1e-9f * tf);
#pragma unroll
    for (int i = 0; i < 4; i++)
        Ph[base + t + i * 256] = __float2half(e[i] * inv);
}

// ======================= fuse + residual + LN1 =======================
__global__ __launch_bounds__(256) void fuse_ln1_kernel(
    const float* __restrict__ src, const float* __restrict__ dense,
    const float* __restrict__ sparse, const float* __restrict__ lam,
    const float* __restrict__ g, const float* __restrict__ bb,
    float* __restrict__ x, __half* __restrict__ xh)
{
    const long row = (long)blockIdx.x * DD;
    __shared__ float buf[DD];
    __shared__ float r1[8], r2[8];
    const float sig = 1.f / (1.f + __expf(-lam[0]));
    const float osig = 1.f - sig;

    float s1 = 0.f, s2 = 0.f;
    for (int d = threadIdx.x; d < DD; d += 256) {
        float v = src[row + d] + sig * dense[row + d] + osig * sparse[row + d];
        buf[d] = v; s1 += v; s2 += v * v;
    }
#pragma unroll
    for (int o = 16; o > 0; o >>= 1) {
        s1 += __shfl_xor_sync(0xffffffffu, s1, o);
        s2 += __shfl_xor_sync(0xffffffffu, s2, o);
    }
    const int w = threadIdx.x >> 5, lane = threadIdx.x & 31;
    if (lane == 0) { r1[w] = s1; r2[w] = s2; }
    __syncthreads();
    if (threadIdx.x == 0) {
        float a = 0.f, c = 0.f;
        for (int i = 0; i < 8; i++) { a += r1[i]; c += r2[i]; }
        r1[0] = a; r2[0] = c;
    }
    __syncthreads();
    const float mean = r1[0] * (1.f / DD);
    const float var = r2[0] * (1.f / DD) - mean * mean;
    const float rstd = rsqrtf(var + 1e-5f);
    for (int d = threadIdx.x; d < DD; d += 256) {
        float v = (buf[d] - mean) * rstd * g[d] + bb[d];
        x[row + d] = v;
        xh[row + d] = __float2half(v);
    }
}

// ======================= residual + LN2 -> out =======================
__global__ __launch_bounds__(256) void ln2_kernel(
    const float* __restrict__ x, const float* __restrict__ ff,
    const float* __restrict__ g, const float* __restrict__ bb,
    float* __restrict__ out)
{
    const long row = (long)blockIdx.x * DD;
    __shared__ float buf[DD];
    __shared__ float r1[8], r2[8];

    float s1 = 0.f, s2 = 0.f;
    for (int d = threadIdx.x; d < DD; d += 256) {
        float v = x[row + d] + ff[row + d];
        buf[d] = v; s1 += v; s2 += v * v;
    }
#pragma unroll
    for (int o = 16; o > 0; o >>= 1) {
        s1 += __shfl_xor_sync(0xffffffffu, s1, o);
        s2 += __shfl_xor_sync(0xffffffffu, s2, o);
    }
    const int w = threadIdx.x >> 5, lane = threadIdx.x & 31;
    if (lane == 0) { r1[w] = s1; r2[w] = s2; }
    __syncthreads();
    if (threadIdx.x == 0) {
        float a = 0.f, c = 0.f;
        for (int i = 0; i < 8; i++) { a += r1[i]; c += r2[i]; }
        r1[0] = a; r2[0] = c;
    }
    __syncthreads();
    const float mean = r1[0] * (1.f / DD);
    const float var = r2[0] * (1.f / DD) - mean * mean;
    const float rstd = rsqrtf(var + 1e-5f);
    for (int d = threadIdx.x; d < DD; d += 256)
        out[row + d] = (buf[d] - mean) * rstd * g[d] + bb[d];
}

// ======================= launch =======================
extern "C" void kernel_launch(void* const* d_in, const int* in_sizes, int n_in,
                              void* d_out, int out_size)
{
    (void)in_sizes; (void)n_in; (void)out_size;
    const float* src    = (const float*)d_in[0];
    const float* in_w   = (const float*)d_in[1];
    const float* in_b   = (const float*)d_in[2];
    const float* outp_w = (const float*)d_in[3];
    const float* outp_b = (const float*)d_in[4];
    const float* Qp_w   = (const float*)d_in[5];
    const float* Qp_b   = (const float*)d_in[6];
    const float* Kp_w   = (const float*)d_in[7];
    const float* Kp_b   = (const float*)d_in[8];
    const float* Vp_w   = (const float*)d_in[9];
    const float* Vp_b   = (const float*)d_in[10];
    const float* lam    = (const float*)d_in[11];
    const float* ff1_w  = (const float*)d_in[12];
    const float* ff1_b  = (const float*)d_in[13];
    const float* ff2_w  = (const float*)d_in[14];
    const float* ff2_b  = (const float*)d_in[15];
    const float* ln1_g  = (const float*)d_in[16];
    const float* ln1_b  = (const float*)d_in[17];
    const float* ln2_g  = (const float*)d_in[18];
    const float* ln2_b  = (const float*)d_in[19];
    float* out = (float*)d_out;

    __half *hw_in, *hw_out, *hw_Vp, *hw_f1, *hw_f2, *hw_QK;
    __half *src_h, *qkv_h, *ctx_h, *QKlr_h, *Vlr_h, *Vt_h, *Ph, *x_h, *h1_h;
    float *bias_QK, *P, *dense, *sparse, *x, *ff;
    cudaGetSymbolAddress((void**)&hw_in,   g_hw_in);
    cudaGetSymbolAddress((void**)&hw_out,  g_hw_out);
    cudaGetSymbolAddress((void**)&hw_Vp,   g_hw_Vp);
    cudaGetSymbolAddress((void**)&hw_f1,   g_hw_f1);
    cudaGetSymbolAddress((void**)&hw_f2,   g_hw_f2);
    cudaGetSymbolAddress((void**)&hw_QK,   g_hw_QK);
    cudaGetSymbolAddress((void**)&bias_QK, g_bias_QK);
    cudaGetSymbolAddress((void**)&src_h,   g_src_h);
    cudaGetSymbolAddress((void**)&qkv_h,   g_qkv_h);
    cudaGetSymbolAddress((void**)&ctx_h,   g_ctx_h);
    cudaGetSymbolAddress((void**)&QKlr_h,  g_QKlr_h);
    cudaGetSymbolAddress((void**)&Vlr_h,   g_Vlr_h);
    cudaGetSymbolAddress((void**)&Vt_h,    g_Vt_h);
    cudaGetSymbolAddress((void**)&Ph,      g_Ph);
    cudaGetSymbolAddress((void**)&x_h,     g_x_h);
    cudaGetSymbolAddress((void**)&h1_h,    g_h1_h);
    cudaGetSymbolAddress((void**)&P,       g_P);
    cudaGetSymbolAddress((void**)&dense,   g_dense);
    cudaGetSymbolAddress((void**)&sparse,  g_sparse);
    cudaGetSymbolAddress((void**)&x,       g_x);
    cudaGetSymbolAddress((void**)&ff,      g_ff);

    cudaFuncSetAttribute(hgemm_nt, cudaFuncAttributeMaxDynamicSharedMemorySize, GEMM_SMEM);

    // 0. fused conversion
    convert_all<<<17537, 256>>>(in_w, outp_w, Vp_w, ff1_w, ff2_w, src,
                                Qp_w, Kp_w, Qp_b, Kp_b,
                                hw_in, hw_out, hw_Vp, hw_f1, hw_f2,
                                src_h, hw_QK, bias_QK);

    // 1. qkv = src @ in_proj^T + b -> half
    hgemm_nt<<<dim3(3 * DD / BN, NTOK / BM), 512, GEMM_SMEM>>>(
        src_h, hw_in, in_b, qkv_h, 3 * DD, DD, DD, DD, 0, 0, 0, 1.f, 0, 1);
    // 2. dense attention -> half ctx
    flash_attn_kernel<<<dim3(SS / 128, HH, BB), 256>>>(qkv_h, ctx_h);
    // 3. dense = ctx @ out_proj^T + b -> f32
    hgemm_nt<<<dim3(DD / BN, NTOK / BM), 512, GEMM_SMEM>>>(
        ctx_h, hw_out, outp_b, dense, DD, DD, DD, DD, 0, 0, 0, 1.f, 0, 0);
    // 4. QKlr = src @ [Qp;Kp]^T + b -> half [4096,128]
    hgemm_nt<<<dim3(1, NTOK / BM), 512, GEMM_SMEM>>>(
        src_h, hw_QK, bias_QK, QKlr_h, 2 * RR, DD, DD, DD, 0, 0, 0, 1.f, 0, 1);
    // 5. Vlr = src @ Vp^T + b -> half
    hgemm_nt<<<dim3(DD / BN, NTOK / BM), 512, GEMM_SMEM>>>(
        src_h, hw_Vp, Vp_b, Vlr_h, DD, DD, DD, DD, 0, 0, 0, 1.f, 0, 1);
    // 6. P = (Q @ K^T)/sqrt(R) per batch -> f32
    hgemm_nt<<<dim3(SS / BN, SS / BM, BB), 512, GEMM_SMEM>>>(
        QKlr_h, QKlr_h + RR, nullptr, P, SS, RR, 2 * RR, 2 * RR,
        (long)SS * 2 * RR, (long)SS * 2 * RR, (long)SS * SS, 0.125f, 0, 0);
    // 7. radix top-k + masked softmax -> half P
    topk_softmax_kernel<<<NTOK, 256>>>(P, Ph);
    // 8. Vt = V^T per batch
    transpose_h_kernel<<<dim3(SS / 32, DD / 32, BB), 256>>>(Vlr_h, Vt_h);
    // 9. sparse = P @ Vt^T per batch -> f32
    hgemm_nt<<<dim3(DD / BN, SS / BM, BB), 512, GEMM_SMEM>>>(
        Ph, Vt_h, nullptr, sparse, DD, SS, SS, SS,
        (long)SS * SS, (long)SS * DD, (long)SS * DD, 1.f, 0, 0);
    // 10. x = LN1(...) -> f32 + half
    fuse_ln1_kernel<<<NTOK, 256>>>(src, dense, sparse, lam, ln1_g, ln1_b, x, x_h);
    // 11. h1 = relu(x @ ff1^T + b) -> half
    hgemm_nt<<<dim3(DFFN / BN, NTOK / BM), 512, GEMM_SMEM>>>(
        x_h, hw_f1, ff1_b, h1_h, DFFN, DD, DD, DD, 0, 0, 0, 1.f, 1, 1);
    // 12. ff = h1 @ ff2^T + b -> f32
    hgemm_nt<<<dim3(DD / BN, NTOK / BM), 512, GEMM_SMEM>>>(
        h1_h, hw_f2, ff2_b, ff, DD, DFFN, DFFN, DFFN, 0, 0, 0, 1.f, 0, 0);
    // 13. out = LN2(x + ff)
    ln2_kernel<<<NTOK, 256>>>(x, ff, ln2_g, ln2_b, out);
}

// round 10
// speedup vs baseline: 1.0349x; 1.0349x over previous
#include <cuda_runtime.h>
#include <cuda_fp16.h>
#include <cstdint>
#include <math.h>

// Problem dims
#define BB   4
#define SS   1024
#define DD   1024
#define HH   16
#define DH   64
#define RR   64
#define DFFN 4096
#define NTOK (BB*SS)       // 4096
#define KSEL 204           // int(1024*0.2)
#define PROJN 4224         // 3*DD + 2*RR + DD  (qkv | Q | K | V)

// ---------------- scratch (device globals) ----------------
__device__ __half g_hw_pack[(long)PROJN * DD];   // [in_w; Qp; Kp; Vp]
__device__ float  g_bias_pack[PROJN];
__device__ __half g_hw_out[(long)DD * DD];
__device__ float  g_bias_dense[DD];              // sig * out_b
__device__ float  g_sig[1];
__device__ __half g_hw_f1[(long)DFFN * DD];
__device__ __half g_hw_f2[(long)DD * DFFN];
__device__ __half g_src_h[(long)NTOK * DD];
__device__ __half g_proj_h[(long)NTOK * PROJN];  // [tok][4224]
__device__ __half g_ctx_h[(long)NTOK * DD];      // pre-scaled by sig
__device__ __half g_Vt_h[(long)NTOK * DD];       // per-batch [DD][SS]
__device__ __half g_Ph[(long)BB * SS * SS];      // pre-scaled by 1-sig
__device__ float g_P[(long)BB * SS * SS];
__device__ float g_fused[(long)NTOK * DD];
__device__ float g_x[(long)NTOK * DD];
__device__ __half g_x_h[(long)NTOK * DD];
__device__ __half g_h1_h[(long)NTOK * DFFN];
__device__ float g_ff[(long)NTOK * DD];

// ======================= helpers =======================
__device__ __forceinline__ uint32_t smem_u32(const void* p) {
    uint32_t a;
    asm("{ .reg .u64 t; cvta.to.shared.u64 t, %1; cvt.u32.u64 %0, t; }" : "=r"(a) : "l"(p));
    return a;
}
__device__ __forceinline__ void cp16(uint32_t saddr, const void* g) {
    asm volatile("cp.async.ca.shared.global [%0], [%1], 16;"
                 :: "r"(saddr), "l"(g) : "memory");
}
#define CP_COMMIT() asm volatile("cp.async.commit_group;" ::: "memory")
#define CP_WAIT2()  asm volatile("cp.async.wait_group 2;" ::: "memory")
#define CP_WAIT1()  asm volatile("cp.async.wait_group 1;" ::: "memory")
#define CP_WAIT0()  asm volatile("cp.async.wait_group 0;" ::: "memory")

__device__ __forceinline__ void mma_f16(float* c, const uint32_t* a, const uint32_t* b) {
    asm volatile(
        "mma.sync.aligned.m16n8k16.row.col.f32.f16.f16.f32 "
        "{%0,%1,%2,%3}, {%4,%5,%6,%7}, {%8,%9}, {%0,%1,%2,%3};"
        : "+f"(c[0]), "+f"(c[1]), "+f"(c[2]), "+f"(c[3])
        : "r"(a[0]), "r"(a[1]), "r"(a[2]), "r"(a[3]), "r"(b[0]), "r"(b[1]));
}
__device__ __forceinline__ void ldsm_x4(uint32_t* r, uint32_t saddr) {
    asm volatile("ldmatrix.sync.aligned.m8n8.x4.shared.b16 {%0,%1,%2,%3}, [%4];"
                 : "=r"(r[0]), "=r"(r[1]), "=r"(r[2]), "=r"(r[3]) : "r"(saddr));
}
__device__ __forceinline__ uint32_t h2u(float x, float y) {
    __half2 h = __floats2half2_rn(x, y);
    return *(uint32_t*)&h;
}

// ======================= fused converter (packed weights + biases + sig) =======================
// grid blocks: [0,4224) pack rows | [4224,5248) outp | [5248,9344) ff1 |
// [9344,13440) ff2 | [13440,17536) src | 17536 = biases + sig
__global__ __launch_bounds__(256) void convert_all(
    const float* in_w, const float* outp_w, const float* Vp_w,
    const float* ff1_w, const float* ff2_w, const float* src,
    const float* Qp_w, const float* Kp_w,
    const float* in_b, const float* Qp_b, const float* Kp_b, const float* Vp_b,
    const float* outp_b, const float* lam,
    __half* hw_pack, __half* hw_out, __half* hw_f1, __half* hw_f2, __half* src_h,
    float* bias_pack, float* bias_dense, float* sigbuf)
{
    const int bid = blockIdx.x, t = threadIdx.x;
    if (bid == 17536) {
        const float sig = 1.f / (1.f + __expf(-lam[0]));
        if (t == 0) sigbuf[0] = sig;
        for (int i = t; i < PROJN; i += 256) {
            float v;
            if      (i < 3 * DD)          v = in_b[i];
            else if (i < 3 * DD + RR)     v = Qp_b[i - 3 * DD];
            else if (i < 3 * DD + 2 * RR) v = Kp_b[i - 3 * DD - RR];
            else                          v = Vp_b[i - 3 * DD - 2 * RR];
            bias_pack[i] = v;
        }
        for (int i = t; i < DD; i += 256)
            bias_dense[i] = sig * outp_b[i];
        return;
    }
    const float* in; __half* out; long off;
    if (bid < PROJN) {
        const int r = bid;
        if      (r < 3 * DD)          in = in_w + (long)r * DD;
        else if (r < 3 * DD + RR)     in = Qp_w + (long)(r - 3 * DD) * DD;
        else if (r < 3 * DD + 2 * RR) in = Kp_w + (long)(r - 3 * DD - RR) * DD;
        else                          in = Vp_w + (long)(r - 3 * DD - 2 * RR) * DD;
        out = hw_pack + (long)r * DD;
        off = 0;
    }
    else if (bid < 5248)  { in = outp_w + (long)(bid - 4224) * 1024; out = hw_out + (long)(bid - 4224) * 1024; off = 0; }
    else if (bid < 9344)  { in = ff1_w;  out = hw_f1;  off = (long)(bid - 5248) * 1024; }
    else if (bid < 13440) { in = ff2_w;  out = hw_f2;  off = (long)(bid - 9344) * 1024; }
    else                  { in = src;    out = src_h;  off = (long)(bid - 13440) * 1024; }
    long i = off + t * 4;
    float4 v = *(const float4*)(in + i);
    *(__half2*)(out + i) = __floats2half2_rn(v.x, v.y);
    *(__half2*)(out + i + 2) = __floats2half2_rn(v.z, v.w);
}

// ======================= fp16 warp-MMA GEMM, two K-segments =======================
// C = alpha * (A1(MxK1)*B1^T + A2(MxK2)*B2^T) + bias ; per-z strides.
// CTA tile 256x128x32h; 8 warps (4x2); warp tile 64x64; 3-stage cp.async; ldmatrix x4.
#define BM 256
#define BN 128
#define BKH 32
#define KSTRH 20
#define A_B32 (BM * KSTRH)
#define STG_B32 (A_B32 + BN * KSTRH)
#define GEMM_SMEM (3 * STG_B32 * 4)

__global__ __launch_bounds__(256) void hgemm_nt(
    const __half* __restrict__ A1, const __half* __restrict__ B1,
    int K1, int lda1, int ldb1, long sA1, long sB1,
    const __half* __restrict__ A2, const __half* __restrict__ B2,
    int K2, int lda2, int ldb2, long sA2, long sB2,
    const float* __restrict__ bias, void* __restrict__ Cout,
    int N, long sC, float alpha, int relu, int out_half)
{
    extern __shared__ uint32_t gsm[];

    const __half* A1g = A1 + (long)blockIdx.z * sA1;
    const __half* B1g = B1 + (long)blockIdx.z * sB1;
    const __half* A2g = A2 + (long)blockIdx.z * sA2;
    const __half* B2g = B2 + (long)blockIdx.z * sB2;

    const int t = threadIdx.x;
    const int wid = t >> 5, l = t & 31;
    const int wm = wid >> 1, wn = wid & 1;     // 4 x 2 warp grid
    const int mbase = wm * 64, nbase = wn * 64;
    const int qr = l >> 2, qc = l & 3;
    const int row0 = blockIdx.y * BM, col0 = blockIdx.x * BN;

    const uint32_t s0 = smem_u32(gsm);

    const int lr = t >> 2;            // 0..63
    const int lc4 = (t & 3) * 4;

    const uint32_t a_lm = s0 + (uint32_t)(((mbase + (l & 15)) * KSTRH + (l >> 4) * 4) * 4);
    const uint32_t b_lm = s0 + (uint32_t)((A_B32 +
        (nbase + (l & 7) + ((l >> 4) << 3)) * KSTRH + (((l >> 3) & 1) * 4)) * 4);

    float acc[4][8][4];
#pragma unroll
    for (int i = 0; i < 4; i++)
#pragma unroll
        for (int j = 0; j < 8; j++)
#pragma unroll
            for (int q = 0; q < 4; q++) acc[i][j][q] = 0.f;

    const int nc1 = K1 / BKH;
    const int nc = nc1 + K2 / BKH;

    auto prefetch = [&](int cc) {
        const int st = cc % 3;
        const __half* Ax; const __half* Bx; int k0, la, lb;
        if (cc < nc1) { Ax = A1g; Bx = B1g; k0 = cc * BKH; la = lda1; lb = ldb1; }
        else          { Ax = A2g; Bx = B2g; k0 = (cc - nc1) * BKH; la = lda2; lb = ldb2; }
        const uint32_t sAs = s0 + st * STG_B32 * 4;
        const uint32_t sBs = sAs + A_B32 * 4;
#pragma unroll
        for (int j = 0; j < 4; j++) {
            int m = lr + j * 64;
            cp16(sAs + (m * KSTRH + lc4) * 4, &Ax[(long)(row0 + m) * la + k0 + lc4 * 2]);
        }
#pragma unroll
        for (int j = 0; j < 2; j++) {
            int n = lr + j * 64;
            cp16(sBs + (n * KSTRH + lc4) * 4, &Bx[(long)(col0 + n) * lb + k0 + lc4 * 2]);
        }
        CP_COMMIT();
    };

    prefetch(0);
    if (nc > 1) prefetch(1);

    for (int c = 0; c < nc; c++) {
        if (c + 2 < nc) { prefetch(c + 2); CP_WAIT2(); }
        else if (c + 1 < nc) { CP_WAIT1(); }
        else { CP_WAIT0(); }
        __syncthreads();

        const uint32_t stoff = (uint32_t)((c % 3) * STG_B32 * 4);
#pragma unroll
        for (int kk = 0; kk < 2; kk++) {
            const uint32_t koff = stoff + kk * 8 * 4;
            uint32_t af[4][4], bf[4][4];
#pragma unroll
            for (int mt = 0; mt < 4; mt++)
                ldsm_x4(af[mt], a_lm + koff + mt * 16 * KSTRH * 4);
#pragma unroll
            for (int np = 0; np < 4; np++)
                ldsm_x4(bf[np], b_lm + koff + np * 16 * KSTRH * 4);
#pragma unroll
            for (int mt = 0; mt < 4; mt++) {
#pragma unroll
                for (int nt = 0; nt < 8; nt++)
                    mma_f16(acc[mt][nt], af[mt], &bf[nt >> 1][(nt & 1) * 2]);
            }
        }
        __syncthreads();
    }

    // ---- epilogue ----
#pragma unroll
    for (int mt = 0; mt < 4; mt++) {
        const int r = row0 + mbase + mt * 16 + qr;
#pragma unroll
        for (int nt = 0; nt < 8; nt++) {
            const int cc = col0 + nbase + nt * 8 + qc * 2;
            float b0 = 0.f, b1 = 0.f;
            if (bias) { b0 = bias[cc]; b1 = bias[cc + 1]; }
            float v0 = acc[mt][nt][0] * alpha + b0;
            float v1 = acc[mt][nt][1] * alpha + b1;
            float v2 = acc[mt][nt][2] * alpha + b0;
            float v3 = acc[mt][nt][3] * alpha + b1;
            if (relu) {
                v0 = fmaxf(v0, 0.f); v1 = fmaxf(v1, 0.f);
                v2 = fmaxf(v2, 0.f); v3 = fmaxf(v3, 0.f);
            }
            if (out_half) {
                __half* C = (__half*)Cout + blockIdx.z * sC;
                *(__half2*)&C[(long)r * N + cc] = __floats2half2_rn(v0, v1);
                *(__half2*)&C[(long)(r + 8) * N + cc] = __floats2half2_rn(v2, v3);
            } else {
                float* C = (float*)Cout + blockIdx.z * sC;
                float2 p0 = {v0, v1}, p1 = {v2, v3};
                *(float2*)&C[(long)r * N + cc] = p0;
                *(float2*)&C[(long)(r + 8) * N + cc] = p1;
            }
        }
    }
}

// ======================= half transpose from proj (V cols) =======================
// Vt[b][d][s] = proj[b*SS+s][3200+d]
__global__ __launch_bounds__(256) void transpose_proj_kernel(const __half* __restrict__ proj,
                                                             __half* __restrict__ Vt)
{
    __shared__ __half tile[32][33];
    const __half* Pb = proj + (long)blockIdx.z * SS * PROJN + (3 * DD + 2 * RR);
    __half* Vtb = Vt + (long)blockIdx.z * DD * SS;
    const int s0 = blockIdx.x * 32, d0 = blockIdx.y * 32;
    const int tx = threadIdx.x & 31, ty0 = threadIdx.x >> 5;
#pragma unroll
    for (int i = 0; i < 4; i++) {
        int ty = ty0 + i * 8;
        tile[ty][tx] = Pb[(long)(s0 + ty) * PROJN + d0 + tx];
    }
    __syncthreads();
#pragma unroll
    for (int i = 0; i < 4; i++) {
        int ty = ty0 + i * 8;
        Vtb[(long)(d0 + ty) * SS + s0 + tx] = tile[tx][ty];
    }
}

// ======================= fp16 flash attention (reads proj, scales by sig) =======================
#define FSTR 36

__global__ __launch_bounds__(256) void flash_attn_kernel(const __half* __restrict__ proj,
                                                         const float* __restrict__ sigbuf,
                                                         __half* __restrict__ ctx)
{
    __shared__ uint32_t ps[128 * FSTR];
    __shared__ uint32_t ks[64 * FSTR];
    __shared__ uint32_t vs[64 * FSTR];
    __half* vs_h = (__half*)vs;

    const int t = threadIdx.x, w = t >> 5, l = t & 31;
    const int qr = l >> 2, qc = l & 3;
    const int q0 = blockIdx.x * 128, h = blockIdx.y, b = blockIdx.z;
    const int wr = w * 16;

    const __half* Qg = proj + (long)(b * SS + q0) * PROJN + h * DH;
    const __half* Kg = proj + (long)(b * SS) * PROJN + DD + h * DH;
    const __half* Vg = proj + (long)(b * SS) * PROJN + 2 * DD + h * DH;

#pragma unroll
    for (int i = 0; i < 4; i++) {
        int idx = t + i * 256;
        int r = idx >> 3, c16 = idx & 7;
        float4 v = *(const float4*)(Qg + (long)r * PROJN + c16 * 8);
        *(float4*)&ps[r * FSTR + c16 * 4] = v;
    }
    __syncthreads();
    uint32_t qa[4][4];
#pragma unroll
    for (int k = 0; k < 4; k++) {
        qa[k][0] = ps[(wr + qr) * FSTR + k * 8 + qc];
        qa[k][1] = ps[(wr + qr + 8) * FSTR + k * 8 + qc];
        qa[k][2] = ps[(wr + qr) * FSTR + k * 8 + qc + 4];
        qa[k][3] = ps[(wr + qr + 8) * FSTR + k * 8 + qc + 4];
    }
    __syncthreads();

    float m0 = -1e30f, m1 = -1e30f, l0 = 0.f, l1 = 0.f;
    float o[8][4];
#pragma unroll
    for (int n = 0; n < 8; n++)
#pragma unroll
        for (int i = 0; i < 4; i++) o[n][i] = 0.f;

    for (int kt = 0; kt < SS; kt += 64) {
#pragma unroll
        for (int i = 0; i < 2; i++) {
            int idx = t + i * 256;
            int r = idx >> 3, c16 = idx & 7;
            float4 kv = *(const float4*)(Kg + (long)(kt + r) * PROJN + c16 * 8);
            *(float4*)&ks[r * FSTR + c16 * 4] = kv;
            float4 vv = *(const float4*)(Vg + (long)(kt + r) * PROJN + c16 * 8);
            const __half* vh = (const __half*)&vv;
#pragma unroll
            for (int j = 0; j < 8; j++)
                vs_h[(c16 * 8 + j) * (2 * FSTR) + r] = vh[j];
        }
        __syncthreads();

        float sa[8][4];
#pragma unroll
        for (int n = 0; n < 8; n++)
#pragma unroll
            for (int i = 0; i < 4; i++) sa[n][i] = 0.f;
#pragma unroll
        for (int k = 0; k < 4; k++) {
#pragma unroll
            for (int n = 0; n < 8; n++) {
                uint32_t bf[2];
                bf[0] = ks[(n * 8 + qr) * FSTR + k * 8 + qc];
                bf[1] = ks[(n * 8 + qr) * FSTR + k * 8 + qc + 4];
                mma_f16(sa[n], qa[k], bf);
            }
        }

        float rm0 = -1e30f, rm1 = -1e30f;
#pragma unroll
        for (int n = 0; n < 8; n++) {
            sa[n][0] *= 0.125f; sa[n][1] *= 0.125f;
            sa[n][2] *= 0.125f; sa[n][3] *= 0.125f;
            rm0 = fmaxf(rm0, fmaxf(sa[n][0], sa[n][1]));
            rm1 = fmaxf(rm1, fmaxf(sa[n][2], sa[n][3]));
        }
        rm0 = fmaxf(rm0, __shfl_xor_sync(0xffffffffu, rm0, 1));
        rm0 = fmaxf(rm0, __shfl_xor_sync(0xffffffffu, rm0, 2));
        rm1 = fmaxf(rm1, __shfl_xor_sync(0xffffffffu, rm1, 1));
        rm1 = fmaxf(rm1, __shfl_xor_sync(0xffffffffu, rm1, 2));

        const float nm0 = fmaxf(m0, rm0), nm1 = fmaxf(m1, rm1);
        const float c0 = __expf(m0 - nm0), c1 = __expf(m1 - nm1);
        float rs0 = 0.f, rs1 = 0.f;
#pragma unroll
        for (int n = 0; n < 8; n++) {
            float p0 = __expf(sa[n][0] - nm0);
            float p1 = __expf(sa[n][1] - nm0);
            float p2 = __expf(sa[n][2] - nm1);
            float p3 = __expf(sa[n][3] - nm1);
            rs0 += p0 + p1; rs1 += p2 + p3;
            ps[(wr + qr) * FSTR + n * 4 + qc] = h2u(p0, p1);
            ps[(wr + qr + 8) * FSTR + n * 4 + qc] = h2u(p2, p3);
            o[n][0] *= c0; o[n][1] *= c0; o[n][2] *= c1; o[n][3] *= c1;
        }
        rs0 += __shfl_xor_sync(0xffffffffu, rs0, 1);
        rs0 += __shfl_xor_sync(0xffffffffu, rs0, 2);
        rs1 += __shfl_xor_sync(0xffffffffu, rs1, 1);
        rs1 += __shfl_xor_sync(0xffffffffu, rs1, 2);
        l0 = l0 * c0 + rs0; l1 = l1 * c1 + rs1;
        m0 = nm0; m1 = nm1;

        __syncwarp();

#pragma unroll
        for (int k = 0; k < 4; k++) {
            uint32_t pa[4];
            pa[0] = ps[(wr + qr) * FSTR + k * 8 + qc];
            pa[1] = ps[(wr + qr + 8) * FSTR + k * 8 + qc];
            pa[2] = ps[(wr + qr) * FSTR + k * 8 + qc + 4];
            pa[3] = ps[(wr + qr + 8) * FSTR + k * 8 + qc + 4];
#pragma unroll
            for (int n = 0; n < 8; n++) {
                uint32_t bf[2];
                bf[0] = vs[(n * 8 + qr) * FSTR + k * 8 + qc];
                bf[1] = vs[(n * 8 + qr) * FSTR + k * 8 + qc + 4];
                mma_f16(o[n], pa, bf);
            }
        }
        __syncthreads();
    }

    const float sig = sigbuf[0];
    const float i0 = sig / l0, i1 = sig / l1;
    __half* Og = ctx + (long)(b * SS + q0 + wr) * DD + h * DH;
#pragma unroll
    for (int n = 0; n < 8; n++) {
        *(__half2*)&Og[(long)qr * DD + n * 8 + 2 * qc] = __floats2half2_rn(o[n][0] * i0, o[n][1] * i0);
        *(__half2*)&Og[(long)(qr + 8) * DD + n * 8 + 2 * qc] = __floats2half2_rn(o[n][2] * i1, o[n][3] * i1);
    }
}

// ======================= radix top-k + masked softmax -> half P (scaled by 1-sig) =======================
__global__ __launch_bounds__(256) void topk_softmax_kernel(const float* __restrict__ P,
                                                           const float* __restrict__ sigbuf,
                                                           __half* __restrict__ Ph)
{
    const long base = (long)blockIdx.x * SS;
    __shared__ float vals[SS];
    __shared__ unsigned keys[SS];
    __shared__ unsigned hist[256];
    __shared__ float redA[8], redB[8];
    __shared__ unsigned s_prefix;
    __shared__ int s_need;

    const int t = threadIdx.x;
    const int w = t >> 5, lane = t & 31;

    float lmax = -1e30f;
#pragma unroll
    for (int i = 0; i < 4; i++) {
        float v = P[base + t + i * 256];
        vals[t + i * 256] = v;
        unsigned u = __float_as_uint(v);
        u ^= (u >> 31) ? 0xFFFFFFFFu : 0x80000000u;
        keys[t + i * 256] = u;
        lmax = fmaxf(lmax, v);
    }
#pragma unroll
    for (int o = 16; o > 0; o >>= 1)
        lmax = fmaxf(lmax, __shfl_xor_sync(0xffffffffu, lmax, o));
    if (lane == 0) redA[w] = lmax;
    __syncthreads();
    float mx = redA[0];
#pragma unroll
    for (int i = 1; i < 8; i++) mx = fmaxf(mx, redA[i]);

    unsigned prefix = 0;
    int need = KSEL;
#pragma unroll
    for (int pass = 0; pass < 4; pass++) {
        const int shift = 24 - 8 * pass;
        const unsigned hmask = pass ? (0xFFFFFFFFu << (shift + 8)) : 0u;
        hist[t] = 0;
        __syncthreads();
#pragma unroll
        for (int i = 0; i < 4; i++) {
            unsigned u = keys[t + i * 256];
            if ((u & hmask) == prefix)
                atomicAdd(&hist[(u >> shift) & 0xFFu], 1u);
        }
        __syncthreads();
        if (t == 0) {
            int cum = 0, bsel = 0;
            for (int bbin = 255; bbin >= 0; bbin--) {
                int hh = (int)hist[bbin];
                if (cum + hh >= need) { bsel = bbin; break; }
                cum += hh;
            }
            s_prefix = prefix | ((unsigned)bsel << shift);
            s_need = need - cum;
        }
        __syncthreads();
        prefix = s_prefix;
        need = s_need;
        __syncthreads();
    }
    const unsigned thr = prefix;

    float e[4];
    float sk = 0.f, sf = 0.f;
#pragma unroll
    for (int i = 0; i < 4; i++) {
        float v = vals[t + i * 256];
        float ef = __expf(v - mx);
        bool kp = keys[t + i * 256] >= thr;
        e[i] = kp ? ef : 0.f;
        sk += e[i];
        sf += ef;
    }
#pragma unroll
    for (int o = 16; o > 0; o >>= 1) {
        sk += __shfl_xor_sync(0xffffffffu, sk, o);
        sf += __shfl_xor_sync(0xffffffffu, sf, o);
    }
    if (lane == 0) { redA[w] = sk; redB[w] = sf; }
    __syncthreads();
    float tk = 0.f, tf = 0.f;
#pragma unroll
    for (int i = 0; i < 8; i++) { tk += redA[i]; tf += redB[i]; }
    const float inv = (1.f - sigbuf[0]) / (tk + 1e-9f * tf);
#pragma unroll
    for (int i = 0; i < 4; i++)
        Ph[base + t + i * 256] = __float2half(e[i] * inv);
}

// ======================= residual + LN1 (fused input) =======================
__global__ __launch_bounds__(256) void fuse_ln1_kernel(
    const float* __restrict__ src, const float* __restrict__ fused,
    const float* __restrict__ g, const float* __restrict__ bb,
    float* __restrict__ x, __half* __restrict__ xh)
{
    const long row = (long)blockIdx.x * DD;
    __shared__ float buf[DD];
    __shared__ float r1[8], r2[8];

    float s1 = 0.f, s2 = 0.f;
    for (int d = threadIdx.x; d < DD; d += 256) {
        float v = src[row + d] + fused[row + d];
        buf[d] = v; s1 += v; s2 += v * v;
    }
#pragma unroll
    for (int o = 16; o > 0; o >>= 1) {
        s1 += __shfl_xor_sync(0xffffffffu, s1, o);
        s2 += __shfl_xor_sync(0xffffffffu, s2, o);
    }
    const int w = threadIdx.x >> 5, lane = threadIdx.x & 31;
    if (lane == 0) { r1[w] = s1; r2[w] = s2; }
    __syncthreads();
    if (threadIdx.x == 0) {
        float a = 0.f, c = 0.f;
        for (int i = 0; i < 8; i++) { a += r1[i]; c += r2[i]; }
        r1[0] = a; r2[0] = c;
    }
    __syncthreads();
    const float mean = r1[0] * (1.f / DD);
    const float var = r2[0] * (1.f / DD) - mean * mean;
    const float rstd = rsqrtf(var + 1e-5f);
    for (int d = threadIdx.x; d < DD; d += 256) {
        float v = (buf[d] - mean) * rstd * g[d] + bb[d];
        x[row + d] = v;
        xh[row + d] = __float2half(v);
    }
}

// ======================= residual + LN2 -> out =======================
__global__ __launch_bounds__(256) void ln2_kernel(
    const float* __restrict__ x, const float* __restrict__ ff,
    const float* __restrict__ g, const float* __restrict__ bb,
    float* __restrict__ out)
{
    const long row = (long)blockIdx.x * DD;
    __shared__ float buf[DD];
    __shared__ float r1[8], r2[8];

    float s1 = 0.f, s2 = 0.f;
    for (int d = threadIdx.x; d < DD; d += 256) {
        float v = x[row + d] + ff[row + d];
        buf[d] = v; s1 += v; s2 += v * v;
    }
#pragma unroll
    for (int o = 16; o > 0; o >>= 1) {
        s1 += __shfl_xor_sync(0xffffffffu, s1, o);
        s2 += __shfl_xor_sync(0xffffffffu, s2, o);
    }
    const int w = threadIdx.x >> 5, lane = threadIdx.x & 31;
    if (lane == 0) { r1[w] = s1; r2[w] = s2; }
    __syncthreads();
    if (threadIdx.x == 0) {
        float a = 0.f, c = 0.f;
        for (int i = 0; i < 8; i++) { a += r1[i]; c += r2[i]; }
        r1[0] = a; r2[0] = c;
    }
    __syncthreads();
    const float mean = r1[0] * (1.f / DD);
    const float var = r2[0] * (1.f / DD) - mean * mean;
    const float rstd = rsqrtf(var + 1e-5f);
    for (int d = threadIdx.x; d < DD; d += 256)
        out[row + d] = (buf[d] - mean) * rstd * g[d] + bb[d];
}

// ======================= launch =======================
extern "C" void kernel_launch(void* const* d_in, const int* in_sizes, int n_in,
                              void* d_out, int out_size)
{
    (void)in_sizes; (void)n_in; (void)out_size;
    const float* src    = (const float*)d_in[0];
    const float* in_w   = (const float*)d_in[1];
    const float* in_b   = (const float*)d_in[2];
    const float* outp_w = (const float*)d_in[3];
    const float* outp_b = (const float*)d_in[4];
    const float* Qp_w   = (const float*)d_in[5];
    const float* Qp_b   = (const float*)d_in[6];
    const float* Kp_w   = (const float*)d_in[7];
    const float* Kp_b   = (const float*)d_in[8];
    const float* Vp_w   = (const float*)d_in[9];
    const float* Vp_b   = (const float*)d_in[10];
    const float* lam    = (const float*)d_in[11];
    const float* ff1_w  = (const float*)d_in[12];
    const float* ff1_b  = (const float*)d_in[13];
    const float* ff2_w  = (const float*)d_in[14];
    const float* ff2_b  = (const float*)d_in[15];
    const float* ln1_g  = (const float*)d_in[16];
    const float* ln1_b  = (const float*)d_in[17];
    const float* ln2_g  = (const float*)d_in[18];
    const float* ln2_b  = (const float*)d_in[19];
    float* out = (float*)d_out;

    __half *hw_pack, *hw_out, *hw_f1, *hw_f2;
    __half *src_h, *proj_h, *ctx_h, *Vt_h, *Ph, *x_h, *h1_h;
    float *bias_pack, *bias_dense, *sigbuf, *P, *fused, *x, *ff;
    cudaGetSymbolAddress((void**)&hw_pack,    g_hw_pack);
    cudaGetSymbolAddress((void**)&hw_out,     g_hw_out);
    cudaGetSymbolAddress((void**)&hw_f1,      g_hw_f1);
    cudaGetSymbolAddress((void**)&hw_f2,      g_hw_f2);
    cudaGetSymbolAddress((void**)&bias_pack,  g_bias_pack);
    cudaGetSymbolAddress((void**)&bias_dense, g_bias_dense);
    cudaGetSymbolAddress((void**)&sigbuf,     g_sig);
    cudaGetSymbolAddress((void**)&src_h,      g_src_h);
    cudaGetSymbolAddress((void**)&proj_h,     g_proj_h);
    cudaGetSymbolAddress((void**)&ctx_h,      g_ctx_h);
    cudaGetSymbolAddress((void**)&Vt_h,       g_Vt_h);
    cudaGetSymbolAddress((void**)&Ph,         g_Ph);
    cudaGetSymbolAddress((void**)&x_h,        g_x_h);
    cudaGetSymbolAddress((void**)&h1_h,       g_h1_h);
    cudaGetSymbolAddress((void**)&P,          g_P);
    cudaGetSymbolAddress((void**)&fused,      g_fused);
    cudaGetSymbolAddress((void**)&x,          g_x);
    cudaGetSymbolAddress((void**)&ff,         g_ff);

    cudaFuncSetAttribute(hgemm_nt, cudaFuncAttributeMaxDynamicSharedMemorySize, GEMM_SMEM);

    // 0. fused conversion (packed weights + biases + sigma)
    convert_all<<<17537, 256>>>(in_w, outp_w, Vp_w, ff1_w, ff2_w, src,
                                Qp_w, Kp_w, in_b, Qp_b, Kp_b, Vp_b, outp_b, lam,
                                hw_pack, hw_out, hw_f1, hw_f2, src_h,
                                bias_pack, bias_dense, sigbuf);

    // 1. proj = src @ [in_w;Qp;Kp;Vp]^T + b  -> half [4096, 4224]
    hgemm_nt<<<dim3(PROJN / BN, NTOK / BM), 256, GEMM_SMEM>>>(
        src_h, hw_pack, DD, DD, DD, 0, 0,
        src_h, hw_pack, 0, DD, DD, 0, 0,
        bias_pack, proj_h, PROJN, 0, 1.f, 0, 1);
    // 2. dense flash attention (scales ctx by sig) -> half ctx
    flash_attn_kernel<<<dim3(SS / 128, HH, BB), 256>>>(proj_h, sigbuf, ctx_h);
    // 3. scores = (Q @ K^T)/sqrt(R) per batch -> f32
    hgemm_nt<<<dim3(SS / BN, SS / BM, BB), 256, GEMM_SMEM>>>(
        proj_h + 3 * DD, proj_h + 3 * DD + RR, RR, PROJN, PROJN,
        (long)SS * PROJN, (long)SS * PROJN,
        proj_h, proj_h, 0, PROJN, PROJN, 0, 0,
        nullptr, P, SS, (long)SS * SS, 0.125f, 0, 0);
    // 4. top-k + masked softmax (scales by 1-sig) -> half P
    topk_softmax_kernel<<<NTOK, 256>>>(P, sigbuf, Ph);
    // 5. Vt = V^T per batch (from proj cols)
    transpose_proj_kernel<<<dim3(SS / 32, DD / 32, BB), 256>>>(proj_h, Vt_h);
    // 6. fused = sig*(ctx@out^T + b) + (1-sig)*(P@V)  [two K-segments] -> f32
    hgemm_nt<<<dim3(DD / BN, SS / BM, BB), 256, GEMM_SMEM>>>(
        ctx_h, hw_out, DD, DD, DD, (long)SS * DD, 0,
        Ph, Vt_h, SS, SS, SS, (long)SS * SS, (long)DD * SS,
        bias_dense, fused, DD, (long)SS * DD, 1.f, 0, 0);
    // 7. x = LN1(src + fused) -> f32 + half
    fuse_ln1_kernel<<<NTOK, 256>>>(src, fused, ln1_g, ln1_b, x, x_h);
    // 8. h1 = relu(x @ ff1^T + b) -> half
    hgemm_nt<<<dim3(DFFN / BN, NTOK / BM), 256, GEMM_SMEM>>>(
        x_h, hw_f1, DD, DD, DD, 0, 0,
        x_h, hw_f1, 0, DD, DD, 0, 0,
        ff1_b, h1_h, DFFN, 0, 1.f, 1, 1);
    // 9. ff = h1 @ ff2^T + b -> f32
    hgemm_nt<<<dim3(DD / BN, NTOK / BM), 256, GEMM_SMEM>>>(
        h1_h, hw_f2, DFFN, DFFN, DFFN, 0, 0,
        h1_h, hw_f2, 0, DFFN, DFFN, 0, 0,
        ff2_b, ff, DD, 0, 1.f, 0, 0);
    // 10. out = LN2(x + ff)
    ln2_kernel<<<NTOK, 256>>>(x, ff, ln2_g, ln2_b, out);
}

// round 11
// speedup vs baseline: 1.0591x; 1.0234x over previous
#include <cuda_runtime.h>
#include <cuda_fp16.h>
#include <cstdint>
#include <math.h>

// Problem dims
#define BB   4
#define SS   1024
#define DD   1024
#define HH   16
#define DH   64
#define RR   64
#define DFFN 4096
#define NTOK (BB*SS)       // 4096
#define KSEL 204           // int(1024*0.2)
#define PROJN 4224         // 3*DD + 2*RR + DD  (qkv | Q | K | V)

// ---------------- scratch (device globals) ----------------
__device__ __half g_hw_pack[(long)PROJN * DD];   // [in_w; Qp; Kp; Vp]
__device__ float  g_bias_pack[PROJN];
__device__ __half g_hw_out[(long)DD * DD];
__device__ float  g_bias_dense[DD];              // sig * out_b
__device__ float  g_sig[1];
__device__ __half g_hw_f1[(long)DFFN * DD];
__device__ __half g_hw_f2[(long)DD * DFFN];
__device__ __half g_src_h[(long)NTOK * DD];
__device__ __half g_proj_h[(long)NTOK * PROJN];  // [tok][4224]
__device__ __half g_ctx_h[(long)NTOK * DD];      // pre-scaled by sig
__device__ __half g_Vt_h[(long)NTOK * DD];       // per-batch [DD][SS]
__device__ __half g_Ph[(long)BB * SS * SS];      // pre-scaled by 1-sig
__device__ float g_P[(long)BB * SS * SS];
__device__ float g_fused[(long)NTOK * DD];
__device__ float g_x[(long)NTOK * DD];
__device__ __half g_x_h[(long)NTOK * DD];
__device__ __half g_h1_h[(long)NTOK * DFFN];
__device__ float g_ff[(long)NTOK * DD];

// ======================= helpers =======================
__device__ __forceinline__ uint32_t smem_u32(const void* p) {
    uint32_t a;
    asm("{ .reg .u64 t; cvta.to.shared.u64 t, %1; cvt.u32.u64 %0, t; }" : "=r"(a) : "l"(p));
    return a;
}
__device__ __forceinline__ void cp16(uint32_t saddr, const void* g) {
    asm volatile("cp.async.ca.shared.global [%0], [%1], 16;"
                 :: "r"(saddr), "l"(g) : "memory");
}
#define CP_COMMIT() asm volatile("cp.async.commit_group;" ::: "memory")
#define CP_WAIT2()  asm volatile("cp.async.wait_group 2;" ::: "memory")
#define CP_WAIT1()  asm volatile("cp.async.wait_group 1;" ::: "memory")
#define CP_WAIT0()  asm volatile("cp.async.wait_group 0;" ::: "memory")

__device__ __forceinline__ void mma_f16(float* c, const uint32_t* a, const uint32_t* b) {
    asm volatile(
        "mma.sync.aligned.m16n8k16.row.col.f32.f16.f16.f32 "
        "{%0,%1,%2,%3}, {%4,%5,%6,%7}, {%8,%9}, {%0,%1,%2,%3};"
        : "+f"(c[0]), "+f"(c[1]), "+f"(c[2]), "+f"(c[3])
        : "r"(a[0]), "r"(a[1]), "r"(a[2]), "r"(a[3]), "r"(b[0]), "r"(b[1]));
}
__device__ __forceinline__ void ldsm_x4(uint32_t* r, uint32_t saddr) {
    asm volatile("ldmatrix.sync.aligned.m8n8.x4.shared.b16 {%0,%1,%2,%3}, [%4];"
                 : "=r"(r[0]), "=r"(r[1]), "=r"(r[2]), "=r"(r[3]) : "r"(saddr));
}
__device__ __forceinline__ uint32_t h2u(float x, float y) {
    __half2 h = __floats2half2_rn(x, y);
    return *(uint32_t*)&h;
}

// ======================= fused converter (packed weights + biases + sig) =======================
__global__ __launch_bounds__(256) void convert_all(
    const float* in_w, const float* outp_w, const float* Vp_w,
    const float* ff1_w, const float* ff2_w, const float* src,
    const float* Qp_w, const float* Kp_w,
    const float* in_b, const float* Qp_b, const float* Kp_b, const float* Vp_b,
    const float* outp_b, const float* lam,
    __half* hw_pack, __half* hw_out, __half* hw_f1, __half* hw_f2, __half* src_h,
    float* bias_pack, float* bias_dense, float* sigbuf)
{
    const int bid = blockIdx.x, t = threadIdx.x;
    if (bid == 17536) {
        const float sig = 1.f / (1.f + __expf(-lam[0]));
        if (t == 0) sigbuf[0] = sig;
        for (int i = t; i < PROJN; i += 256) {
            float v;
            if      (i < 3 * DD)          v = in_b[i];
            else if (i < 3 * DD + RR)     v = Qp_b[i - 3 * DD];
            else if (i < 3 * DD + 2 * RR) v = Kp_b[i - 3 * DD - RR];
            else                          v = Vp_b[i - 3 * DD - 2 * RR];
            bias_pack[i] = v;
        }
        for (int i = t; i < DD; i += 256)
            bias_dense[i] = sig * outp_b[i];
        return;
    }
    const float* in; __half* out; long off;
    if (bid < PROJN) {
        const int r = bid;
        if      (r < 3 * DD)          in = in_w + (long)r * DD;
        else if (r < 3 * DD + RR)     in = Qp_w + (long)(r - 3 * DD) * DD;
        else if (r < 3 * DD + 2 * RR) in = Kp_w + (long)(r - 3 * DD - RR) * DD;
        else                          in = Vp_w + (long)(r - 3 * DD - 2 * RR) * DD;
        out = hw_pack + (long)r * DD;
        off = 0;
    }
    else if (bid < 5248)  { in = outp_w + (long)(bid - 4224) * 1024; out = hw_out + (long)(bid - 4224) * 1024; off = 0; }
    else if (bid < 9344)  { in = ff1_w;  out = hw_f1;  off = (long)(bid - 5248) * 1024; }
    else if (bid < 13440) { in = ff2_w;  out = hw_f2;  off = (long)(bid - 9344) * 1024; }
    else                  { in = src;    out = src_h;  off = (long)(bid - 13440) * 1024; }
    long i = off + t * 4;
    float4 v = *(const float4*)(in + i);
    *(__half2*)(out + i) = __floats2half2_rn(v.x, v.y);
    *(__half2*)(out + i + 2) = __floats2half2_rn(v.z, v.w);
}

// ======================= fp16 warp-MMA GEMM, two K-segments =======================
#define BM 256
#define BN 128
#define BKH 32
#define KSTRH 20
#define A_B32 (BM * KSTRH)
#define STG_B32 (A_B32 + BN * KSTRH)
#define GEMM_SMEM (3 * STG_B32 * 4)

__global__ __launch_bounds__(256) void hgemm_nt(
    const __half* __restrict__ A1, const __half* __restrict__ B1,
    int K1, int lda1, int ldb1, long sA1, long sB1,
    const __half* __restrict__ A2, const __half* __restrict__ B2,
    int K2, int lda2, int ldb2, long sA2, long sB2,
    const float* __restrict__ bias, void* __restrict__ Cout,
    int N, long sC, float alpha, int relu, int out_half)
{
    extern __shared__ uint32_t gsm[];

    const __half* A1g = A1 + (long)blockIdx.z * sA1;
    const __half* B1g = B1 + (long)blockIdx.z * sB1;
    const __half* A2g = A2 + (long)blockIdx.z * sA2;
    const __half* B2g = B2 + (long)blockIdx.z * sB2;

    const int t = threadIdx.x;
    const int wid = t >> 5, l = t & 31;
    const int wm = wid >> 1, wn = wid & 1;
    const int mbase = wm * 64, nbase = wn * 64;
    const int qr = l >> 2, qc = l & 3;
    const int row0 = blockIdx.y * BM, col0 = blockIdx.x * BN;

    const uint32_t s0 = smem_u32(gsm);

    const int lr = t >> 2;
    const int lc4 = (t & 3) * 4;

    const uint32_t a_lm = s0 + (uint32_t)(((mbase + (l & 15)) * KSTRH + (l >> 4) * 4) * 4);
    const uint32_t b_lm = s0 + (uint32_t)((A_B32 +
        (nbase + (l & 7) + ((l >> 4) << 3)) * KSTRH + (((l >> 3) & 1) * 4)) * 4);

    float acc[4][8][4];
#pragma unroll
    for (int i = 0; i < 4; i++)
#pragma unroll
        for (int j = 0; j < 8; j++)
#pragma unroll
            for (int q = 0; q < 4; q++) acc[i][j][q] = 0.f;

    const int nc1 = K1 / BKH;
    const int nc = nc1 + K2 / BKH;

    auto prefetch = [&](int cc) {
        const int st = cc % 3;
        const __half* Ax; const __half* Bx; int k0, la, lb;
        if (cc < nc1) { Ax = A1g; Bx = B1g; k0 = cc * BKH; la = lda1; lb = ldb1; }
        else          { Ax = A2g; Bx = B2g; k0 = (cc - nc1) * BKH; la = lda2; lb = ldb2; }
        const uint32_t sAs = s0 + st * STG_B32 * 4;
        const uint32_t sBs = sAs + A_B32 * 4;
#pragma unroll
        for (int j = 0; j < 4; j++) {
            int m = lr + j * 64;
            cp16(sAs + (m * KSTRH + lc4) * 4, &Ax[(long)(row0 + m) * la + k0 + lc4 * 2]);
        }
#pragma unroll
        for (int j = 0; j < 2; j++) {
            int n = lr + j * 64;
            cp16(sBs + (n * KSTRH + lc4) * 4, &Bx[(long)(col0 + n) * lb + k0 + lc4 * 2]);
        }
        CP_COMMIT();
    };

    prefetch(0);
    if (nc > 1) prefetch(1);

    for (int c = 0; c < nc; c++) {
        if (c + 2 < nc) { prefetch(c + 2); CP_WAIT2(); }
        else if (c + 1 < nc) { CP_WAIT1(); }
        else { CP_WAIT0(); }
        __syncthreads();

        const uint32_t stoff = (uint32_t)((c % 3) * STG_B32 * 4);
#pragma unroll
        for (int kk = 0; kk < 2; kk++) {
            const uint32_t koff = stoff + kk * 8 * 4;
            uint32_t af[4][4], bf[4][4];
#pragma unroll
            for (int mt = 0; mt < 4; mt++)
                ldsm_x4(af[mt], a_lm + koff + mt * 16 * KSTRH * 4);
#pragma unroll
            for (int np = 0; np < 4; np++)
                ldsm_x4(bf[np], b_lm + koff + np * 16 * KSTRH * 4);
#pragma unroll
            for (int mt = 0; mt < 4; mt++) {
#pragma unroll
                for (int nt = 0; nt < 8; nt++)
                    mma_f16(acc[mt][nt], af[mt], &bf[nt >> 1][(nt & 1) * 2]);
            }
        }
        __syncthreads();
    }

    // ---- epilogue ----
#pragma unroll
    for (int mt = 0; mt < 4; mt++) {
        const int r = row0 + mbase + mt * 16 + qr;
#pragma unroll
        for (int nt = 0; nt < 8; nt++) {
            const int cc = col0 + nbase + nt * 8 + qc * 2;
            float b0 = 0.f, b1 = 0.f;
            if (bias) { b0 = bias[cc]; b1 = bias[cc + 1]; }
            float v0 = acc[mt][nt][0] * alpha + b0;
            float v1 = acc[mt][nt][1] * alpha + b1;
            float v2 = acc[mt][nt][2] * alpha + b0;
            float v3 = acc[mt][nt][3] * alpha + b1;
            if (relu) {
                v0 = fmaxf(v0, 0.f); v1 = fmaxf(v1, 0.f);
                v2 = fmaxf(v2, 0.f); v3 = fmaxf(v3, 0.f);
            }
            if (out_half) {
                __half* C = (__half*)Cout + blockIdx.z * sC;
                *(__half2*)&C[(long)r * N + cc] = __floats2half2_rn(v0, v1);
                *(__half2*)&C[(long)(r + 8) * N + cc] = __floats2half2_rn(v2, v3);
            } else {
                float* C = (float*)Cout + blockIdx.z * sC;
                float2 p0 = {v0, v1}, p1 = {v2, v3};
                *(float2*)&C[(long)r * N + cc] = p0;
                *(float2*)&C[(long)(r + 8) * N + cc] = p1;
            }
        }
    }
}

// ======================= half transpose from proj (V cols) =======================
__global__ __launch_bounds__(256) void transpose_proj_kernel(const __half* __restrict__ proj,
                                                             __half* __restrict__ Vt)
{
    __shared__ __half tile[32][33];
    const __half* Pb = proj + (long)blockIdx.z * SS * PROJN + (3 * DD + 2 * RR);
    __half* Vtb = Vt + (long)blockIdx.z * DD * SS;
    const int s0 = blockIdx.x * 32, d0 = blockIdx.y * 32;
    const int tx = threadIdx.x & 31, ty0 = threadIdx.x >> 5;
#pragma unroll
    for (int i = 0; i < 4; i++) {
        int ty = ty0 + i * 8;
        tile[ty][tx] = Pb[(long)(s0 + ty) * PROJN + d0 + tx];
    }
    __syncthreads();
#pragma unroll
    for (int i = 0; i < 4; i++) {
        int ty = ty0 + i * 8;
        Vtb[(long)(d0 + ty) * SS + s0 + tx] = tile[tx][ty];
    }
}

// ======================= fp16 flash attention (reads proj, scales by sig) =======================
#define FSTR 36

__global__ __launch_bounds__(256) void flash_attn_kernel(const __half* __restrict__ proj,
                                                         const float* __restrict__ sigbuf,
                                                         __half* __restrict__ ctx)
{
    __shared__ uint32_t ps[128 * FSTR];
    __shared__ uint32_t ks[64 * FSTR];
    __shared__ uint32_t vs[64 * FSTR];
    __half* vs_h = (__half*)vs;

    const int t = threadIdx.x, w = t >> 5, l = t & 31;
    const int qr = l >> 2, qc = l & 3;
    const int q0 = blockIdx.x * 128, h = blockIdx.y, b = blockIdx.z;
    const int wr = w * 16;

    const __half* Qg = proj + (long)(b * SS + q0) * PROJN + h * DH;
    const __half* Kg = proj + (long)(b * SS) * PROJN + DD + h * DH;
    const __half* Vg = proj + (long)(b * SS) * PROJN + 2 * DD + h * DH;

#pragma unroll
    for (int i = 0; i < 4; i++) {
        int idx = t + i * 256;
        int r = idx >> 3, c16 = idx & 7;
        float4 v = *(const float4*)(Qg + (long)r * PROJN + c16 * 8);
        *(float4*)&ps[r * FSTR + c16 * 4] = v;
    }
    __syncthreads();
    uint32_t qa[4][4];
#pragma unroll
    for (int k = 0; k < 4; k++) {
        qa[k][0] = ps[(wr + qr) * FSTR + k * 8 + qc];
        qa[k][1] = ps[(wr + qr + 8) * FSTR + k * 8 + qc];
        qa[k][2] = ps[(wr + qr) * FSTR + k * 8 + qc + 4];
        qa[k][3] = ps[(wr + qr + 8) * FSTR + k * 8 + qc + 4];
    }
    __syncthreads();

    float m0 = -1e30f, m1 = -1e30f, l0 = 0.f, l1 = 0.f;
    float o[8][4];
#pragma unroll
    for (int n = 0; n < 8; n++)
#pragma unroll
        for (int i = 0; i < 4; i++) o[n][i] = 0.f;

    for (int kt = 0; kt < SS; kt += 64) {
#pragma unroll
        for (int i = 0; i < 2; i++) {
            int idx = t + i * 256;
            int r = idx >> 3, c16 = idx & 7;
            float4 kv = *(const float4*)(Kg + (long)(kt + r) * PROJN + c16 * 8);
            *(float4*)&ks[r * FSTR + c16 * 4] = kv;
            float4 vv = *(const float4*)(Vg + (long)(kt + r) * PROJN + c16 * 8);
            const __half* vh = (const __half*)&vv;
#pragma unroll
            for (int j = 0; j < 8; j++)
                vs_h[(c16 * 8 + j) * (2 * FSTR) + r] = vh[j];
        }
        __syncthreads();

        float sa[8][4];
#pragma unroll
        for (int n = 0; n < 8; n++)
#pragma unroll
            for (int i = 0; i < 4; i++) sa[n][i] = 0.f;
#pragma unroll
        for (int k = 0; k < 4; k++) {
#pragma unroll
            for (int n = 0; n < 8; n++) {
                uint32_t bf[2];
                bf[0] = ks[(n * 8 + qr) * FSTR + k * 8 + qc];
                bf[1] = ks[(n * 8 + qr) * FSTR + k * 8 + qc + 4];
                mma_f16(sa[n], qa[k], bf);
            }
        }

        float rm0 = -1e30f, rm1 = -1e30f;
#pragma unroll
        for (int n = 0; n < 8; n++) {
            sa[n][0] *= 0.125f; sa[n][1] *= 0.125f;
            sa[n][2] *= 0.125f; sa[n][3] *= 0.125f;
            rm0 = fmaxf(rm0, fmaxf(sa[n][0], sa[n][1]));
            rm1 = fmaxf(rm1, fmaxf(sa[n][2], sa[n][3]));
        }
        rm0 = fmaxf(rm0, __shfl_xor_sync(0xffffffffu, rm0, 1));
        rm0 = fmaxf(rm0, __shfl_xor_sync(0xffffffffu, rm0, 2));
        rm1 = fmaxf(rm1, __shfl_xor_sync(0xffffffffu, rm1, 1));
        rm1 = fmaxf(rm1, __shfl_xor_sync(0xffffffffu, rm1, 2));

        const float nm0 = fmaxf(m0, rm0), nm1 = fmaxf(m1, rm1);
        const float c0 = __expf(m0 - nm0), c1 = __expf(m1 - nm1);
        float rs0 = 0.f, rs1 = 0.f;
#pragma unroll
        for (int n = 0; n < 8; n++) {
            float p0 = __expf(sa[n][0] - nm0);
            float p1 = __expf(sa[n][1] - nm0);
            float p2 = __expf(sa[n][2] - nm1);
            float p3 = __expf(sa[n][3] - nm1);
            rs0 += p0 + p1; rs1 += p2 + p3;
            ps[(wr + qr) * FSTR + n * 4 + qc] = h2u(p0, p1);
            ps[(wr + qr + 8) * FSTR + n * 4 + qc] = h2u(p2, p3);
            o[n][0] *= c0; o[n][1] *= c0; o[n][2] *= c1; o[n][3] *= c1;
        }
        rs0 += __shfl_xor_sync(0xffffffffu, rs0, 1);
        rs0 += __shfl_xor_sync(0xffffffffu, rs0, 2);
        rs1 += __shfl_xor_sync(0xffffffffu, rs1, 1);
        rs1 += __shfl_xor_sync(0xffffffffu, rs1, 2);
        l0 = l0 * c0 + rs0; l1 = l1 * c1 + rs1;
        m0 = nm0; m1 = nm1;

        __syncwarp();

#pragma unroll
        for (int k = 0; k < 4; k++) {
            uint32_t pa[4];
            pa[0] = ps[(wr + qr) * FSTR + k * 8 + qc];
            pa[1] = ps[(wr + qr + 8) * FSTR + k * 8 + qc];
            pa[2] = ps[(wr + qr) * FSTR + k * 8 + qc + 4];
            pa[3] = ps[(wr + qr + 8) * FSTR + k * 8 + qc + 4];
#pragma unroll
            for (int n = 0; n < 8; n++) {
                uint32_t bf[2];
                bf[0] = vs[(n * 8 + qr) * FSTR + k * 8 + qc];
                bf[1] = vs[(n * 8 + qr) * FSTR + k * 8 + qc + 4];
                mma_f16(o[n], pa, bf);
            }
        }
        __syncthreads();
    }

    const float sig = sigbuf[0];
    const float i0 = sig / l0, i1 = sig / l1;
    __half* Og = ctx + (long)(b * SS + q0 + wr) * DD + h * DH;
#pragma unroll
    for (int n = 0; n < 8; n++) {
        *(__half2*)&Og[(long)qr * DD + n * 8 + 2 * qc] = __floats2half2_rn(o[n][0] * i0, o[n][1] * i0);
        *(__half2*)&Og[(long)(qr + 8) * DD + n * 8 + 2 * qc] = __floats2half2_rn(o[n][2] * i1, o[n][3] * i1);
    }
}

// ======================= radix top-k + masked softmax -> half P (scaled by 1-sig) =======================
__global__ __launch_bounds__(256) void topk_softmax_kernel(const float* __restrict__ P,
                                                           const float* __restrict__ sigbuf,
                                                           __half* __restrict__ Ph)
{
    const long base = (long)blockIdx.x * SS;
    __shared__ float vals[SS];
    __shared__ unsigned keys[SS];
    __shared__ unsigned hist[256];
    __shared__ float redA[8], redB[8];
    __shared__ unsigned s_prefix;
    __shared__ int s_need;

    const int t = threadIdx.x;
    const int w = t >> 5, lane = t & 31;

    float lmax = -1e30f;
#pragma unroll
    for (int i = 0; i < 4; i++) {
        float v = P[base + t + i * 256];
        vals[t + i * 256] = v;
        unsigned u = __float_as_uint(v);
        u ^= (u >> 31) ? 0xFFFFFFFFu : 0x80000000u;
        keys[t + i * 256] = u;
        lmax = fmaxf(lmax, v);
    }
#pragma unroll
    for (int o = 16; o > 0; o >>= 1)
        lmax = fmaxf(lmax, __shfl_xor_sync(0xffffffffu, lmax, o));
    if (lane == 0) redA[w] = lmax;
    __syncthreads();
    float mx = redA[0];
#pragma unroll
    for (int i = 1; i < 8; i++) mx = fmaxf(mx, redA[i]);

    unsigned prefix = 0;
    int need = KSEL;
#pragma unroll
    for (int pass = 0; pass < 4; pass++) {
        const int shift = 24 - 8 * pass;
        const unsigned hmask = pass ? (0xFFFFFFFFu << (shift + 8)) : 0u;
        hist[t] = 0;
        __syncthreads();
#pragma unroll
        for (int i = 0; i < 4; i++) {
            unsigned u = keys[t + i * 256];
            if ((u & hmask) == prefix)
                atomicAdd(&hist[(u >> shift) & 0xFFu], 1u);
        }
        __syncthreads();
        if (t == 0) {
            int cum = 0, bsel = 0;
            for (int bbin = 255; bbin >= 0; bbin--) {
                int hh = (int)hist[bbin];
                if (cum + hh >= need) { bsel = bbin; break; }
                cum += hh;
            }
            s_prefix = prefix | ((unsigned)bsel << shift);
            s_need = need - cum;
        }
        __syncthreads();
        prefix = s_prefix;
        need = s_need;
        __syncthreads();
    }
    const unsigned thr = prefix;

    float e[4];
    float sk = 0.f, sf = 0.f;
#pragma unroll
    for (int i = 0; i < 4; i++) {
        float v = vals[t + i * 256];
        float ef = __expf(v - mx);
        bool kp = keys[t + i * 256] >= thr;
        e[i] = kp ? ef : 0.f;
        sk += e[i];
        sf += ef;
    }
#pragma unroll
    for (int o = 16; o > 0; o >>= 1) {
        sk += __shfl_xor_sync(0xffffffffu, sk, o);
        sf += __shfl_xor_sync(0xffffffffu, sf, o);
    }
    if (lane == 0) { redA[w] = sk; redB[w] = sf; }
    __syncthreads();
    float tk = 0.f, tf = 0.f;
#pragma unroll
    for (int i = 0; i < 8; i++) { tk += redA[i]; tf += redB[i]; }
    const float inv = (1.f - sigbuf[0]) / (tk + 1e-9f * tf);
#pragma unroll
    for (int i = 0; i < 4; i++)
        Ph[base + t + i * 256] = __float2half(e[i] * inv);
}

// ======================= residual + LN1 (fused input) =======================
__global__ __launch_bounds__(256) void fuse_ln1_kernel(
    const float* __restrict__ src, const float* __restrict__ fused,
    const float* __restrict__ g, const float* __restrict__ bb,
    float* __restrict__ x, __half* __restrict__ xh)
{
    const long row = (long)blockIdx.x * DD;
    __shared__ float buf[DD];
    __shared__ float r1[8], r2[8];

    float s1 = 0.f, s2 = 0.f;
    for (int d = threadIdx.x; d < DD; d += 256) {
        float v = src[row + d] + fused[row + d];
        buf[d] = v; s1 += v; s2 += v * v;
    }
#pragma unroll
    for (int o = 16; o > 0; o >>= 1) {
        s1 += __shfl_xor_sync(0xffffffffu, s1, o);
        s2 += __shfl_xor_sync(0xffffffffu, s2, o);
    }
    const int w = threadIdx.x >> 5, lane = threadIdx.x & 31;
    if (lane == 0) { r1[w] = s1; r2[w] = s2; }
    __syncthreads();
    if (threadIdx.x == 0) {
        float a = 0.f, c = 0.f;
        for (int i = 0; i < 8; i++) { a += r1[i]; c += r2[i]; }
        r1[0] = a; r2[0] = c;
    }
    __syncthreads();
    const float mean = r1[0] * (1.f / DD);
    const float var = r2[0] * (1.f / DD) - mean * mean;
    const float rstd = rsqrtf(var + 1e-5f);
    for (int d = threadIdx.x; d < DD; d += 256) {
        float v = (buf[d] - mean) * rstd * g[d] + bb[d];
        x[row + d] = v;
        xh[row + d] = __float2half(v);
    }
}

// ======================= residual + LN2 -> out =======================
__global__ __launch_bounds__(256) void ln2_kernel(
    const float* __restrict__ x, const float* __restrict__ ff,
    const float* __restrict__ g, const float* __restrict__ bb,
    float* __restrict__ out)
{
    const long row = (long)blockIdx.x * DD;
    __shared__ float buf[DD];
    __shared__ float r1[8], r2[8];

    float s1 = 0.f, s2 = 0.f;
    for (int d = threadIdx.x; d < DD; d += 256) {
        float v = x[row + d] + ff[row + d];
        buf[d] = v; s1 += v; s2 += v * v;
    }
#pragma unroll
    for (int o = 16; o > 0; o >>= 1) {
        s1 += __shfl_xor_sync(0xffffffffu, s1, o);
        s2 += __shfl_xor_sync(0xffffffffu, s2, o);
    }
    const int w = threadIdx.x >> 5, lane = threadIdx.x & 31;
    if (lane == 0) { r1[w] = s1; r2[w] = s2; }
    __syncthreads();
    if (threadIdx.x == 0) {
        float a = 0.f, c = 0.f;
        for (int i = 0; i < 8; i++) { a += r1[i]; c += r2[i]; }
        r1[0] = a; r2[0] = c;
    }
    __syncthreads();
    const float mean = r1[0] * (1.f / DD);
    const float var = r2[0] * (1.f / DD) - mean * mean;
    const float rstd = rsqrtf(var + 1e-5f);
    for (int d = threadIdx.x; d < DD; d += 256)
        out[row + d] = (buf[d] - mean) * rstd * g[d] + bb[d];
}

// ======================= launch =======================
extern "C" void kernel_launch(void* const* d_in, const int* in_sizes, int n_in,
                              void* d_out, int out_size)
{
    (void)in_sizes; (void)n_in; (void)out_size;
    const float* src    = (const float*)d_in[0];
    const float* in_w   = (const float*)d_in[1];
    const float* in_b   = (const float*)d_in[2];
    const float* outp_w = (const float*)d_in[3];
    const float* outp_b = (const float*)d_in[4];
    const float* Qp_w   = (const float*)d_in[5];
    const float* Qp_b   = (const float*)d_in[6];
    const float* Kp_w   = (const float*)d_in[7];
    const float* Kp_b   = (const float*)d_in[8];
    const float* Vp_w   = (const float*)d_in[9];
    const float* Vp_b   = (const float*)d_in[10];
    const float* lam    = (const float*)d_in[11];
    const float* ff1_w  = (const float*)d_in[12];
    const float* ff1_b  = (const float*)d_in[13];
    const float* ff2_w  = (const float*)d_in[14];
    const float* ff2_b  = (const float*)d_in[15];
    const float* ln1_g  = (const float*)d_in[16];
    const float* ln1_b  = (const float*)d_in[17];
    const float* ln2_g  = (const float*)d_in[18];
    const float* ln2_b  = (const float*)d_in[19];
    float* out = (float*)d_out;

    __half *hw_pack, *hw_out, *hw_f1, *hw_f2;
    __half *src_h, *proj_h, *ctx_h, *Vt_h, *Ph, *x_h, *h1_h;
    float *bias_pack, *bias_dense, *sigbuf, *P, *fused, *x, *ff;
    cudaGetSymbolAddress((void**)&hw_pack,    g_hw_pack);
    cudaGetSymbolAddress((void**)&hw_out,     g_hw_out);
    cudaGetSymbolAddress((void**)&hw_f1,      g_hw_f1);
    cudaGetSymbolAddress((void**)&hw_f2,      g_hw_f2);
    cudaGetSymbolAddress((void**)&bias_pack,  g_bias_pack);
    cudaGetSymbolAddress((void**)&bias_dense, g_bias_dense);
    cudaGetSymbolAddress((void**)&sigbuf,     g_sig);
    cudaGetSymbolAddress((void**)&src_h,      g_src_h);
    cudaGetSymbolAddress((void**)&proj_h,     g_proj_h);
    cudaGetSymbolAddress((void**)&ctx_h,      g_ctx_h);
    cudaGetSymbolAddress((void**)&Vt_h,       g_Vt_h);
    cudaGetSymbolAddress((void**)&Ph,         g_Ph);
    cudaGetSymbolAddress((void**)&x_h,        g_x_h);
    cudaGetSymbolAddress((void**)&h1_h,       g_h1_h);
    cudaGetSymbolAddress((void**)&P,          g_P);
    cudaGetSymbolAddress((void**)&fused,      g_fused);
    cudaGetSymbolAddress((void**)&x,          g_x);
    cudaGetSymbolAddress((void**)&ff,         g_ff);

    cudaFuncSetAttribute(hgemm_nt, cudaFuncAttributeMaxDynamicSharedMemorySize, GEMM_SMEM);

    // Fork-join streams/events: created ONCE on the first (correctness) call so
    // their lazy device resources predate the harness's pre-capture memory
    // baseline. The capture call reuses them — no allocation during/after capture.
    static cudaStream_t sA = nullptr, sB = nullptr;
    static cudaEvent_t evC = nullptr, evA = nullptr, evB = nullptr;
    if (!sA) {
        cudaStreamCreateWithFlags(&sA, cudaStreamNonBlocking);
        cudaStreamCreateWithFlags(&sB, cudaStreamNonBlocking);
        cudaEventCreateWithFlags(&evC, cudaEventDisableTiming);
        cudaEventCreateWithFlags(&evA, cudaEventDisableTiming);
        cudaEventCreateWithFlags(&evB, cudaEventDisableTiming);
    }

    // 0. fused conversion (main stream)
    convert_all<<<17537, 256>>>(in_w, outp_w, Vp_w, ff1_w, ff2_w, src,
                                Qp_w, Kp_w, in_b, Qp_b, Kp_b, Vp_b, outp_b, lam,
                                hw_pack, hw_out, hw_f1, hw_f2, src_h,
                                bias_pack, bias_dense, sigbuf);

    // 1. proj = src @ [in_w;Qp;Kp;Vp]^T + b  -> half [4096, 4224] (main stream)
    hgemm_nt<<<dim3(PROJN / BN, NTOK / BM), 256, GEMM_SMEM>>>(
        src_h, hw_pack, DD, DD, DD, 0, 0,
        src_h, hw_pack, 0, DD, DD, 0, 0,
        bias_pack, proj_h, PROJN, 0, 1.f, 0, 1);
    cudaEventRecord(evC, 0);
    cudaStreamWaitEvent(sA, evC, 0);
    cudaStreamWaitEvent(sB, evC, 0);

    // ---- branch A: dense flash attention (scales ctx by sig) ----
    flash_attn_kernel<<<dim3(SS / 128, HH, BB), 256, 0, sA>>>(proj_h, sigbuf, ctx_h);
    cudaEventRecord(evA, sA);

    // ---- branch B: sparse path ----
    hgemm_nt<<<dim3(SS / BN, SS / BM, BB), 256, GEMM_SMEM, sB>>>(
        proj_h + 3 * DD, proj_h + 3 * DD + RR, RR, PROJN, PROJN,
        (long)SS * PROJN, (long)SS * PROJN,
        proj_h, proj_h, 0, PROJN, PROJN, 0, 0,
        nullptr, P, SS, (long)SS * SS, 0.125f, 0, 0);
    topk_softmax_kernel<<<NTOK, 256, 0, sB>>>(P, sigbuf, Ph);
    transpose_proj_kernel<<<dim3(SS / 32, DD / 32, BB), 256, 0, sB>>>(proj_h, Vt_h);
    cudaEventRecord(evB, sB);

    // ---- join ----
    cudaStreamWaitEvent(0, evA, 0);
    cudaStreamWaitEvent(0, evB, 0);

    // 6. fused = sig*(ctx@out^T + b) + (1-sig)*(P@V)  [two K-segments] -> f32
    hgemm_nt<<<dim3(DD / BN, SS / BM, BB), 256, GEMM_SMEM>>>(
        ctx_h, hw_out, DD, DD, DD, (long)SS * DD, 0,
        Ph, Vt_h, SS, SS, SS, (long)SS * SS, (long)DD * SS,
        bias_dense, fused, DD, (long)SS * DD, 1.f, 0, 0);
    // 7. x = LN1(src + fused) -> f32 + half
    fuse_ln1_kernel<<<NTOK, 256>>>(src, fused, ln1_g, ln1_b, x, x_h);
    // 8. h1 = relu(x @ ff1^T + b) -> half
    hgemm_nt<<<dim3(DFFN / BN, NTOK / BM), 256, GEMM_SMEM>>>(
        x_h, hw_f1, DD, DD, DD, 0, 0,
        x_h, hw_f1, 0, DD, DD, 0, 0,
        ff1_b, h1_h, DFFN, 0, 1.f, 1, 1);
    // 9. ff = h1 @ ff2^T + b -> f32
    hgemm_nt<<<dim3(DD / BN, NTOK / BM), 256, GEMM_SMEM>>>(
        h1_h, hw_f2, DFFN, DFFN, DFFN, 0, 0,
        h1_h, hw_f2, 0, DFFN, DFFN, 0, 0,
        ff2_b, ff, DD, 0, 1.f, 0, 0);
    // 10. out = LN2(x + ff)
    ln2_kernel<<<NTOK, 256>>>(x, ff, ln2_g, ln2_b, out);
}

// round 12
// speedup vs baseline: 1.0887x; 1.0280x over previous
#include <cuda_runtime.h>
#include <cuda_fp16.h>
#include <cstdint>
#include <math.h>

// Problem dims
#define BB   4
#define SS   1024
#define DD   1024
#define HH   16
#define DH   64
#define RR   64
#define DFFN 4096
#define NTOK (BB*SS)       // 4096
#define KSEL 204           // int(1024*0.2)
#define PROJN 4224         // 3*DD + 2*RR + DD  (qkv | Q | K | V)

// ---------------- scratch (device globals) ----------------
__device__ __half g_hw_pack[(long)PROJN * DD];   // [in_w; Qp; Kp; Vp]
__device__ float  g_bias_pack[PROJN];
__device__ __half g_hw_out[(long)DD * DD];
__device__ float  g_bias_dense[DD];              // sig * out_b
__device__ float  g_sig[1];
__device__ __half g_hw_f1[(long)DFFN * DD];
__device__ __half g_hw_f2[(long)DD * DFFN];
__device__ __half g_src_h[(long)NTOK * DD];
__device__ __half g_proj_h[(long)NTOK * PROJN];  // [tok][4224]
__device__ __half g_ctx_h[(long)NTOK * DD];      // pre-scaled by sig
__device__ __half g_Vt_h[(long)NTOK * DD];       // per-batch [DD][SS]
__device__ __half g_Ph[(long)BB * SS * SS];      // pre-scaled by 1-sig
__device__ float g_P[(long)BB * SS * SS];
__device__ float g_dense[(long)NTOK * DD];
__device__ float g_sparse[(long)NTOK * DD];
__device__ float g_x[(long)NTOK * DD];
__device__ __half g_x_h[(long)NTOK * DD];
__device__ __half g_h1_h[(long)NTOK * DFFN];
__device__ float g_ff[(long)NTOK * DD];

// ======================= helpers =======================
__device__ __forceinline__ uint32_t smem_u32(const void* p) {
    uint32_t a;
    asm("{ .reg .u64 t; cvta.to.shared.u64 t, %1; cvt.u32.u64 %0, t; }" : "=r"(a) : "l"(p));
    return a;
}
__device__ __forceinline__ void cp16(uint32_t saddr, const void* g) {
    asm volatile("cp.async.ca.shared.global [%0], [%1], 16;"
                 :: "r"(saddr), "l"(g) : "memory");
}
#define CP_COMMIT() asm volatile("cp.async.commit_group;" ::: "memory")
#define CP_WAIT2()  asm volatile("cp.async.wait_group 2;" ::: "memory")
#define CP_WAIT1()  asm volatile("cp.async.wait_group 1;" ::: "memory")
#define CP_WAIT0()  asm volatile("cp.async.wait_group 0;" ::: "memory")

__device__ __forceinline__ void mma_f16(float* c, const uint32_t* a, const uint32_t* b) {
    asm volatile(
        "mma.sync.aligned.m16n8k16.row.col.f32.f16.f16.f32 "
        "{%0,%1,%2,%3}, {%4,%5,%6,%7}, {%8,%9}, {%0,%1,%2,%3};"
        : "+f"(c[0]), "+f"(c[1]), "+f"(c[2]), "+f"(c[3])
        : "r"(a[0]), "r"(a[1]), "r"(a[2]), "r"(a[3]), "r"(b[0]), "r"(b[1]));
}
__device__ __forceinline__ void ldsm_x4(uint32_t* r, uint32_t saddr) {
    asm volatile("ldmatrix.sync.aligned.m8n8.x4.shared.b16 {%0,%1,%2,%3}, [%4];"
                 : "=r"(r[0]), "=r"(r[1]), "=r"(r[2]), "=r"(r[3]) : "r"(saddr));
}
__device__ __forceinline__ uint32_t h2u(float x, float y) {
    __half2 h = __floats2half2_rn(x, y);
    return *(uint32_t*)&h;
}

// ======================= critical converter (pack weights + src + biases + sig) =======================
// blocks: [0,4224) pack rows | [4224,8320) src | 8320 = biases + sig
__global__ __launch_bounds__(256) void convert_crit(
    const float* in_w, const float* Qp_w, const float* Kp_w, const float* Vp_w,
    const float* src,
    const float* in_b, const float* Qp_b, const float* Kp_b, const float* Vp_b,
    const float* outp_b, const float* lam,
    __half* hw_pack, __half* src_h,
    float* bias_pack, float* bias_dense, float* sigbuf)
{
    const int bid = blockIdx.x, t = threadIdx.x;
    if (bid == 8320) {
        const float sig = 1.f / (1.f + __expf(-lam[0]));
        if (t == 0) sigbuf[0] = sig;
        for (int i = t; i < PROJN; i += 256) {
            float v;
            if      (i < 3 * DD)          v = in_b[i];
            else if (i < 3 * DD + RR)     v = Qp_b[i - 3 * DD];
            else if (i < 3 * DD + 2 * RR) v = Kp_b[i - 3 * DD - RR];
            else                          v = Vp_b[i - 3 * DD - 2 * RR];
            bias_pack[i] = v;
        }
        for (int i = t; i < DD; i += 256)
            bias_dense[i] = sig * outp_b[i];
        return;
    }
    const float* in; __half* out;
    if (bid < PROJN) {
        const int r = bid;
        if      (r < 3 * DD)          in = in_w + (long)r * DD;
        else if (r < 3 * DD + RR)     in = Qp_w + (long)(r - 3 * DD) * DD;
        else if (r < 3 * DD + 2 * RR) in = Kp_w + (long)(r - 3 * DD - RR) * DD;
        else                          in = Vp_w + (long)(r - 3 * DD - 2 * RR) * DD;
        out = hw_pack + (long)bid * DD;
    } else {
        in = src + (long)(bid - PROJN) * 1024;
        out = src_h + (long)(bid - PROJN) * 1024;
    }
    long i = t * 4;
    float4 v = *(const float4*)(in + i);
    *(__half2*)(out + i) = __floats2half2_rn(v.x, v.y);
    *(__half2*)(out + i + 2) = __floats2half2_rn(v.z, v.w);
}

// ======================= non-critical converter (out_proj, ff1, ff2) =======================
// blocks: [0,1024) outp | [1024,5120) ff1 | [5120,9216) ff2
__global__ __launch_bounds__(256) void convert_rest(
    const float* outp_w, const float* ff1_w, const float* ff2_w,
    __half* hw_out, __half* hw_f1, __half* hw_f2)
{
    const int bid = blockIdx.x, t = threadIdx.x;
    const float* in; __half* out; long off;
    if      (bid < 1024) { in = outp_w; out = hw_out; off = (long)bid * 1024; }
    else if (bid < 5120) { in = ff1_w;  out = hw_f1;  off = (long)(bid - 1024) * 1024; }
    else                 { in = ff2_w;  out = hw_f2;  off = (long)(bid - 5120) * 1024; }
    long i = off + t * 4;
    float4 v = *(const float4*)(in + i);
    *(__half2*)(out + i) = __floats2half2_rn(v.x, v.y);
    *(__half2*)(out + i + 2) = __floats2half2_rn(v.z, v.w);
}

// ======================= fp16 warp-MMA GEMM, two K-segments =======================
#define BM 256
#define BN 128
#define BKH 32
#define KSTRH 20
#define A_B32 (BM * KSTRH)
#define STG_B32 (A_B32 + BN * KSTRH)
#define GEMM_SMEM (3 * STG_B32 * 4)

__global__ __launch_bounds__(256) void hgemm_nt(
    const __half* __restrict__ A1, const __half* __restrict__ B1,
    int K1, int lda1, int ldb1, long sA1, long sB1,
    const __half* __restrict__ A2, const __half* __restrict__ B2,
    int K2, int lda2, int ldb2, long sA2, long sB2,
    const float* __restrict__ bias, void* __restrict__ Cout,
    int N, long sC, float alpha, int relu, int out_half)
{
    extern __shared__ uint32_t gsm[];

    const __half* A1g = A1 + (long)blockIdx.z * sA1;
    const __half* B1g = B1 + (long)blockIdx.z * sB1;
    const __half* A2g = A2 + (long)blockIdx.z * sA2;
    const __half* B2g = B2 + (long)blockIdx.z * sB2;

    const int t = threadIdx.x;
    const int wid = t >> 5, l = t & 31;
    const int wm = wid >> 1, wn = wid & 1;
    const int mbase = wm * 64, nbase = wn * 64;
    const int qr = l >> 2, qc = l & 3;
    const int row0 = blockIdx.y * BM, col0 = blockIdx.x * BN;

    const uint32_t s0 = smem_u32(gsm);

    const int lr = t >> 2;
    const int lc4 = (t & 3) * 4;

    const uint32_t a_lm = s0 + (uint32_t)(((mbase + (l & 15)) * KSTRH + (l >> 4) * 4) * 4);
    const uint32_t b_lm = s0 + (uint32_t)((A_B32 +
        (nbase + (l & 7) + ((l >> 4) << 3)) * KSTRH + (((l >> 3) & 1) * 4)) * 4);

    float acc[4][8][4];
#pragma unroll
    for (int i = 0; i < 4; i++)
#pragma unroll
        for (int j = 0; j < 8; j++)
#pragma unroll
            for (int q = 0; q < 4; q++) acc[i][j][q] = 0.f;

    const int nc1 = K1 / BKH;
    const int nc = nc1 + K2 / BKH;

    auto prefetch = [&](int cc) {
        const int st = cc % 3;
        const __half* Ax; const __half* Bx; int k0, la, lb;
        if (cc < nc1) { Ax = A1g; Bx = B1g; k0 = cc * BKH; la = lda1; lb = ldb1; }
        else          { Ax = A2g; Bx = B2g; k0 = (cc - nc1) * BKH; la = lda2; lb = ldb2; }
        const uint32_t sAs = s0 + st * STG_B32 * 4;
        const uint32_t sBs = sAs + A_B32 * 4;
#pragma unroll
        for (int j = 0; j < 4; j++) {
            int m = lr + j * 64;
            cp16(sAs + (m * KSTRH + lc4) * 4, &Ax[(long)(row0 + m) * la + k0 + lc4 * 2]);
        }
#pragma unroll
        for (int j = 0; j < 2; j++) {
            int n = lr + j * 64;
            cp16(sBs + (n * KSTRH + lc4) * 4, &Bx[(long)(col0 + n) * lb + k0 + lc4 * 2]);
        }
        CP_COMMIT();
    };

    prefetch(0);
    if (nc > 1) prefetch(1);

    for (int c = 0; c < nc; c++) {
        if (c + 2 < nc) { prefetch(c + 2); CP_WAIT2(); }
        else if (c + 1 < nc) { CP_WAIT1(); }
        else { CP_WAIT0(); }
        __syncthreads();

        const uint32_t stoff = (uint32_t)((c % 3) * STG_B32 * 4);
#pragma unroll
        for (int kk = 0; kk < 2; kk++) {
            const uint32_t koff = stoff + kk * 8 * 4;
            uint32_t af[4][4], bf[4][4];
#pragma unroll
            for (int mt = 0; mt < 4; mt++)
                ldsm_x4(af[mt], a_lm + koff + mt * 16 * KSTRH * 4);
#pragma unroll
            for (int np = 0; np < 4; np++)
                ldsm_x4(bf[np], b_lm + koff + np * 16 * KSTRH * 4);
#pragma unroll
            for (int mt = 0; mt < 4; mt++) {
#pragma unroll
                for (int nt = 0; nt < 8; nt++)
                    mma_f16(acc[mt][nt], af[mt], &bf[nt >> 1][(nt & 1) * 2]);
            }
        }
        __syncthreads();
    }

    // ---- epilogue ----
#pragma unroll
    for (int mt = 0; mt < 4; mt++) {
        const int r = row0 + mbase + mt * 16 + qr;
#pragma unroll
        for (int nt = 0; nt < 8; nt++) {
            const int cc = col0 + nbase + nt * 8 + qc * 2;
            float b0 = 0.f, b1 = 0.f;
            if (bias) { b0 = bias[cc]; b1 = bias[cc + 1]; }
            float v0 = acc[mt][nt][0] * alpha + b0;
            float v1 = acc[mt][nt][1] * alpha + b1;
            float v2 = acc[mt][nt][2] * alpha + b0;
            float v3 = acc[mt][nt][3] * alpha + b1;
            if (relu) {
                v0 = fmaxf(v0, 0.f); v1 = fmaxf(v1, 0.f);
                v2 = fmaxf(v2, 0.f); v3 = fmaxf(v3, 0.f);
            }
            if (out_half) {
                __half* C = (__half*)Cout + blockIdx.z * sC;
                *(__half2*)&C[(long)r * N + cc] = __floats2half2_rn(v0, v1);
                *(__half2*)&C[(long)(r + 8) * N + cc] = __floats2half2_rn(v2, v3);
            } else {
                float* C = (float*)Cout + blockIdx.z * sC;
                float2 p0 = {v0, v1}, p1 = {v2, v3};
                *(float2*)&C[(long)r * N + cc] = p0;
                *(float2*)&C[(long)(r + 8) * N + cc] = p1;
            }
        }
    }
}

// ======================= half transpose from proj (V cols) =======================
__global__ __launch_bounds__(256) void transpose_proj_kernel(const __half* __restrict__ proj,
                                                             __half* __restrict__ Vt)
{
    __shared__ __half tile[32][33];
    const __half* Pb = proj + (long)blockIdx.z * SS * PROJN + (3 * DD + 2 * RR);
    __half* Vtb = Vt + (long)blockIdx.z * DD * SS;
    const int s0 = blockIdx.x * 32, d0 = blockIdx.y * 32;
    const int tx = threadIdx.x & 31, ty0 = threadIdx.x >> 5;
#pragma unroll
    for (int i = 0; i < 4; i++) {
        int ty = ty0 + i * 8;
        tile[ty][tx] = Pb[(long)(s0 + ty) * PROJN + d0 + tx];
    }
    __syncthreads();
#pragma unroll
    for (int i = 0; i < 4; i++) {
        int ty = ty0 + i * 8;
        Vtb[(long)(d0 + ty) * SS + s0 + tx] = tile[tx][ty];
    }
}

// ======================= fp16 flash attention (reads proj, scales by sig) =======================
#define FSTR 36

__global__ __launch_bounds__(256) void flash_attn_kernel(const __half* __restrict__ proj,
                                                         const float* __restrict__ sigbuf,
                                                         __half* __restrict__ ctx)
{
    __shared__ uint32_t ps[128 * FSTR];
    __shared__ uint32_t ks[64 * FSTR];
    __shared__ uint32_t vs[64 * FSTR];
    __half* vs_h = (__half*)vs;

    const int t = threadIdx.x, w = t >> 5, l = t & 31;
    const int qr = l >> 2, qc = l & 3;
    const int q0 = blockIdx.x * 128, h = blockIdx.y, b = blockIdx.z;
    const int wr = w * 16;

    const __half* Qg = proj + (long)(b * SS + q0) * PROJN + h * DH;
    const __half* Kg = proj + (long)(b * SS) * PROJN + DD + h * DH;
    const __half* Vg = proj + (long)(b * SS) * PROJN + 2 * DD + h * DH;

#pragma unroll
    for (int i = 0; i < 4; i++) {
        int idx = t + i * 256;
        int r = idx >> 3, c16 = idx & 7;
        float4 v = *(const float4*)(Qg + (long)r * PROJN + c16 * 8);
        *(float4*)&ps[r * FSTR + c16 * 4] = v;
    }
    __syncthreads();
    uint32_t qa[4][4];
#pragma unroll
    for (int k = 0; k < 4; k++) {
        qa[k][0] = ps[(wr + qr) * FSTR + k * 8 + qc];
        qa[k][1] = ps[(wr + qr + 8) * FSTR + k * 8 + qc];
        qa[k][2] = ps[(wr + qr) * FSTR + k * 8 + qc + 4];
        qa[k][3] = ps[(wr + qr + 8) * FSTR + k * 8 + qc + 4];
    }
    __syncthreads();

    float m0 = -1e30f, m1 = -1e30f, l0 = 0.f, l1 = 0.f;
    float o[8][4];
#pragma unroll
    for (int n = 0; n < 8; n++)
#pragma unroll
        for (int i = 0; i < 4; i++) o[n][i] = 0.f;

    for (int kt = 0; kt < SS; kt += 64) {
#pragma unroll
        for (int i = 0; i < 2; i++) {
            int idx = t + i * 256;
            int r = idx >> 3, c16 = idx & 7;
            float4 kv = *(const float4*)(Kg + (long)(kt + r) * PROJN + c16 * 8);
            *(float4*)&ks[r * FSTR + c16 * 4] = kv;
            float4 vv = *(const float4*)(Vg + (long)(kt + r) * PROJN + c16 * 8);
            const __half* vh = (const __half*)&vv;
#pragma unroll
            for (int j = 0; j < 8; j++)
                vs_h[(c16 * 8 + j) * (2 * FSTR) + r] = vh[j];
        }
        __syncthreads();

        float sa[8][4];
#pragma unroll
        for (int n = 0; n < 8; n++)
#pragma unroll
            for (int i = 0; i < 4; i++) sa[n][i] = 0.f;
#pragma unroll
        for (int k = 0; k < 4; k++) {
#pragma unroll
            for (int n = 0; n < 8; n++) {
                uint32_t bf[2];
                bf[0] = ks[(n * 8 + qr) * FSTR + k * 8 + qc];
                bf[1] = ks[(n * 8 + qr) * FSTR + k * 8 + qc + 4];
                mma_f16(sa[n], qa[k], bf);
            }
        }

        float rm0 = -1e30f, rm1 = -1e30f;
#pragma unroll
        for (int n = 0; n < 8; n++) {
            sa[n][0] *= 0.125f; sa[n][1] *= 0.125f;
            sa[n][2] *= 0.125f; sa[n][3] *= 0.125f;
            rm0 = fmaxf(rm0, fmaxf(sa[n][0], sa[n][1]));
            rm1 = fmaxf(rm1, fmaxf(sa[n][2], sa[n][3]));
        }
        rm0 = fmaxf(rm0, __shfl_xor_sync(0xffffffffu, rm0, 1));
        rm0 = fmaxf(rm0, __shfl_xor_sync(0xffffffffu, rm0, 2));
        rm1 = fmaxf(rm1, __shfl_xor_sync(0xffffffffu, rm1, 1));
        rm1 = fmaxf(rm1, __shfl_xor_sync(0xffffffffu, rm1, 2));

        const float nm0 = fmaxf(m0, rm0), nm1 = fmaxf(m1, rm1);
        const float c0 = __expf(m0 - nm0), c1 = __expf(m1 - nm1);
        float rs0 = 0.f, rs1 = 0.f;
#pragma unroll
        for (int n = 0; n < 8; n++) {
            float p0 = __expf(sa[n][0] - nm0);
            float p1 = __expf(sa[n][1] - nm0);
            float p2 = __expf(sa[n][2] - nm1);
            float p3 = __expf(sa[n][3] - nm1);
            rs0 += p0 + p1; rs1 += p2 + p3;
            ps[(wr + qr) * FSTR + n * 4 + qc] = h2u(p0, p1);
            ps[(wr + qr + 8) * FSTR + n * 4 + qc] = h2u(p2, p3);
            o[n][0] *= c0; o[n][1] *= c0; o[n][2] *= c1; o[n][3] *= c1;
        }
        rs0 += __shfl_xor_sync(0xffffffffu, rs0, 1);
        rs0 += __shfl_xor_sync(0xffffffffu, rs0, 2);
        rs1 += __shfl_xor_sync(0xffffffffu, rs1, 1);
        rs1 += __shfl_xor_sync(0xffffffffu, rs1, 2);
        l0 = l0 * c0 + rs0; l1 = l1 * c1 + rs1;
        m0 = nm0; m1 = nm1;

        __syncwarp();

#pragma unroll
        for (int k = 0; k < 4; k++) {
            uint32_t pa[4];
            pa[0] = ps[(wr + qr) * FSTR + k * 8 + qc];
            pa[1] = ps[(wr + qr + 8) * FSTR + k * 8 + qc];
            pa[2] = ps[(wr + qr) * FSTR + k * 8 + qc + 4];
            pa[3] = ps[(wr + qr + 8) * FSTR + k * 8 + qc + 4];
#pragma unroll
            for (int n = 0; n < 8; n++) {
                uint32_t bf[2];
                bf[0] = vs[(n * 8 + qr) * FSTR + k * 8 + qc];
                bf[1] = vs[(n * 8 + qr) * FSTR + k * 8 + qc + 4];
                mma_f16(o[n], pa, bf);
            }
        }
        __syncthreads();
    }

    const float sig = sigbuf[0];
    const float i0 = sig / l0, i1 = sig / l1;
    __half* Og = ctx + (long)(b * SS + q0 + wr) * DD + h * DH;
#pragma unroll
    for (int n = 0; n < 8; n++) {
        *(__half2*)&Og[(long)qr * DD + n * 8 + 2 * qc] = __floats2half2_rn(o[n][0] * i0, o[n][1] * i0);
        *(__half2*)&Og[(long)(qr + 8) * DD + n * 8 + 2 * qc] = __floats2half2_rn(o[n][2] * i1, o[n][3] * i1);
    }
}

// ======================= radix top-k + masked softmax -> half P (scaled by 1-sig) =======================
__global__ __launch_bounds__(256) void topk_softmax_kernel(const float* __restrict__ P,
                                                           const float* __restrict__ sigbuf,
                                                           __half* __restrict__ Ph)
{
    const long base = (long)blockIdx.x * SS;
    __shared__ float vals[SS];
    __shared__ unsigned keys[SS];
    __shared__ unsigned hist[256];
    __shared__ float redA[8], redB[8];
    __shared__ unsigned s_prefix;
    __shared__ int s_need;

    const int t = threadIdx.x;
    const int w = t >> 5, lane = t & 31;

    float lmax = -1e30f;
#pragma unroll
    for (int i = 0; i < 4; i++) {
        float v = P[base + t + i * 256];
        vals[t + i * 256] = v;
        unsigned u = __float_as_uint(v);
        u ^= (u >> 31) ? 0xFFFFFFFFu : 0x80000000u;
        keys[t + i * 256] = u;
        lmax = fmaxf(lmax, v);
    }
#pragma unroll
    for (int o = 16; o > 0; o >>= 1)
        lmax = fmaxf(lmax, __shfl_xor_sync(0xffffffffu, lmax, o));
    if (lane == 0) redA[w] = lmax;
    __syncthreads();
    float mx = redA[0];
#pragma unroll
    for (int i = 1; i < 8; i++) mx = fmaxf(mx, redA[i]);

    unsigned prefix = 0;
    int need = KSEL;
#pragma unroll
    for (int pass = 0; pass < 4; pass++) {
        const int shift = 24 - 8 * pass;
        const unsigned hmask = pass ? (0xFFFFFFFFu << (shift + 8)) : 0u;
        hist[t] = 0;
        __syncthreads();
#pragma unroll
        for (int i = 0; i < 4; i++) {
            unsigned u = keys[t + i * 256];
            if ((u & hmask) == prefix)
                atomicAdd(&hist[(u >> shift) & 0xFFu], 1u);
        }
        __syncthreads();
        if (t == 0) {
            int cum = 0, bsel = 0;
            for (int bbin = 255; bbin >= 0; bbin--) {
                int hh = (int)hist[bbin];
                if (cum + hh >= need) { bsel = bbin; break; }
                cum += hh;
            }
            s_prefix = prefix | ((unsigned)bsel << shift);
            s_need = need - cum;
        }
        __syncthreads();
        prefix = s_prefix;
        need = s_need;
        __syncthreads();
    }
    const unsigned thr = prefix;

    float e[4];
    float sk = 0.f, sf = 0.f;
#pragma unroll
    for (int i = 0; i < 4; i++) {
        float v = vals[t + i * 256];
        float ef = __expf(v - mx);
        bool kp = keys[t + i * 256] >= thr;
        e[i] = kp ? ef : 0.f;
        sk += e[i];
        sf += ef;
    }
#pragma unroll
    for (int o = 16; o > 0; o >>= 1) {
        sk += __shfl_xor_sync(0xffffffffu, sk, o);
        sf += __shfl_xor_sync(0xffffffffu, sf, o);
    }
    if (lane == 0) { redA[w] = sk; redB[w] = sf; }
    __syncthreads();
    float tk = 0.f, tf = 0.f;
#pragma unroll
    for (int i = 0; i < 8; i++) { tk += redA[i]; tf += redB[i]; }
    const float inv = (1.f - sigbuf[0]) / (tk + 1e-9f * tf);
#pragma unroll
    for (int i = 0; i < 4; i++)
        Ph[base + t + i * 256] = __float2half(e[i] * inv);
}

// ======================= residual + LN1 (3 inputs) =======================
__global__ __launch_bounds__(256) void fuse_ln1_kernel(
    const float* __restrict__ src, const float* __restrict__ dense,
    const float* __restrict__ sparse,
    const float* __restrict__ g, const float* __restrict__ bb,
    float* __restrict__ x, __half* __restrict__ xh)
{
    const long row = (long)blockIdx.x * DD;
    __shared__ float buf[DD];
    __shared__ float r1[8], r2[8];

    float s1 = 0.f, s2 = 0.f;
    for (int d = threadIdx.x; d < DD; d += 256) {
        float v = src[row + d] + dense[row + d] + sparse[row + d];
        buf[d] = v; s1 += v; s2 += v * v;
    }
#pragma unroll
    for (int o = 16; o > 0; o >>= 1) {
        s1 += __shfl_xor_sync(0xffffffffu, s1, o);
        s2 += __shfl_xor_sync(0xffffffffu, s2, o);
    }
    const int w = threadIdx.x >> 5, lane = threadIdx.x & 31;
    if (lane == 0) { r1[w] = s1; r2[w] = s2; }
    __syncthreads();
    if (threadIdx.x == 0) {
        float a = 0.f, c = 0.f;
        for (int i = 0; i < 8; i++) { a += r1[i]; c += r2[i]; }
        r1[0] = a; r2[0] = c;
    }
    __syncthreads();
    const float mean = r1[0] * (1.f / DD);
    const float var = r2[0] * (1.f / DD) - mean * mean;
    const float rstd = rsqrtf(var + 1e-5f);
    for (int d = threadIdx.x; d < DD; d += 256) {
        float v = (buf[d] - mean) * rstd * g[d] + bb[d];
        x[row + d] = v;
        xh[row + d] = __float2half(v);
    }
}

// ======================= residual + LN2 -> out =======================
__global__ __launch_bounds__(256) void ln2_kernel(
    const float* __restrict__ x, const float* __restrict__ ff,
    const float* __restrict__ g, const float* __restrict__ bb,
    float* __restrict__ out)
{
    const long row = (long)blockIdx.x * DD;
    __shared__ float buf[DD];
    __shared__ float r1[8], r2[8];

    float s1 = 0.f, s2 = 0.f;
    for (int d = threadIdx.x; d < DD; d += 256) {
        float v = x[row + d] + ff[row + d];
        buf[d] = v; s1 += v; s2 += v * v;
    }
#pragma unroll
    for (int o = 16; o > 0; o >>= 1) {
        s1 += __shfl_xor_sync(0xffffffffu, s1, o);
        s2 += __shfl_xor_sync(0xffffffffu, s2, o);
    }
    const int w = threadIdx.x >> 5, lane = threadIdx.x & 31;
    if (lane == 0) { r1[w] = s1; r2[w] = s2; }
    __syncthreads();
    if (threadIdx.x == 0) {
        float a = 0.f, c = 0.f;
        for (int i = 0; i < 8; i++) { a += r1[i]; c += r2[i]; }
        r1[0] = a; r2[0] = c;
    }
    __syncthreads();
    const float mean = r1[0] * (1.f / DD);
    const float var = r2[0] * (1.f / DD) - mean * mean;
    const float rstd = rsqrtf(var + 1e-5f);
    for (int d = threadIdx.x; d < DD; d += 256)
        out[row + d] = (buf[d] - mean) * rstd * g[d] + bb[d];
}

// ======================= launch =======================
extern "C" void kernel_launch(void* const* d_in, const int* in_sizes, int n_in,
                              void* d_out, int out_size)
{
    (void)in_sizes; (void)n_in; (void)out_size;
    const float* src    = (const float*)d_in[0];
    const float* in_w   = (const float*)d_in[1];
    const float* in_b   = (const float*)d_in[2];
    const float* outp_w = (const float*)d_in[3];
    const float* outp_b = (const float*)d_in[4];
    const float* Qp_w   = (const float*)d_in[5];
    const float* Qp_b   = (const float*)d_in[6];
    const float* Kp_w   = (const float*)d_in[7];
    const float* Kp_b   = (const float*)d_in[8];
    const float* Vp_w   = (const float*)d_in[9];
    const float* Vp_b   = (const float*)d_in[10];
    const float* lam    = (const float*)d_in[11];
    const float* ff1_w  = (const float*)d_in[12];
    const float* ff1_b  = (const float*)d_in[13];
    const float* ff2_w  = (const float*)d_in[14];
    const float* ff2_b  = (const float*)d_in[15];
    const float* ln1_g  = (const float*)d_in[16];
    const float* ln1_b  = (const float*)d_in[17];
    const float* ln2_g  = (const float*)d_in[18];
    const float* ln2_b  = (const float*)d_in[19];
    float* out = (float*)d_out;

    __half *hw_pack, *hw_out, *hw_f1, *hw_f2;
    __half *src_h, *proj_h, *ctx_h, *Vt_h, *Ph, *x_h, *h1_h;
    float *bias_pack, *bias_dense, *sigbuf, *P, *dense, *sparse, *x, *ff;
    cudaGetSymbolAddress((void**)&hw_pack,    g_hw_pack);
    cudaGetSymbolAddress((void**)&hw_out,     g_hw_out);
    cudaGetSymbolAddress((void**)&hw_f1,      g_hw_f1);
    cudaGetSymbolAddress((void**)&hw_f2,      g_hw_f2);
    cudaGetSymbolAddress((void**)&bias_pack,  g_bias_pack);
    cudaGetSymbolAddress((void**)&bias_dense, g_bias_dense);
    cudaGetSymbolAddress((void**)&sigbuf,     g_sig);
    cudaGetSymbolAddress((void**)&src_h,      g_src_h);
    cudaGetSymbolAddress((void**)&proj_h,     g_proj_h);
    cudaGetSymbolAddress((void**)&ctx_h,      g_ctx_h);
    cudaGetSymbolAddress((void**)&Vt_h,       g_Vt_h);
    cudaGetSymbolAddress((void**)&Ph,         g_Ph);
    cudaGetSymbolAddress((void**)&x_h,        g_x_h);
    cudaGetSymbolAddress((void**)&h1_h,       g_h1_h);
    cudaGetSymbolAddress((void**)&P,          g_P);
    cudaGetSymbolAddress((void**)&dense,      g_dense);
    cudaGetSymbolAddress((void**)&sparse,     g_sparse);
    cudaGetSymbolAddress((void**)&x,          g_x);
    cudaGetSymbolAddress((void**)&ff,         g_ff);

    cudaFuncSetAttribute(hgemm_nt, cudaFuncAttributeMaxDynamicSharedMemorySize, GEMM_SMEM);

    // Fork-join streams/events created once (first call) so device resources
    // predate the harness pre-capture baseline. Reused on the capture call.
    static cudaStream_t sA = nullptr, sB = nullptr;
    static cudaEvent_t evC = nullptr, evA = nullptr, evB = nullptr;
    if (!sA) {
        cudaStreamCreateWithFlags(&sA, cudaStreamNonBlocking);
        cudaStreamCreateWithFlags(&sB, cudaStreamNonBlocking);
        cudaEventCreateWithFlags(&evC, cudaEventDisableTiming);
        cudaEventCreateWithFlags(&evA, cudaEventDisableTiming);
        cudaEventCreateWithFlags(&evB, cudaEventDisableTiming);
    }

    // sA: non-critical weight conversion, overlapped with the critical path below
    convert_rest<<<9216, 256, 0, sA>>>(outp_w, ff1_w, ff2_w, hw_out, hw_f1, hw_f2);

    // main: critical conversion then proj GEMM
    convert_crit<<<8321, 256>>>(in_w, Qp_w, Kp_w, Vp_w, src,
                                in_b, Qp_b, Kp_b, Vp_b, outp_b, lam,
                                hw_pack, src_h, bias_pack, bias_dense, sigbuf);
    hgemm_nt<<<dim3(PROJN / BN, NTOK / BM), 256, GEMM_SMEM>>>(
        src_h, hw_pack, DD, DD, DD, 0, 0,
        src_h, hw_pack, 0, DD, DD, 0, 0,
        bias_pack, proj_h, PROJN, 0, 1.f, 0, 1);
    cudaEventRecord(evC, 0);
    cudaStreamWaitEvent(sA, evC, 0);
    cudaStreamWaitEvent(sB, evC, 0);

    // ---- branch A: flash attention -> dense = sig*(ctx@out^T) + sig*b ----
    flash_attn_kernel<<<dim3(SS / 128, HH, BB), 256, 0, sA>>>(proj_h, sigbuf, ctx_h);
    hgemm_nt<<<dim3(DD / BN, NTOK / BM), 256, GEMM_SMEM, sA>>>(
        ctx_h, hw_out, DD, DD, DD, 0, 0,
        ctx_h, hw_out, 0, DD, DD, 0, 0,
        bias_dense, dense, DD, 0, 1.f, 0, 0);
    cudaEventRecord(evA, sA);

    // ---- branch B: scores -> topk -> transpose -> sparse = (1-sig)*(P@V) ----
    hgemm_nt<<<dim3(SS / BN, SS / BM, BB), 256, GEMM_SMEM, sB>>>(
        proj_h + 3 * DD, proj_h + 3 * DD + RR, RR, PROJN, PROJN,
        (long)SS * PROJN, (long)SS * PROJN,
        proj_h, proj_h, 0, PROJN, PROJN, 0, 0,
        nullptr, P, SS, (long)SS * SS, 0.125f, 0, 0);
    topk_softmax_kernel<<<NTOK, 256, 0, sB>>>(P, sigbuf, Ph);
    transpose_proj_kernel<<<dim3(SS / 32, DD / 32, BB), 256, 0, sB>>>(proj_h, Vt_h);
    hgemm_nt<<<dim3(DD / BN, SS / BM, BB), 256, GEMM_SMEM, sB>>>(
        Ph, Vt_h, SS, SS, SS, (long)SS * SS, (long)DD * SS,
        Ph, Vt_h, 0, SS, SS, 0, 0,
        nullptr, sparse, DD, (long)SS * DD, 1.f, 0, 0);
    cudaEventRecord(evB, sB);

    // ---- join ----
    cudaStreamWaitEvent(0, evA, 0);
    cudaStreamWaitEvent(0, evB, 0);

    // 7. x = LN1(src + dense + sparse) -> f32 + half
    fuse_ln1_kernel<<<NTOK, 256>>>(src, dense, sparse, ln1_g, ln1_b, x, x_h);
    // 8. h1 = relu(x @ ff1^T + b) -> half
    hgemm_nt<<<dim3(DFFN / BN, NTOK / BM), 256, GEMM_SMEM>>>(
        x_h, hw_f1, DD, DD, DD, 0, 0,
        x_h, hw_f1, 0, DD, DD, 0, 0,
        ff1_b, h1_h, DFFN, 0, 1.f, 1, 1);
    // 9. ff = h1 @ ff2^T + b -> f32
    hgemm_nt<<<dim3(DD / BN, NTOK / BM), 256, GEMM_SMEM>>>(
        h1_h, hw_f2, DFFN, DFFN, DFFN, 0, 0,
        h1_h, hw_f2, 0, DFFN, DFFN, 0, 0,
        ff2_b, ff, DD, 0, 1.f, 0, 0);
    // 10. out = LN2(x + ff)
    ln2_kernel<<<NTOK, 256>>>(x, ff, ln2_g, ln2_b, out);
}

// round 13
// speedup vs baseline: 1.1406x; 1.0476x over previous
#include <cuda_runtime.h>
#include <cuda_fp16.h>
#include <cstdint>
#include <math.h>

// Problem dims
#define BB   4
#define SS   1024
#define DD   1024
#define HH   16
#define DH   64
#define RR   64
#define DFFN 4096
#define NTOK (BB*SS)       // 4096
#define KSEL 204           // int(1024*0.2)
#define PROJN 4224         // 3*DD + 2*RR + DD  (qkv | Q | K | V)

// ---------------- scratch (device globals) ----------------
__device__ __half g_hw_pack[(long)PROJN * DD];
__device__ float  g_bias_pack[PROJN];
__device__ __half g_hw_out[(long)DD * DD];
__device__ float  g_bias_dense[DD];
__device__ float  g_sig[1];
__device__ __half g_hw_f1[(long)DFFN * DD];
__device__ __half g_hw_f2[(long)DD * DFFN];
__device__ __half g_src_h[(long)NTOK * DD];
__device__ __half g_proj_h[(long)NTOK * PROJN];
__device__ __half g_ctx_h[(long)NTOK * DD];
__device__ __half g_Vt_h[(long)NTOK * DD];
__device__ __half g_Ph[(long)BB * SS * SS];
__device__ float g_P[(long)BB * SS * SS];
__device__ float g_dense[(long)NTOK * DD];
__device__ float g_sparse[(long)NTOK * DD];
__device__ float g_x[(long)NTOK * DD];
__device__ __half g_x_h[(long)NTOK * DD];
__device__ __half g_h1_h[(long)NTOK * DFFN];
__device__ float g_ff[(long)NTOK * DD];

// ======================= helpers =======================
__device__ __forceinline__ uint32_t smem_u32(const void* p) {
    uint32_t a;
    asm("{ .reg .u64 t; cvta.to.shared.u64 t, %1; cvt.u32.u64 %0, t; }" : "=r"(a) : "l"(p));
    return a;
}
__device__ __forceinline__ void cp16(uint32_t saddr, const void* g) {
    asm volatile("cp.async.ca.shared.global [%0], [%1], 16;"
                 :: "r"(saddr), "l"(g) : "memory");
}
#define CP_COMMIT() asm volatile("cp.async.commit_group;" ::: "memory")
#define CP_WAIT2()  asm volatile("cp.async.wait_group 2;" ::: "memory")
#define CP_WAIT1()  asm volatile("cp.async.wait_group 1;" ::: "memory")
#define CP_WAIT0()  asm volatile("cp.async.wait_group 0;" ::: "memory")

__device__ __forceinline__ void mma_f16(float* c, const uint32_t* a, const uint32_t* b) {
    asm volatile(
        "mma.sync.aligned.m16n8k16.row.col.f32.f16.f16.f32 "
        "{%0,%1,%2,%3}, {%4,%5,%6,%7}, {%8,%9}, {%0,%1,%2,%3};"
        : "+f"(c[0]), "+f"(c[1]), "+f"(c[2]), "+f"(c[3])
        : "r"(a[0]), "r"(a[1]), "r"(a[2]), "r"(a[3]), "r"(b[0]), "r"(b[1]));
}
__device__ __forceinline__ void ldsm_x4(uint32_t* r, uint32_t saddr) {
    asm volatile("ldmatrix.sync.aligned.m8n8.x4.shared.b16 {%0,%1,%2,%3}, [%4];"
                 : "=r"(r[0]), "=r"(r[1]), "=r"(r[2]), "=r"(r[3]) : "r"(saddr));
}
__device__ __forceinline__ void ldsm_x4_t(uint32_t* r, uint32_t saddr) {
    asm volatile("ldmatrix.sync.aligned.m8n8.x4.trans.shared.b16 {%0,%1,%2,%3}, [%4];"
                 : "=r"(r[0]), "=r"(r[1]), "=r"(r[2]), "=r"(r[3]) : "r"(saddr));
}
__device__ __forceinline__ uint32_t h2u(float x, float y) {
    __half2 h = __floats2half2_rn(x, y);
    return *(uint32_t*)&h;
}

// ======================= critical converter =======================
__global__ __launch_bounds__(256) void convert_crit(
    const float* in_w, const float* Qp_w, const float* Kp_w, const float* Vp_w,
    const float* src,
    const float* in_b, const float* Qp_b, const float* Kp_b, const float* Vp_b,
    const float* outp_b, const float* lam,
    __half* hw_pack, __half* src_h,
    float* bias_pack, float* bias_dense, float* sigbuf)
{
    const int bid = blockIdx.x, t = threadIdx.x;
    if (bid == 8320) {
        const float sig = 1.f / (1.f + __expf(-lam[0]));
        if (t == 0) sigbuf[0] = sig;
        for (int i = t; i < PROJN; i += 256) {
            float v;
            if      (i < 3 * DD)          v = in_b[i];
            else if (i < 3 * DD + RR)     v = Qp_b[i - 3 * DD];
            else if (i < 3 * DD + 2 * RR) v = Kp_b[i - 3 * DD - RR];
            else                          v = Vp_b[i - 3 * DD - 2 * RR];
            bias_pack[i] = v;
        }
        for (int i = t; i < DD; i += 256)
            bias_dense[i] = sig * outp_b[i];
        return;
    }
    const float* in; __half* out;
    if (bid < PROJN) {
        const int r = bid;
        if      (r < 3 * DD)          in = in_w + (long)r * DD;
        else if (r < 3 * DD + RR)     in = Qp_w + (long)(r - 3 * DD) * DD;
        else if (r < 3 * DD + 2 * RR) in = Kp_w + (long)(r - 3 * DD - RR) * DD;
        else                          in = Vp_w + (long)(r - 3 * DD - 2 * RR) * DD;
        out = hw_pack + (long)bid * DD;
    } else {
        in = src + (long)(bid - PROJN) * 1024;
        out = src_h + (long)(bid - PROJN) * 1024;
    }
    long i = t * 4;
    float4 v = *(const float4*)(in + i);
    *(__half2*)(out + i) = __floats2half2_rn(v.x, v.y);
    *(__half2*)(out + i + 2) = __floats2half2_rn(v.z, v.w);
}

// ======================= non-critical converter =======================
__global__ __launch_bounds__(256) void convert_rest(
    const float* outp_w, const float* ff1_w, const float* ff2_w,
    __half* hw_out, __half* hw_f1, __half* hw_f2)
{
    const int bid = blockIdx.x, t = threadIdx.x;
    const float* in; __half* out; long off;
    if      (bid < 1024) { in = outp_w; out = hw_out; off = (long)bid * 1024; }
    else if (bid < 5120) { in = ff1_w;  out = hw_f1;  off = (long)(bid - 1024) * 1024; }
    else                 { in = ff2_w;  out = hw_f2;  off = (long)(bid - 5120) * 1024; }
    long i = off + t * 4;
    float4 v = *(const float4*)(in + i);
    *(__half2*)(out + i) = __floats2half2_rn(v.x, v.y);
    *(__half2*)(out + i + 2) = __floats2half2_rn(v.z, v.w);
}

// ======================= fp16 warp-MMA GEMM, two K-segments =======================
#define BM 256
#define BN 128
#define BKH 32
#define KSTRH 20
#define A_B32 (BM * KSTRH)
#define STG_B32 (A_B32 + BN * KSTRH)
#define GEMM_SMEM (3 * STG_B32 * 4)

__global__ __launch_bounds__(256) void hgemm_nt(
    const __half* __restrict__ A1, const __half* __restrict__ B1,
    int K1, int lda1, int ldb1, long sA1, long sB1,
    const __half* __restrict__ A2, const __half* __restrict__ B2,
    int K2, int lda2, int ldb2, long sA2, long sB2,
    const float* __restrict__ bias, void* __restrict__ Cout,
    int N, long sC, float alpha, int relu, int out_half)
{
    extern __shared__ uint32_t gsm[];

    const __half* A1g = A1 + (long)blockIdx.z * sA1;
    const __half* B1g = B1 + (long)blockIdx.z * sB1;
    const __half* A2g = A2 + (long)blockIdx.z * sA2;
    const __half* B2g = B2 + (long)blockIdx.z * sB2;

    const int t = threadIdx.x;
    const int wid = t >> 5, l = t & 31;
    const int wm = wid >> 1, wn = wid & 1;
    const int mbase = wm * 64, nbase = wn * 64;
    const int qr = l >> 2, qc = l & 3;
    const int row0 = blockIdx.y * BM, col0 = blockIdx.x * BN;

    const uint32_t s0 = smem_u32(gsm);

    const int lr = t >> 2;
    const int lc4 = (t & 3) * 4;

    const uint32_t a_lm = s0 + (uint32_t)(((mbase + (l & 15)) * KSTRH + (l >> 4) * 4) * 4);
    const uint32_t b_lm = s0 + (uint32_t)((A_B32 +
        (nbase + (l & 7) + ((l >> 4) << 3)) * KSTRH + (((l >> 3) & 1) * 4)) * 4);

    float acc[4][8][4];
#pragma unroll
    for (int i = 0; i < 4; i++)
#pragma unroll
        for (int j = 0; j < 8; j++)
#pragma unroll
            for (int q = 0; q < 4; q++) acc[i][j][q] = 0.f;

    const int nc1 = K1 / BKH;
    const int nc = nc1 + K2 / BKH;

    auto prefetch = [&](int cc) {
        const int st = cc % 3;
        const __half* Ax; const __half* Bx; int k0, la, lb;
        if (cc < nc1) { Ax = A1g; Bx = B1g; k0 = cc * BKH; la = lda1; lb = ldb1; }
        else          { Ax = A2g; Bx = B2g; k0 = (cc - nc1) * BKH; la = lda2; lb = ldb2; }
        const uint32_t sAs = s0 + st * STG_B32 * 4;
        const uint32_t sBs = sAs + A_B32 * 4;
#pragma unroll
        for (int j = 0; j < 4; j++) {
            int m = lr + j * 64;
            cp16(sAs + (m * KSTRH + lc4) * 4, &Ax[(long)(row0 + m) * la + k0 + lc4 * 2]);
        }
#pragma unroll
        for (int j = 0; j < 2; j++) {
            int n = lr + j * 64;
            cp16(sBs + (n * KSTRH + lc4) * 4, &Bx[(long)(col0 + n) * lb + k0 + lc4 * 2]);
        }
        CP_COMMIT();
    };

    prefetch(0);
    if (nc > 1) prefetch(1);

    for (int c = 0; c < nc; c++) {
        if (c + 2 < nc) { prefetch(c + 2); CP_WAIT2(); }
        else if (c + 1 < nc) { CP_WAIT1(); }
        else { CP_WAIT0(); }
        __syncthreads();

        const uint32_t stoff = (uint32_t)((c % 3) * STG_B32 * 4);
#pragma unroll
        for (int kk = 0; kk < 2; kk++) {
            const uint32_t koff = stoff + kk * 8 * 4;
            uint32_t af[4][4], bf[4][4];
#pragma unroll
            for (int mt = 0; mt < 4; mt++)
                ldsm_x4(af[mt], a_lm + koff + mt * 16 * KSTRH * 4);
#pragma unroll
            for (int np = 0; np < 4; np++)
                ldsm_x4(bf[np], b_lm + koff + np * 16 * KSTRH * 4);
#pragma unroll
            for (int mt = 0; mt < 4; mt++) {
#pragma unroll
                for (int nt = 0; nt < 8; nt++)
                    mma_f16(acc[mt][nt], af[mt], &bf[nt >> 1][(nt & 1) * 2]);
            }
        }
        __syncthreads();
    }

    // ---- epilogue ----
#pragma unroll
    for (int mt = 0; mt < 4; mt++) {
        const int r = row0 + mbase + mt * 16 + qr;
#pragma unroll
        for (int nt = 0; nt < 8; nt++) {
            const int cc = col0 + nbase + nt * 8 + qc * 2;
            float b0 = 0.f, b1 = 0.f;
            if (bias) { b0 = bias[cc]; b1 = bias[cc + 1]; }
            float v0 = acc[mt][nt][0] * alpha + b0;
            float v1 = acc[mt][nt][1] * alpha + b1;
            float v2 = acc[mt][nt][2] * alpha + b0;
            float v3 = acc[mt][nt][3] * alpha + b1;
            if (relu) {
                v0 = fmaxf(v0, 0.f); v1 = fmaxf(v1, 0.f);
                v2 = fmaxf(v2, 0.f); v3 = fmaxf(v3, 0.f);
            }
            if (out_half) {
                __half* C = (__half*)Cout + blockIdx.z * sC;
                *(__half2*)&C[(long)r * N + cc] = __floats2half2_rn(v0, v1);
                *(__half2*)&C[(long)(r + 8) * N + cc] = __floats2half2_rn(v2, v3);
            } else {
                float* C = (float*)Cout + blockIdx.z * sC;
                float2 p0 = {v0, v1}, p1 = {v2, v3};
                *(float2*)&C[(long)r * N + cc] = p0;
                *(float2*)&C[(long)(r + 8) * N + cc] = p1;
            }
        }
    }
}

// ======================= half transpose from proj (V cols) =======================
__global__ __launch_bounds__(256) void transpose_proj_kernel(const __half* __restrict__ proj,
                                                             __half* __restrict__ Vt)
{
    __shared__ __half tile[32][33];
    const __half* Pb = proj + (long)blockIdx.z * SS * PROJN + (3 * DD + 2 * RR);
    __half* Vtb = Vt + (long)blockIdx.z * DD * SS;
    const int s0 = blockIdx.x * 32, d0 = blockIdx.y * 32;
    const int tx = threadIdx.x & 31, ty0 = threadIdx.x >> 5;
#pragma unroll
    for (int i = 0; i < 4; i++) {
        int ty = ty0 + i * 8;
        tile[ty][tx] = Pb[(long)(s0 + ty) * PROJN + d0 + tx];
    }
    __syncthreads();
#pragma unroll
    for (int i = 0; i < 4; i++) {
        int ty = ty0 + i * 8;
        Vtb[(long)(d0 + ty) * SS + s0 + tx] = tile[tx][ty];
    }
}

// ======================= fp16 flash attention (ldmatrix + register P) =======================
// grid (SS/128, HH, BB), block 256. Key tile 64. Stride 72 halves (conflict-free ldsm).
#define VSTRH 72
#define VSTRB 144

__global__ __launch_bounds__(256) void flash_attn_kernel(const __half* __restrict__ proj,
                                                         const float* __restrict__ sigbuf,
                                                         __half* __restrict__ ctx)
{
    __shared__ __half sm[128 * VSTRH];    // Q stage (128x72) then K|V tiles (64x72 each)
    __half* ks = sm;
    __half* vs = sm + 64 * VSTRH;

    const int t = threadIdx.x, w = t >> 5, l = t & 31;
    const int qr = l >> 2, qc = l & 3;
    const int q0 = blockIdx.x * 128, h = blockIdx.y, b = blockIdx.z;
    const int wr = w * 16;

    const __half* Qg = proj + (long)(b * SS + q0) * PROJN + h * DH;
    const __half* Kg = proj + (long)(b * SS) * PROJN + DD + h * DH;
    const __half* Vg = proj + (long)(b * SS) * PROJN + 2 * DD + h * DH;

    const uint32_t smb = smem_u32(sm);
    const uint32_t ksb = smb;
    const uint32_t vsb = smem_u32(vs);

    // ---- stage Q (row-major, stride 72), load A fragments via ldmatrix ----
#pragma unroll
    for (int i = 0; i < 4; i++) {
        int idx = t + i * 256;
        int r = idx >> 3, c16 = idx & 7;
        *(float4*)&sm[r * VSTRH + c16 * 8] = *(const float4*)(Qg + (long)r * PROJN + c16 * 8);
    }
    __syncthreads();
    uint32_t qa[4][4];
    {
        const uint32_t q_lm = smb + (uint32_t)((wr + (l & 15)) * VSTRB + (l >> 4) * 16);
#pragma unroll
        for (int k = 0; k < 4; k++)
            ldsm_x4(qa[k], q_lm + k * 32);
    }
    __syncthreads();

    // ldmatrix lane bases for K (non-trans B frags) and V (trans B frags)
    const uint32_t kb_lm = ksb + (uint32_t)(((l & 7) + ((l >> 4) << 3)) * VSTRB + ((l >> 3) & 1) * 16);
    const uint32_t vb_lm = vsb + (uint32_t)(((l & 7) + ((l >> 3) & 1) * 8) * VSTRB + ((l >> 4) & 1) * 16);

    float m0 = -1e30f, m1 = -1e30f, l0 = 0.f, l1 = 0.f;
    float o[8][4];
#pragma unroll
    for (int n = 0; n < 8; n++)
#pragma unroll
        for (int i = 0; i < 4; i++) o[n][i] = 0.f;

    for (int kt = 0; kt < SS; kt += 64) {
        // ---- load K and V tiles row-major (coalesced float4) ----
#pragma unroll
        for (int i = 0; i < 2; i++) {
            int idx = t + i * 256;
            int r = idx >> 3, c16 = idx & 7;
            *(float4*)&ks[r * VSTRH + c16 * 8] = *(const float4*)(Kg + (long)(kt + r) * PROJN + c16 * 8);
            *(float4*)&vs[r * VSTRH + c16 * 8] = *(const float4*)(Vg + (long)(kt + r) * PROJN + c16 * 8);
        }
        __syncthreads();

        // ---- S = Q @ K^T ----
        float sa[8][4];
#pragma unroll
        for (int n = 0; n < 8; n++)
#pragma unroll
            for (int i = 0; i < 4; i++) sa[n][i] = 0.f;
#pragma unroll
        for (int k = 0; k < 4; k++) {
            uint32_t kb[4][4];
#pragma unroll
            for (int ng = 0; ng < 4; ng++)
                ldsm_x4(kb[ng], kb_lm + ng * 16 * VSTRB + k * 32);
#pragma unroll
            for (int n = 0; n < 8; n++)
                mma_f16(sa[n], qa[k], &kb[n >> 1][(n & 1) * 2]);
        }

        // ---- online softmax (probabilities stay in sa) ----
        float rm0 = -1e30f, rm1 = -1e30f;
#pragma unroll
        for (int n = 0; n < 8; n++) {
            sa[n][0] *= 0.125f; sa[n][1] *= 0.125f;
            sa[n][2] *= 0.125f; sa[n][3] *= 0.125f;
            rm0 = fmaxf(rm0, fmaxf(sa[n][0], sa[n][1]));
            rm1 = fmaxf(rm1, fmaxf(sa[n][2], sa[n][3]));
        }
        rm0 = fmaxf(rm0, __shfl_xor_sync(0xffffffffu, rm0, 1));
        rm0 = fmaxf(rm0, __shfl_xor_sync(0xffffffffu, rm0, 2));
        rm1 = fmaxf(rm1, __shfl_xor_sync(0xffffffffu, rm1, 1));
        rm1 = fmaxf(rm1, __shfl_xor_sync(0xffffffffu, rm1, 2));

        const float nm0 = fmaxf(m0, rm0), nm1 = fmaxf(m1, rm1);
        const float c0 = __expf(m0 - nm0), c1 = __expf(m1 - nm1);
        float rs0 = 0.f, rs1 = 0.f;
#pragma unroll
        for (int n = 0; n < 8; n++) {
            sa[n][0] = __expf(sa[n][0] - nm0);
            sa[n][1] = __expf(sa[n][1] - nm0);
            sa[n][2] = __expf(sa[n][2] - nm1);
            sa[n][3] = __expf(sa[n][3] - nm1);
            rs0 += sa[n][0] + sa[n][1];
            rs1 += sa[n][2] + sa[n][3];
            o[n][0] *= c0; o[n][1] *= c0; o[n][2] *= c1; o[n][3] *= c1;
        }
        rs0 += __shfl_xor_sync(0xffffffffu, rs0, 1);
        rs0 += __shfl_xor_sync(0xffffffffu, rs0, 2);
        rs1 += __shfl_xor_sync(0xffffffffu, rs1, 1);
        rs1 += __shfl_xor_sync(0xffffffffu, rs1, 2);
        l0 = l0 * c0 + rs0; l1 = l1 * c1 + rs1;
        m0 = nm0; m1 = nm1;

        // ---- O += P @ V  (P fragments built in registers; V via ldmatrix.trans) ----
#pragma unroll
        for (int k = 0; k < 4; k++) {
            uint32_t pa[4];
            pa[0] = h2u(sa[2 * k][0], sa[2 * k][1]);
            pa[1] = h2u(sa[2 * k][2], sa[2 * k][3]);
            pa[2] = h2u(sa[2 * k + 1][0], sa[2 * k + 1][1]);
            pa[3] = h2u(sa[2 * k + 1][2], sa[2 * k + 1][3]);
#pragma unroll
            for (int dg = 0; dg < 4; dg++) {
                uint32_t vb[4];
                ldsm_x4_t(vb, vb_lm + k * 16 * VSTRB + dg * 32);
                mma_f16(o[dg * 2 + 0], pa, &vb[0]);
                mma_f16(o[dg * 2 + 1], pa, &vb[2]);
            }
        }
        __syncthreads();
    }

    const float sig = sigbuf[0];
    const float i0 = sig / l0, i1 = sig / l1;
    __half* Og = ctx + (long)(b * SS + q0 + wr) * DD + h * DH;
#pragma unroll
    for (int n = 0; n < 8; n++) {
        *(__half2*)&Og[(long)qr * DD + n * 8 + 2 * qc] = __floats2half2_rn(o[n][0] * i0, o[n][1] * i0);
        *(__half2*)&Og[(long)(qr + 8) * DD + n * 8 + 2 * qc] = __floats2half2_rn(o[n][2] * i1, o[n][3] * i1);
    }
}

// ======================= radix top-k + masked softmax -> half P =======================
__global__ __launch_bounds__(256) void topk_softmax_kernel(const float* __restrict__ P,
                                                           const float* __restrict__ sigbuf,
                                                           __half* __restrict__ Ph)
{
    const long base = (long)blockIdx.x * SS;
    __shared__ float vals[SS];
    __shared__ unsigned keys[SS];
    __shared__ unsigned hist[256];
    __shared__ float redA[8], redB[8];
    __shared__ unsigned s_prefix;
    __shared__ int s_need;

    const int t = threadIdx.x;
    const int w = t >> 5, lane = t & 31;

    float lmax = -1e30f;
#pragma unroll
    for (int i = 0; i < 4; i++) {
        float v = P[base + t + i * 256];
        vals[t + i * 256] = v;
        unsigned u = __float_as_uint(v);
        u ^= (u >> 31) ? 0xFFFFFFFFu : 0x80000000u;
        keys[t + i * 256] = u;
        lmax = fmaxf(lmax, v);
    }
#pragma unroll
    for (int o = 16; o > 0; o >>= 1)
        lmax = fmaxf(lmax, __shfl_xor_sync(0xffffffffu, lmax, o));
    if (lane == 0) redA[w] = lmax;
    __syncthreads();
    float mx = redA[0];
#pragma unroll
    for (int i = 1; i < 8; i++) mx = fmaxf(mx, redA[i]);

    unsigned prefix = 0;
    int need = KSEL;
#pragma unroll
    for (int pass = 0; pass < 4; pass++) {
        const int shift = 24 - 8 * pass;
        const unsigned hmask = pass ? (0xFFFFFFFFu << (shift + 8)) : 0u;
        hist[t] = 0;
        __syncthreads();
#pragma unroll
        for (int i = 0; i < 4; i++) {
            unsigned u = keys[t + i * 256];
            if ((u & hmask) == prefix)
                atomicAdd(&hist[(u >> shift) & 0xFFu], 1u);
        }
        __syncthreads();
        if (t == 0) {
            int cum = 0, bsel = 0;
            for (int bbin = 255; bbin >= 0; bbin--) {
                int hh = (int)hist[bbin];
                if (cum + hh >= need) { bsel = bbin; break; }
                cum += hh;
            }
            s_prefix = prefix | ((unsigned)bsel << shift);
            s_need = need - cum;
        }
        __syncthreads();
        prefix = s_prefix;
        need = s_need;
        __syncthreads();
    }
    const unsigned thr = prefix;

    float e[4];
    float sk = 0.f, sf = 0.f;
#pragma unroll
    for (int i = 0; i < 4; i++) {
        float v = vals[t + i * 256];
        float ef = __expf(v - mx);
        bool kp = keys[t + i * 256] >= thr;
        e[i] = kp ? ef : 0.f;
        sk += e[i];
        sf += ef;
    }
#pragma unroll
    for (int o = 16; o > 0; o >>= 1) {
        sk += __shfl_xor_sync(0xffffffffu, sk, o);
        sf += __shfl_xor_sync(0xffffffffu, sf, o);
    }
    if (lane == 0) { redA[w] = sk; redB[w] = sf; }
    __syncthreads();
    float tk = 0.f, tf = 0.f;
#pragma unroll
    for (int i = 0; i < 8; i++) { tk += redA[i]; tf += redB[i]; }
    const float inv = (1.f - sigbuf[0]) / (tk + 1e-9f * tf);
#pragma unroll
    for (int i = 0; i < 4; i++)
        Ph[base + t + i * 256] = __float2half(e[i] * inv);
}

// ======================= residual + LN1 (3 inputs) =======================
__global__ __launch_bounds__(256) void fuse_ln1_kernel(
    const float* __restrict__ src, const float* __restrict__ dense,
    const float* __restrict__ sparse,
    const float* __restrict__ g, const float* __restrict__ bb,
    float* __restrict__ x, __half* __restrict__ xh)
{
    const long row = (long)blockIdx.x * DD;
    __shared__ float buf[DD];
    __shared__ float r1[8], r2[8];

    float s1 = 0.f, s2 = 0.f;
    for (int d = threadIdx.x; d < DD; d += 256) {
        float v = src[row + d] + dense[row + d] + sparse[row + d];
        buf[d] = v; s1 += v; s2 += v * v;
    }
#pragma unroll
    for (int o = 16; o > 0; o >>= 1) {
        s1 += __shfl_xor_sync(0xffffffffu, s1, o);
        s2 += __shfl_xor_sync(0xffffffffu, s2, o);
    }
    const int w = threadIdx.x >> 5, lane = threadIdx.x & 31;
    if (lane == 0) { r1[w] = s1; r2[w] = s2; }
    __syncthreads();
    if (threadIdx.x == 0) {
        float a = 0.f, c = 0.f;
        for (int i = 0; i < 8; i++) { a += r1[i]; c += r2[i]; }
        r1[0] = a; r2[0] = c;
    }
    __syncthreads();
    const float mean = r1[0] * (1.f / DD);
    const float var = r2[0] * (1.f / DD) - mean * mean;
    const float rstd = rsqrtf(var + 1e-5f);
    for (int d = threadIdx.x; d < DD; d += 256) {
        float v = (buf[d] - mean) * rstd * g[d] + bb[d];
        x[row + d] = v;
        xh[row + d] = __float2half(v);
    }
}

// ======================= residual + LN2 -> out =======================
__global__ __launch_bounds__(256) void ln2_kernel(
    const float* __restrict__ x, const float* __restrict__ ff,
    const float* __restrict__ g, const float* __restrict__ bb,
    float* __restrict__ out)
{
    const long row = (long)blockIdx.x * DD;
    __shared__ float buf[DD];
    __shared__ float r1[8], r2[8];

    float s1 = 0.f, s2 = 0.f;
    for (int d = threadIdx.x; d < DD; d += 256) {
        float v = x[row + d] + ff[row + d];
        buf[d] = v; s1 += v; s2 += v * v;
    }
#pragma unroll
    for (int o = 16; o > 0; o >>= 1) {
        s1 += __shfl_xor_sync(0xffffffffu, s1, o);
        s2 += __shfl_xor_sync(0xffffffffu, s2, o);
    }
    const int w = threadIdx.x >> 5, lane = threadIdx.x & 31;
    if (lane == 0) { r1[w] = s1; r2[w] = s2; }
    __syncthreads();
    if (threadIdx.x == 0) {
        float a = 0.f, c = 0.f;
        for (int i = 0; i < 8; i++) { a += r1[i]; c += r2[i]; }
        r1[0] = a; r2[0] = c;
    }
    __syncthreads();
    const float mean = r1[0] * (1.f / DD);
    const float var = r2[0] * (1.f / DD) - mean * mean;
    const float rstd = rsqrtf(var + 1e-5f);
    for (int d = threadIdx.x; d < DD; d += 256)
        out[row + d] = (buf[d] - mean) * rstd * g[d] + bb[d];
}

// ======================= launch =======================
extern "C" void kernel_launch(void* const* d_in, const int* in_sizes, int n_in,
                              void* d_out, int out_size)
{
    (void)in_sizes; (void)n_in; (void)out_size;
    const float* src    = (const float*)d_in[0];
    const float* in_w   = (const float*)d_in[1];
    const float* in_b   = (const float*)d_in[2];
    const float* outp_w = (const float*)d_in[3];
    const float* outp_b = (const float*)d_in[4];
    const float* Qp_w   = (const float*)d_in[5];
    const float* Qp_b   = (const float*)d_in[6];
    const float* Kp_w   = (const float*)d_in[7];
    const float* Kp_b   = (const float*)d_in[8];
    const float* Vp_w   = (const float*)d_in[9];
    const float* Vp_b   = (const float*)d_in[10];
    const float* lam    = (const float*)d_in[11];
    const float* ff1_w  = (const float*)d_in[12];
    const float* ff1_b  = (const float*)d_in[13];
    const float* ff2_w  = (const float*)d_in[14];
    const float* ff2_b  = (const float*)d_in[15];
    const float* ln1_g  = (const float*)d_in[16];
    const float* ln1_b  = (const float*)d_in[17];
    const float* ln2_g  = (const float*)d_in[18];
    const float* ln2_b  = (const float*)d_in[19];
    float* out = (float*)d_out;

    __half *hw_pack, *hw_out, *hw_f1, *hw_f2;
    __half *src_h, *proj_h, *ctx_h, *Vt_h, *Ph, *x_h, *h1_h;
    float *bias_pack, *bias_dense, *sigbuf, *P, *dense, *sparse, *x, *ff;
    cudaGetSymbolAddress((void**)&hw_pack,    g_hw_pack);
    cudaGetSymbolAddress((void**)&hw_out,     g_hw_out);
    cudaGetSymbolAddress((void**)&hw_f1,      g_hw_f1);
    cudaGetSymbolAddress((void**)&hw_f2,      g_hw_f2);
    cudaGetSymbolAddress((void**)&bias_pack,  g_bias_pack);
    cudaGetSymbolAddress((void**)&bias_dense, g_bias_dense);
    cudaGetSymbolAddress((void**)&sigbuf,     g_sig);
    cudaGetSymbolAddress((void**)&src_h,      g_src_h);
    cudaGetSymbolAddress((void**)&proj_h,     g_proj_h);
    cudaGetSymbolAddress((void**)&ctx_h,      g_ctx_h);
    cudaGetSymbolAddress((void**)&Vt_h,       g_Vt_h);
    cudaGetSymbolAddress((void**)&Ph,         g_Ph);
    cudaGetSymbolAddress((void**)&x_h,        g_x_h);
    cudaGetSymbolAddress((void**)&h1_h,       g_h1_h);
    cudaGetSymbolAddress((void**)&P,          g_P);
    cudaGetSymbolAddress((void**)&dense,      g_dense);
    cudaGetSymbolAddress((void**)&sparse,     g_sparse);
    cudaGetSymbolAddress((void**)&x,          g_x);
    cudaGetSymbolAddress((void**)&ff,         g_ff);

    cudaFuncSetAttribute(hgemm_nt, cudaFuncAttributeMaxDynamicSharedMemorySize, GEMM_SMEM);

    static cudaStream_t sA = nullptr, sB = nullptr;
    static cudaEvent_t evC = nullptr, evA = nullptr, evB = nullptr;
    if (!sA) {
        cudaStreamCreateWithFlags(&sA, cudaStreamNonBlocking);
        cudaStreamCreateWithFlags(&sB, cudaStreamNonBlocking);
        cudaEventCreateWithFlags(&evC, cudaEventDisableTiming);
        cudaEventCreateWithFlags(&evA, cudaEventDisableTiming);
        cudaEventCreateWithFlags(&evB, cudaEventDisableTiming);
    }

    // sA: non-critical weight conversion, overlaps the critical path
    convert_rest<<<9216, 256, 0, sA>>>(outp_w, ff1_w, ff2_w, hw_out, hw_f1, hw_f2);

    // main: critical conversion then proj GEMM
    convert_crit<<<8321, 256>>>(in_w, Qp_w, Kp_w, Vp_w, src,
                                in_b, Qp_b, Kp_b, Vp_b, outp_b, lam,
                                hw_pack, src_h, bias_pack, bias_dense, sigbuf);
    hgemm_nt<<<dim3(PROJN / BN, NTOK / BM), 256, GEMM_SMEM>>>(
        src_h, hw_pack, DD, DD, DD, 0, 0,
        src_h, hw_pack, 0, DD, DD, 0, 0,
        bias_pack, proj_h, PROJN, 0, 1.f, 0, 1);
    cudaEventRecord(evC, 0);
    cudaStreamWaitEvent(sA, evC, 0);
    cudaStreamWaitEvent(sB, evC, 0);

    // ---- branch A: flash attention -> dense = sig*(ctx@out^T) + sig*b ----
    flash_attn_kernel<<<dim3(SS / 128, HH, BB), 256, 0, sA>>>(proj_h, sigbuf, ctx_h);
    hgemm_nt<<<dim3(DD / BN, NTOK / BM), 256, GEMM_SMEM, sA>>>(
        ctx_h, hw_out, DD, DD, DD, 0, 0,
        ctx_h, hw_out, 0, DD, DD, 0, 0,
        bias_dense, dense, DD, 0, 1.f, 0, 0);
    cudaEventRecord(evA, sA);

    // ---- branch B: scores -> topk -> transpose -> sparse = (1-sig)*(P@V) ----
    hgemm_nt<<<dim3(SS / BN, SS / BM, BB), 256, GEMM_SMEM, sB>>>(
        proj_h + 3 * DD, proj_h + 3 * DD + RR, RR, PROJN, PROJN,
        (long)SS * PROJN, (long)SS * PROJN,
        proj_h, proj_h, 0, PROJN, PROJN, 0, 0,
        nullptr, P, SS, (long)SS * SS, 0.125f, 0, 0);
    topk_softmax_kernel<<<NTOK, 256, 0, sB>>>(P, sigbuf, Ph);
    transpose_proj_kernel<<<dim3(SS / 32, DD / 32, BB), 256, 0, sB>>>(proj_h, Vt_h);
    hgemm_nt<<<dim3(DD / BN, SS / BM, BB), 256, GEMM_SMEM, sB>>>(
        Ph, Vt_h, SS, SS, SS, (long)SS * SS, (long)DD * SS,
        Ph, Vt_h, 0, SS, SS, 0, 0,
        nullptr, sparse, DD, (long)SS * DD, 1.f, 0, 0);
    cudaEventRecord(evB, sB);

    // ---- join ----
    cudaStreamWaitEvent(0, evA, 0);
    cudaStreamWaitEvent(0, evB, 0);

    // x = LN1(src + dense + sparse) -> f32 + half
    fuse_ln1_kernel<<<NTOK, 256>>>(src, dense, sparse, ln1_g, ln1_b, x, x_h);
    // h1 = relu(x @ ff1^T + b) -> half
    hgemm_nt<<<dim3(DFFN / BN, NTOK / BM), 256, GEMM_SMEM>>>(
        x_h, hw_f1, DD, DD, DD, 0, 0,
        x_h, hw_f1, 0, DD, DD, 0, 0,
        ff1_b, h1_h, DFFN, 0, 1.f, 1, 1);
    // ff = h1 @ ff2^T + b -> f32
    hgemm_nt<<<dim3(DD / BN, NTOK / BM), 256, GEMM_SMEM>>>(
        h1_h, hw_f2, DFFN, DFFN, DFFN, 0, 0,
        h1_h, hw_f2, 0, DFFN, DFFN, 0, 0,
        ff2_b, ff, DD, 0, 1.f, 0, 0);
    // out = LN2(x + ff)
    ln2_kernel<<<NTOK, 256>>>(x, ff, ln2_g, ln2_b, out);
}

// round 14
// speedup vs baseline: 1.1487x; 1.0071x over previous
#include <cuda_runtime.h>
#include <cuda_fp16.h>
#include <cstdint>
#include <math.h>

// Problem dims
#define BB   4
#define SS   1024
#define DD   1024
#define HH   16
#define DH   64
#define RR   64
#define DFFN 4096
#define NTOK (BB*SS)       // 4096
#define KSEL 204           // int(1024*0.2)
#define PROJN 4224         // 3*DD + 2*RR + DD  (qkv | Q | K | V)

// ---------------- scratch (device globals) ----------------
__device__ __half g_hw_pack[(long)PROJN * DD];
__device__ float  g_bias_pack[PROJN];
__device__ __half g_hw_out[(long)DD * DD];
__device__ float  g_bias_dense[DD];
__device__ float  g_sig[1];
__device__ __half g_hw_f1[(long)DFFN * DD];
__device__ __half g_hw_f2[(long)DD * DFFN];
__device__ __half g_src_h[(long)NTOK * DD];
__device__ __half g_proj_h[(long)NTOK * PROJN];
__device__ __half g_ctx_h[(long)NTOK * DD];
__device__ __half g_Vt_h[(long)NTOK * DD];
__device__ __half g_Ph[(long)BB * SS * SS];
__device__ float g_P[(long)BB * SS * SS];
__device__ float g_dense[(long)NTOK * DD];
__device__ float g_sparse[(long)NTOK * DD];
__device__ float g_x[(long)NTOK * DD];
__device__ __half g_x_h[(long)NTOK * DD];
__device__ __half g_h1_h[(long)NTOK * DFFN];
__device__ float g_ff[(long)NTOK * DD];

// ======================= helpers =======================
__device__ __forceinline__ uint32_t smem_u32(const void* p) {
    uint32_t a;
    asm("{ .reg .u64 t; cvta.to.shared.u64 t, %1; cvt.u32.u64 %0, t; }" : "=r"(a) : "l"(p));
    return a;
}
__device__ __forceinline__ void cp16(uint32_t saddr, const void* g) {
    asm volatile("cp.async.ca.shared.global [%0], [%1], 16;"
                 :: "r"(saddr), "l"(g) : "memory");
}
#define CP_COMMIT() asm volatile("cp.async.commit_group;" ::: "memory")
#define CP_WAIT2()  asm volatile("cp.async.wait_group 2;" ::: "memory")
#define CP_WAIT1()  asm volatile("cp.async.wait_group 1;" ::: "memory")
#define CP_WAIT0()  asm volatile("cp.async.wait_group 0;" ::: "memory")

__device__ __forceinline__ void mma_f16(float* c, const uint32_t* a, const uint32_t* b) {
    asm volatile(
        "mma.sync.aligned.m16n8k16.row.col.f32.f16.f16.f32 "
        "{%0,%1,%2,%3}, {%4,%5,%6,%7}, {%8,%9}, {%0,%1,%2,%3};"
        : "+f"(c[0]), "+f"(c[1]), "+f"(c[2]), "+f"(c[3])
        : "r"(a[0]), "r"(a[1]), "r"(a[2]), "r"(a[3]), "r"(b[0]), "r"(b[1]));
}
__device__ __forceinline__ void ldsm_x4(uint32_t* r, uint32_t saddr) {
    asm volatile("ldmatrix.sync.aligned.m8n8.x4.shared.b16 {%0,%1,%2,%3}, [%4];"
                 : "=r"(r[0]), "=r"(r[1]), "=r"(r[2]), "=r"(r[3]) : "r"(saddr));
}
__device__ __forceinline__ void ldsm_x4_t(uint32_t* r, uint32_t saddr) {
    asm volatile("ldmatrix.sync.aligned.m8n8.x4.trans.shared.b16 {%0,%1,%2,%3}, [%4];"
                 : "=r"(r[0]), "=r"(r[1]), "=r"(r[2]), "=r"(r[3]) : "r"(saddr));
}
__device__ __forceinline__ uint32_t h2u(float x, float y) {
    __half2 h = __floats2half2_rn(x, y);
    return *(uint32_t*)&h;
}

// ======================= critical converter =======================
__global__ __launch_bounds__(256) void convert_crit(
    const float* in_w, const float* Qp_w, const float* Kp_w, const float* Vp_w,
    const float* src,
    const float* in_b, const float* Qp_b, const float* Kp_b, const float* Vp_b,
    const float* outp_b, const float* lam,
    __half* hw_pack, __half* src_h,
    float* bias_pack, float* bias_dense, float* sigbuf)
{
    const int bid = blockIdx.x, t = threadIdx.x;
    if (bid == 8320) {
        const float sig = 1.f / (1.f + __expf(-lam[0]));
        if (t == 0) sigbuf[0] = sig;
        for (int i = t; i < PROJN; i += 256) {
            float v;
            if      (i < 3 * DD)          v = in_b[i];
            else if (i < 3 * DD + RR)     v = Qp_b[i - 3 * DD];
            else if (i < 3 * DD + 2 * RR) v = Kp_b[i - 3 * DD - RR];
            else                          v = Vp_b[i - 3 * DD - 2 * RR];
            bias_pack[i] = v;
        }
        for (int i = t; i < DD; i += 256)
            bias_dense[i] = sig * outp_b[i];
        return;
    }
    const float* in; __half* out;
    if (bid < PROJN) {
        const int r = bid;
        if      (r < 3 * DD)          in = in_w + (long)r * DD;
        else if (r < 3 * DD + RR)     in = Qp_w + (long)(r - 3 * DD) * DD;
        else if (r < 3 * DD + 2 * RR) in = Kp_w + (long)(r - 3 * DD - RR) * DD;
        else                          in = Vp_w + (long)(r - 3 * DD - 2 * RR) * DD;
        out = hw_pack + (long)bid * DD;
    } else {
        in = src + (long)(bid - PROJN) * 1024;
        out = src_h + (long)(bid - PROJN) * 1024;
    }
    long i = t * 4;
    float4 v = *(const float4*)(in + i);
    *(__half2*)(out + i) = __floats2half2_rn(v.x, v.y);
    *(__half2*)(out + i + 2) = __floats2half2_rn(v.z, v.w);
}

// ======================= non-critical converter =======================
__global__ __launch_bounds__(256) void convert_rest(
    const float* outp_w, const float* ff1_w, const float* ff2_w,
    __half* hw_out, __half* hw_f1, __half* hw_f2)
{
    const int bid = blockIdx.x, t = threadIdx.x;
    const float* in; __half* out; long off;
    if      (bid < 1024) { in = outp_w; out = hw_out; off = (long)bid * 1024; }
    else if (bid < 5120) { in = ff1_w;  out = hw_f1;  off = (long)(bid - 1024) * 1024; }
    else                 { in = ff2_w;  out = hw_f2;  off = (long)(bid - 5120) * 1024; }
    long i = off + t * 4;
    float4 v = *(const float4*)(in + i);
    *(__half2*)(out + i) = __floats2half2_rn(v.x, v.y);
    *(__half2*)(out + i + 2) = __floats2half2_rn(v.z, v.w);
}

// ======================= fp16 warp-MMA GEMM, two K-segments =======================
#define BM 256
#define BN 128
#define BKH 32
#define KSTRH 20
#define A_B32 (BM * KSTRH)
#define STG_B32 (A_B32 + BN * KSTRH)
#define GEMM_SMEM (3 * STG_B32 * 4)

__global__ __launch_bounds__(256) void hgemm_nt(
    const __half* __restrict__ A1, const __half* __restrict__ B1,
    int K1, int lda1, int ldb1, long sA1, long sB1,
    const __half* __restrict__ A2, const __half* __restrict__ B2,
    int K2, int lda2, int ldb2, long sA2, long sB2,
    const float* __restrict__ bias, void* __restrict__ Cout,
    int N, long sC, float alpha, int relu, int out_half)
{
    extern __shared__ uint32_t gsm[];

    const __half* A1g = A1 + (long)blockIdx.z * sA1;
    const __half* B1g = B1 + (long)blockIdx.z * sB1;
    const __half* A2g = A2 + (long)blockIdx.z * sA2;
    const __half* B2g = B2 + (long)blockIdx.z * sB2;

    const int t = threadIdx.x;
    const int wid = t >> 5, l = t & 31;
    const int wm = wid >> 1, wn = wid & 1;
    const int mbase = wm * 64, nbase = wn * 64;
    const int qr = l >> 2, qc = l & 3;
    const int row0 = blockIdx.y * BM, col0 = blockIdx.x * BN;

    const uint32_t s0 = smem_u32(gsm);

    const int lr = t >> 2;
    const int lc4 = (t & 3) * 4;

    const uint32_t a_lm = s0 + (uint32_t)(((mbase + (l & 15)) * KSTRH + (l >> 4) * 4) * 4);
    const uint32_t b_lm = s0 + (uint32_t)((A_B32 +
        (nbase + (l & 7) + ((l >> 4) << 3)) * KSTRH + (((l >> 3) & 1) * 4)) * 4);

    float acc[4][8][4];
#pragma unroll
    for (int i = 0; i < 4; i++)
#pragma unroll
        for (int j = 0; j < 8; j++)
#pragma unroll
            for (int q = 0; q < 4; q++) acc[i][j][q] = 0.f;

    const int nc1 = K1 / BKH;
    const int nc = nc1 + K2 / BKH;

    auto prefetch = [&](int cc) {
        const int st = cc % 3;
        const __half* Ax; const __half* Bx; int k0, la, lb;
        if (cc < nc1) { Ax = A1g; Bx = B1g; k0 = cc * BKH; la = lda1; lb = ldb1; }
        else          { Ax = A2g; Bx = B2g; k0 = (cc - nc1) * BKH; la = lda2; lb = ldb2; }
        const uint32_t sAs = s0 + st * STG_B32 * 4;
        const uint32_t sBs = sAs + A_B32 * 4;
#pragma unroll
        for (int j = 0; j < 4; j++) {
            int m = lr + j * 64;
            cp16(sAs + (m * KSTRH + lc4) * 4, &Ax[(long)(row0 + m) * la + k0 + lc4 * 2]);
        }
#pragma unroll
        for (int j = 0; j < 2; j++) {
            int n = lr + j * 64;
            cp16(sBs + (n * KSTRH + lc4) * 4, &Bx[(long)(col0 + n) * lb + k0 + lc4 * 2]);
        }
        CP_COMMIT();
    };

    prefetch(0);
    if (nc > 1) prefetch(1);

    for (int c = 0; c < nc; c++) {
        if (c + 2 < nc) { prefetch(c + 2); CP_WAIT2(); }
        else if (c + 1 < nc) { CP_WAIT1(); }
        else { CP_WAIT0(); }
        __syncthreads();

        const uint32_t stoff = (uint32_t)((c % 3) * STG_B32 * 4);
#pragma unroll
        for (int kk = 0; kk < 2; kk++) {
            const uint32_t koff = stoff + kk * 8 * 4;
            uint32_t af[4][4], bf[4][4];
#pragma unroll
            for (int mt = 0; mt < 4; mt++)
                ldsm_x4(af[mt], a_lm + koff + mt * 16 * KSTRH * 4);
#pragma unroll
            for (int np = 0; np < 4; np++)
                ldsm_x4(bf[np], b_lm + koff + np * 16 * KSTRH * 4);
#pragma unroll
            for (int mt = 0; mt < 4; mt++) {
#pragma unroll
                for (int nt = 0; nt < 8; nt++)
                    mma_f16(acc[mt][nt], af[mt], &bf[nt >> 1][(nt & 1) * 2]);
            }
        }
        __syncthreads();
    }

    // ---- epilogue ----
#pragma unroll
    for (int mt = 0; mt < 4; mt++) {
        const int r = row0 + mbase + mt * 16 + qr;
#pragma unroll
        for (int nt = 0; nt < 8; nt++) {
            const int cc = col0 + nbase + nt * 8 + qc * 2;
            float b0 = 0.f, b1 = 0.f;
            if (bias) { b0 = bias[cc]; b1 = bias[cc + 1]; }
            float v0 = acc[mt][nt][0] * alpha + b0;
            float v1 = acc[mt][nt][1] * alpha + b1;
            float v2 = acc[mt][nt][2] * alpha + b0;
            float v3 = acc[mt][nt][3] * alpha + b1;
            if (relu) {
                v0 = fmaxf(v0, 0.f); v1 = fmaxf(v1, 0.f);
                v2 = fmaxf(v2, 0.f); v3 = fmaxf(v3, 0.f);
            }
            if (out_half) {
                __half* C = (__half*)Cout + blockIdx.z * sC;
                *(__half2*)&C[(long)r * N + cc] = __floats2half2_rn(v0, v1);
                *(__half2*)&C[(long)(r + 8) * N + cc] = __floats2half2_rn(v2, v3);
            } else {
                float* C = (float*)Cout + blockIdx.z * sC;
                float2 p0 = {v0, v1}, p1 = {v2, v3};
                *(float2*)&C[(long)r * N + cc] = p0;
                *(float2*)&C[(long)(r + 8) * N + cc] = p1;
            }
        }
    }
}

// ======================= half transpose from proj (V cols) =======================
__global__ __launch_bounds__(256) void transpose_proj_kernel(const __half* __restrict__ proj,
                                                             __half* __restrict__ Vt)
{
    __shared__ __half tile[32][33];
    const __half* Pb = proj + (long)blockIdx.z * SS * PROJN + (3 * DD + 2 * RR);
    __half* Vtb = Vt + (long)blockIdx.z * DD * SS;
    const int s0 = blockIdx.x * 32, d0 = blockIdx.y * 32;
    const int tx = threadIdx.x & 31, ty0 = threadIdx.x >> 5;
#pragma unroll
    for (int i = 0; i < 4; i++) {
        int ty = ty0 + i * 8;
        tile[ty][tx] = Pb[(long)(s0 + ty) * PROJN + d0 + tx];
    }
    __syncthreads();
#pragma unroll
    for (int i = 0; i < 4; i++) {
        int ty = ty0 + i * 8;
        Vtb[(long)(d0 + ty) * SS + s0 + tx] = tile[tx][ty];
    }
}

// ======================= fp16 flash attention (ldmatrix + register P + cp.async db) =======================
#define VSTRH 72
#define VSTRB 144
#define FA_TILE (64 * VSTRH)          // halves per K or V tile
#define FA_BUF  (2 * FA_TILE)         // K+V per buffer
#define FA_NT   (SS / 64)             // 16 tiles

__global__ __launch_bounds__(256) void flash_attn_kernel(const __half* __restrict__ proj,
                                                         const float* __restrict__ sigbuf,
                                                         __half* __restrict__ ctx)
{
    __shared__ __half sm[2 * FA_BUF];   // 36,864 B; Q staging reuses the front

    const int t = threadIdx.x, w = t >> 5, l = t & 31;
    const int qr = l >> 2, qc = l & 3;
    const int q0 = blockIdx.x * 128, h = blockIdx.y, b = blockIdx.z;
    const int wr = w * 16;

    const __half* Qg = proj + (long)(b * SS + q0) * PROJN + h * DH;
    const __half* Kg = proj + (long)(b * SS) * PROJN + DD + h * DH;
    const __half* Vg = proj + (long)(b * SS) * PROJN + 2 * DD + h * DH;

    const uint32_t smb = smem_u32(sm);

    // ---- stage Q (row-major, stride 72), fragments via ldmatrix ----
#pragma unroll
    for (int i = 0; i < 4; i++) {
        int idx = t + i * 256;
        int r = idx >> 3, c16 = idx & 7;
        *(float4*)&sm[r * VSTRH + c16 * 8] = *(const float4*)(Qg + (long)r * PROJN + c16 * 8);
    }
    __syncthreads();
    uint32_t qa[4][4];
    {
        const uint32_t q_lm = smb + (uint32_t)((wr + (l & 15)) * VSTRB + (l >> 4) * 16);
#pragma unroll
        for (int k = 0; k < 4; k++)
            ldsm_x4(qa[k], q_lm + k * 32);
    }
    __syncthreads();

    // ldmatrix lane byte-offsets within a tile
    const uint32_t kb_off = (uint32_t)(((l & 7) + ((l >> 4) << 3)) * VSTRB + ((l >> 3) & 1) * 16);
    const uint32_t vb_off = (uint32_t)(((l & 7) + ((l >> 3) & 1) * 8) * VSTRB + ((l >> 4) & 1) * 16);

    // per-thread cp.async assignments (2 K + 2 V rows-chunks)
    const int pr0 = t >> 3, pc0 = (t & 7) * 8;
    const int pr1 = (t + 256) >> 3, pc1 = pc0;

    auto prefetch = [&](int ti) {
        const uint32_t kd = smb + (uint32_t)((ti & 1) * FA_BUF * 2);
        const uint32_t vd = kd + FA_TILE * 2;
        const long kt = (long)ti * 64;
        cp16(kd + (pr0 * VSTRH + pc0) * 2, Kg + (kt + pr0) * PROJN + pc0);
        cp16(kd + (pr1 * VSTRH + pc1) * 2, Kg + (kt + pr1) * PROJN + pc1);
        cp16(vd + (pr0 * VSTRH + pc0) * 2, Vg + (kt + pr0) * PROJN + pc0);
        cp16(vd + (pr1 * VSTRH + pc1) * 2, Vg + (kt + pr1) * PROJN + pc1);
        CP_COMMIT();
    };

    float m0 = -1e30f, m1 = -1e30f, l0 = 0.f, l1 = 0.f;
    float o[8][4];
#pragma unroll
    for (int n = 0; n < 8; n++)
#pragma unroll
        for (int i = 0; i < 4; i++) o[n][i] = 0.f;

    prefetch(0);

    for (int ti = 0; ti < FA_NT; ti++) {
        if (ti + 1 < FA_NT) { prefetch(ti + 1); CP_WAIT1(); }
        else { CP_WAIT0(); }
        __syncthreads();

        const uint32_t kbase = smb + (uint32_t)((ti & 1) * FA_BUF * 2);
        const uint32_t vbase = kbase + FA_TILE * 2;

        // ---- S = Q @ K^T ----
        float sa[8][4];
#pragma unroll
        for (int n = 0; n < 8; n++)
#pragma unroll
            for (int i = 0; i < 4; i++) sa[n][i] = 0.f;
#pragma unroll
        for (int k = 0; k < 4; k++) {
            uint32_t kb[4][4];
#pragma unroll
            for (int ng = 0; ng < 4; ng++)
                ldsm_x4(kb[ng], kbase + kb_off + ng * 16 * VSTRB + k * 32);
#pragma unroll
            for (int n = 0; n < 8; n++)
                mma_f16(sa[n], qa[k], &kb[n >> 1][(n & 1) * 2]);
        }

        // ---- online softmax ----
        float rm0 = -1e30f, rm1 = -1e30f;
#pragma unroll
        for (int n = 0; n < 8; n++) {
            sa[n][0] *= 0.125f; sa[n][1] *= 0.125f;
            sa[n][2] *= 0.125f; sa[n][3] *= 0.125f;
            rm0 = fmaxf(rm0, fmaxf(sa[n][0], sa[n][1]));
            rm1 = fmaxf(rm1, fmaxf(sa[n][2], sa[n][3]));
        }
        rm0 = fmaxf(rm0, __shfl_xor_sync(0xffffffffu, rm0, 1));
        rm0 = fmaxf(rm0, __shfl_xor_sync(0xffffffffu, rm0, 2));
        rm1 = fmaxf(rm1, __shfl_xor_sync(0xffffffffu, rm1, 1));
        rm1 = fmaxf(rm1, __shfl_xor_sync(0xffffffffu, rm1, 2));

        const float nm0 = fmaxf(m0, rm0), nm1 = fmaxf(m1, rm1);
        const float c0 = __expf(m0 - nm0), c1 = __expf(m1 - nm1);
        float rs0 = 0.f, rs1 = 0.f;
#pragma unroll
        for (int n = 0; n < 8; n++) {
            sa[n][0] = __expf(sa[n][0] - nm0);
            sa[n][1] = __expf(sa[n][1] - nm0);
            sa[n][2] = __expf(sa[n][2] - nm1);
            sa[n][3] = __expf(sa[n][3] - nm1);
            rs0 += sa[n][0] + sa[n][1];
            rs1 += sa[n][2] + sa[n][3];
            o[n][0] *= c0; o[n][1] *= c0; o[n][2] *= c1; o[n][3] *= c1;
        }
        rs0 += __shfl_xor_sync(0xffffffffu, rs0, 1);
        rs0 += __shfl_xor_sync(0xffffffffu, rs0, 2);
        rs1 += __shfl_xor_sync(0xffffffffu, rs1, 1);
        rs1 += __shfl_xor_sync(0xffffffffu, rs1, 2);
        l0 = l0 * c0 + rs0; l1 = l1 * c1 + rs1;
        m0 = nm0; m1 = nm1;

        // ---- O += P @ V (register P fragments; V via ldmatrix.trans) ----
#pragma unroll
        for (int k = 0; k < 4; k++) {
            uint32_t pa[4];
            pa[0] = h2u(sa[2 * k][0], sa[2 * k][1]);
            pa[1] = h2u(sa[2 * k][2], sa[2 * k][3]);
            pa[2] = h2u(sa[2 * k + 1][0], sa[2 * k + 1][1]);
            pa[3] = h2u(sa[2 * k + 1][2], sa[2 * k + 1][3]);
#pragma unroll
            for (int dg = 0; dg < 4; dg++) {
                uint32_t vb[4];
                ldsm_x4_t(vb, vbase + vb_off + k * 16 * VSTRB + dg * 32);
                mma_f16(o[dg * 2 + 0], pa, &vb[0]);
                mma_f16(o[dg * 2 + 1], pa, &vb[2]);
            }
        }
        __syncthreads();
    }

    const float sig = sigbuf[0];
    const float i0 = sig / l0, i1 = sig / l1;
    __half* Og = ctx + (long)(b * SS + q0 + wr) * DD + h * DH;
#pragma unroll
    for (int n = 0; n < 8; n++) {
        *(__half2*)&Og[(long)qr * DD + n * 8 + 2 * qc] = __floats2half2_rn(o[n][0] * i0, o[n][1] * i0);
        *(__half2*)&Og[(long)(qr + 8) * DD + n * 8 + 2 * qc] = __floats2half2_rn(o[n][2] * i1, o[n][3] * i1);
    }
}

// ======================= radix top-k + masked softmax -> half P =======================
__global__ __launch_bounds__(256) void topk_softmax_kernel(const float* __restrict__ P,
                                                           const float* __restrict__ sigbuf,
                                                           __half* __restrict__ Ph)
{
    const long base = (long)blockIdx.x * SS;
    __shared__ float vals[SS];
    __shared__ unsigned keys[SS];
    __shared__ unsigned hist[256];
    __shared__ float redA[8], redB[8];
    __shared__ unsigned s_prefix;
    __shared__ int s_need;

    const int t = threadIdx.x;
    const int w = t >> 5, lane = t & 31;

    float lmax = -1e30f;
#pragma unroll
    for (int i = 0; i < 4; i++) {
        float v = P[base + t + i * 256];
        vals[t + i * 256] = v;
        unsigned u = __float_as_uint(v);
        u ^= (u >> 31) ? 0xFFFFFFFFu : 0x80000000u;
        keys[t + i * 256] = u;
        lmax = fmaxf(lmax, v);
    }
#pragma unroll
    for (int o = 16; o > 0; o >>= 1)
        lmax = fmaxf(lmax, __shfl_xor_sync(0xffffffffu, lmax, o));
    if (lane == 0) redA[w] = lmax;
    __syncthreads();
    float mx = redA[0];
#pragma unroll
    for (int i = 1; i < 8; i++) mx = fmaxf(mx, redA[i]);

    unsigned prefix = 0;
    int need = KSEL;
#pragma unroll
    for (int pass = 0; pass < 4; pass++) {
        const int shift = 24 - 8 * pass;
        const unsigned hmask = pass ? (0xFFFFFFFFu << (shift + 8)) : 0u;
        hist[t] = 0;
        __syncthreads();
#pragma unroll
        for (int i = 0; i < 4; i++) {
            unsigned u = keys[t + i * 256];
            if ((u & hmask) == prefix)
                atomicAdd(&hist[(u >> shift) & 0xFFu], 1u);
        }
        __syncthreads();
        if (t == 0) {
            int cum = 0, bsel = 0;
            for (int bbin = 255; bbin >= 0; bbin--) {
                int hh = (int)hist[bbin];
                if (cum + hh >= need) { bsel = bbin; break; }
                cum += hh;
            }
            s_prefix = prefix | ((unsigned)bsel << shift);
            s_need = need - cum;
        }
        __syncthreads();
        prefix = s_prefix;
        need = s_need;
        __syncthreads();
    }
    const unsigned thr = prefix;

    float e[4];
    float sk = 0.f, sf = 0.f;
#pragma unroll
    for (int i = 0; i < 4; i++) {
        float v = vals[t + i * 256];
        float ef = __expf(v - mx);
        bool kp = keys[t + i * 256] >= thr;
        e[i] = kp ? ef : 0.f;
        sk += e[i];
        sf += ef;
    }
#pragma unroll
    for (int o = 16; o > 0; o >>= 1) {
        sk += __shfl_xor_sync(0xffffffffu, sk, o);
        sf += __shfl_xor_sync(0xffffffffu, sf, o);
    }
    if (lane == 0) { redA[w] = sk; redB[w] = sf; }
    __syncthreads();
    float tk = 0.f, tf = 0.f;
#pragma unroll
    for (int i = 0; i < 8; i++) { tk += redA[i]; tf += redB[i]; }
    const float inv = (1.f - sigbuf[0]) / (tk + 1e-9f * tf);
#pragma unroll
    for (int i = 0; i < 4; i++)
        Ph[base + t + i * 256] = __float2half(e[i] * inv);
}

// ======================= residual + LN1 (3 inputs) =======================
__global__ __launch_bounds__(256) void fuse_ln1_kernel(
    const float* __restrict__ src, const float* __restrict__ dense,
    const float* __restrict__ sparse,
    const float* __restrict__ g, const float* __restrict__ bb,
    float* __restrict__ x, __half* __restrict__ xh)
{
    const long row = (long)blockIdx.x * DD;
    __shared__ float buf[DD];
    __shared__ float r1[8], r2[8];

    float s1 = 0.f, s2 = 0.f;
    for (int d = threadIdx.x; d < DD; d += 256) {
        float v = src[row + d] + dense[row + d] + sparse[row + d];
        buf[d] = v; s1 += v; s2 += v * v;
    }
#pragma unroll
    for (int o = 16; o > 0; o >>= 1) {
        s1 += __shfl_xor_sync(0xffffffffu, s1, o);
        s2 += __shfl_xor_sync(0xffffffffu, s2, o);
    }
    const int w = threadIdx.x >> 5, lane = threadIdx.x & 31;
    if (lane == 0) { r1[w] = s1; r2[w] = s2; }
    __syncthreads();
    if (threadIdx.x == 0) {
        float a = 0.f, c = 0.f;
        for (int i = 0; i < 8; i++) { a += r1[i]; c += r2[i]; }
        r1[0] = a; r2[0] = c;
    }
    __syncthreads();
    const float mean = r1[0] * (1.f / DD);
    const float var = r2[0] * (1.f / DD) - mean * mean;
    const float rstd = rsqrtf(var + 1e-5f);
    for (int d = threadIdx.x; d < DD; d += 256) {
        float v = (buf[d] - mean) * rstd * g[d] + bb[d];
        x[row + d] = v;
        xh[row + d] = __float2half(v);
    }
}

// ======================= residual + LN2 -> out =======================
__global__ __launch_bounds__(256) void ln2_kernel(
    const float* __restrict__ x, const float* __restrict__ ff,
    const float* __restrict__ g, const float* __restrict__ bb,
    float* __restrict__ out)
{
    const long row = (long)blockIdx.x * DD;
    __shared__ float buf[DD];
    __shared__ float r1[8], r2[8];

    float s1 = 0.f, s2 = 0.f;
    for (int d = threadIdx.x; d < DD; d += 256) {
        float v = x[row + d] + ff[row + d];
        buf[d] = v; s1 += v; s2 += v * v;
    }
#pragma unroll
    for (int o = 16; o > 0; o >>= 1) {
        s1 += __shfl_xor_sync(0xffffffffu, s1, o);
        s2 += __shfl_xor_sync(0xffffffffu, s2, o);
    }
    const int w = threadIdx.x >> 5, lane = threadIdx.x & 31;
    if (lane == 0) { r1[w] = s1; r2[w] = s2; }
    __syncthreads();
    if (threadIdx.x == 0) {
        float a = 0.f, c = 0.f;
        for (int i = 0; i < 8; i++) { a += r1[i]; c += r2[i]; }
        r1[0] = a; r2[0] = c;
    }
    __syncthreads();
    const float mean = r1[0] * (1.f / DD);
    const float var = r2[0] * (1.f / DD) - mean * mean;
    const float rstd = rsqrtf(var + 1e-5f);
    for (int d = threadIdx.x; d < DD; d += 256)
        out[row + d] = (buf[d] - mean) * rstd * g[d] + bb[d];
}

// ======================= launch =======================
extern "C" void kernel_launch(void* const* d_in, const int* in_sizes, int n_in,
                              void* d_out, int out_size)
{
    (void)in_sizes; (void)n_in; (void)out_size;
    const float* src    = (const float*)d_in[0];
    const float* in_w   = (const float*)d_in[1];
    const float* in_b   = (const float*)d_in[2];
    const float* outp_w = (const float*)d_in[3];
    const float* outp_b = (const float*)d_in[4];
    const float* Qp_w   = (const float*)d_in[5];
    const float* Qp_b   = (const float*)d_in[6];
    const float* Kp_w   = (const float*)d_in[7];
    const float* Kp_b   = (const float*)d_in[8];
    const float* Vp_w   = (const float*)d_in[9];
    const float* Vp_b   = (const float*)d_in[10];
    const float* lam    = (const float*)d_in[11];
    const float* ff1_w  = (const float*)d_in[12];
    const float* ff1_b  = (const float*)d_in[13];
    const float* ff2_w  = (const float*)d_in[14];
    const float* ff2_b  = (const float*)d_in[15];
    const float* ln1_g  = (const float*)d_in[16];
    const float* ln1_b  = (const float*)d_in[17];
    const float* ln2_g  = (const float*)d_in[18];
    const float* ln2_b  = (const float*)d_in[19];
    float* out = (float*)d_out;

    __half *hw_pack, *hw_out, *hw_f1, *hw_f2;
    __half *src_h, *proj_h, *ctx_h, *Vt_h, *Ph, *x_h, *h1_h;
    float *bias_pack, *bias_dense, *sigbuf, *P, *dense, *sparse, *x, *ff;
    cudaGetSymbolAddress((void**)&hw_pack,    g_hw_pack);
    cudaGetSymbolAddress((void**)&hw_out,     g_hw_out);
    cudaGetSymbolAddress((void**)&hw_f1,      g_hw_f1);
    cudaGetSymbolAddress((void**)&hw_f2,      g_hw_f2);
    cudaGetSymbolAddress((void**)&bias_pack,  g_bias_pack);
    cudaGetSymbolAddress((void**)&bias_dense, g_bias_dense);
    cudaGetSymbolAddress((void**)&sigbuf,     g_sig);
    cudaGetSymbolAddress((void**)&src_h,      g_src_h);
    cudaGetSymbolAddress((void**)&proj_h,     g_proj_h);
    cudaGetSymbolAddress((void**)&ctx_h,      g_ctx_h);
    cudaGetSymbolAddress((void**)&Vt_h,       g_Vt_h);
    cudaGetSymbolAddress((void**)&Ph,         g_Ph);
    cudaGetSymbolAddress((void**)&x_h,        g_x_h);
    cudaGetSymbolAddress((void**)&h1_h,       g_h1_h);
    cudaGetSymbolAddress((void**)&P,          g_P);
    cudaGetSymbolAddress((void**)&dense,      g_dense);
    cudaGetSymbolAddress((void**)&sparse,     g_sparse);
    cudaGetSymbolAddress((void**)&x,          g_x);
    cudaGetSymbolAddress((void**)&ff,         g_ff);

    cudaFuncSetAttribute(hgemm_nt, cudaFuncAttributeMaxDynamicSharedMemorySize, GEMM_SMEM);

    static cudaStream_t sA = nullptr, sB = nullptr, sC = nullptr;
    static cudaEvent_t evC = nullptr, evA = nullptr, evB = nullptr, evT = nullptr;
    if (!sA) {
        cudaStreamCreateWithFlags(&sA, cudaStreamNonBlocking);
        cudaStreamCreateWithFlags(&sB, cudaStreamNonBlocking);
        cudaStreamCreateWithFlags(&sC, cudaStreamNonBlocking);
        cudaEventCreateWithFlags(&evC, cudaEventDisableTiming);
        cudaEventCreateWithFlags(&evA, cudaEventDisableTiming);
        cudaEventCreateWithFlags(&evB, cudaEventDisableTiming);
        cudaEventCreateWithFlags(&evT, cudaEventDisableTiming);
    }

    // sA: non-critical weight conversion, overlaps the critical path
    convert_rest<<<9216, 256, 0, sA>>>(outp_w, ff1_w, ff2_w, hw_out, hw_f1, hw_f2);

    // main: critical conversion then proj GEMM
    convert_crit<<<8321, 256>>>(in_w, Qp_w, Kp_w, Vp_w, src,
                                in_b, Qp_b, Kp_b, Vp_b, outp_b, lam,
                                hw_pack, src_h, bias_pack, bias_dense, sigbuf);
    hgemm_nt<<<dim3(PROJN / BN, NTOK / BM), 256, GEMM_SMEM>>>(
        src_h, hw_pack, DD, DD, DD, 0, 0,
        src_h, hw_pack, 0, DD, DD, 0, 0,
        bias_pack, proj_h, PROJN, 0, 1.f, 0, 1);
    cudaEventRecord(evC, 0);
    cudaStreamWaitEvent(sA, evC, 0);
    cudaStreamWaitEvent(sB, evC, 0);
    cudaStreamWaitEvent(sC, evC, 0);

    // ---- branch A: flash attention -> dense = sig*(ctx@out^T) + sig*b ----
    flash_attn_kernel<<<dim3(SS / 128, HH, BB), 256, 0, sA>>>(proj_h, sigbuf, ctx_h);
    hgemm_nt<<<dim3(DD / BN, NTOK / BM), 256, GEMM_SMEM, sA>>>(
        ctx_h, hw_out, DD, DD, DD, 0, 0,
        ctx_h, hw_out, 0, DD, DD, 0, 0,
        bias_dense, dense, DD, 0, 1.f, 0, 0);
    cudaEventRecord(evA, sA);

    // ---- branch C: V transpose (independent of scores/topk) ----
    transpose_proj_kernel<<<dim3(SS / 32, DD / 32, BB), 256, 0, sC>>>(proj_h, Vt_h);
    cudaEventRecord(evT, sC);

    // ---- branch B: scores -> topk -> sparse = (1-sig)*(P@V) ----
    hgemm_nt<<<dim3(SS / BN, SS / BM, BB), 256, GEMM_SMEM, sB>>>(
        proj_h + 3 * DD, proj_h + 3 * DD + RR, RR, PROJN, PROJN,
        (long)SS * PROJN, (long)SS * PROJN,
        proj_h, proj_h, 0, PROJN, PROJN, 0, 0,
        nullptr, P, SS, (long)SS * SS, 0.125f, 0, 0);
    topk_softmax_kernel<<<NTOK, 256, 0, sB>>>(P, sigbuf, Ph);
    cudaStreamWaitEvent(sB, evT, 0);
    hgemm_nt<<<dim3(DD / BN, SS / BM, BB), 256, GEMM_SMEM, sB>>>(
        Ph, Vt_h, SS, SS, SS, (long)SS * SS, (long)DD * SS,
        Ph, Vt_h, 0, SS, SS, 0, 0,
        nullptr, sparse, DD, (long)SS * DD, 1.f, 0, 0);
    cudaEventRecord(evB, sB);

    // ---- join ----
    cudaStreamWaitEvent(0, evA, 0);
    cudaStreamWaitEvent(0, evB, 0);

    // x = LN1(src + dense + sparse) -> f32 + half
    fuse_ln1_kernel<<<NTOK, 256>>>(src, dense, sparse, ln1_g, ln1_b, x, x_h);
    // h1 = relu(x @ ff1^T + b) -> half
    hgemm_nt<<<dim3(DFFN / BN, NTOK / BM), 256, GEMM_SMEM>>>(
        x_h, hw_f1, DD, DD, DD, 0, 0,
        x_h, hw_f1, 0, DD, DD, 0, 0,
        ff1_b, h1_h, DFFN, 0, 1.f, 1, 1);
    // ff = h1 @ ff2^T + b -> f32
    hgemm_nt<<<dim3(DD / BN, NTOK / BM), 256, GEMM_SMEM>>>(
        h1_h, hw_f2, DFFN, DFFN, DFFN, 0, 0,
        h1_h, hw_f2, 0, DFFN, DFFN, 0, 0,
        ff2_b, ff, DD, 0, 1.f, 0, 0);
    // out = LN2(x + ff)
    ln2_kernel<<<NTOK, 256>>>(x, ff, ln2_g, ln2_b, out);
}

// round 15
// speedup vs baseline: 1.3617x; 1.1854x over previous
#include <cuda_runtime.h>
#include <cuda_fp16.h>
#include <cstdint>
#include <math.h>

// Problem dims
#define BB   4
#define SS   1024
#define DD   1024
#define HH   16
#define DH   64
#define RR   64
#define DFFN 4096
#define NTOK (BB*SS)       // 4096
#define KSEL 204           // int(1024*0.2)
#define PROJN 4224         // 3*DD + 2*RR + DD  (qkv | Q | K | V)

// ---------------- scratch (device globals) ----------------
__device__ __half g_hw_pack[(long)PROJN * DD];
__device__ float  g_bias_pack[PROJN];
__device__ __half g_hw_out[(long)DD * DD];
__device__ float  g_bias_dense[DD];
__device__ float  g_sig[1];
__device__ __half g_hw_f1[(long)DFFN * DD];
__device__ __half g_hw_f2[(long)DD * DFFN];
__device__ __half g_src_h[(long)NTOK * DD];
__device__ __half g_proj_h[(long)NTOK * PROJN];
__device__ __half g_ctx_h[(long)NTOK * DD];
__device__ __half g_Vt_h[(long)NTOK * DD];
__device__ __half g_Ph[(long)BB * SS * SS];
__device__ float g_P[(long)BB * SS * SS];
__device__ float g_dense[(long)NTOK * DD];
__device__ float g_sparse[(long)NTOK * DD];
__device__ float g_x[(long)NTOK * DD];
__device__ __half g_x_h[(long)NTOK * DD];
__device__ __half g_h1_h[(long)NTOK * DFFN];
__device__ float g_ff[(long)NTOK * DD];

// ======================= helpers =======================
__device__ __forceinline__ uint32_t smem_u32(const void* p) {
    uint32_t a;
    asm("{ .reg .u64 t; cvta.to.shared.u64 t, %1; cvt.u32.u64 %0, t; }" : "=r"(a) : "l"(p));
    return a;
}
__device__ __forceinline__ void cp16(uint32_t saddr, const void* g) {
    asm volatile("cp.async.ca.shared.global [%0], [%1], 16;"
                 :: "r"(saddr), "l"(g) : "memory");
}
#define CP_COMMIT() asm volatile("cp.async.commit_group;" ::: "memory")
#define CP_WAIT2()  asm volatile("cp.async.wait_group 2;" ::: "memory")
#define CP_WAIT1()  asm volatile("cp.async.wait_group 1;" ::: "memory")
#define CP_WAIT0()  asm volatile("cp.async.wait_group 0;" ::: "memory")

__device__ __forceinline__ void mma_f16(float* c, const uint32_t* a, const uint32_t* b) {
    asm volatile(
        "mma.sync.aligned.m16n8k16.row.col.f32.f16.f16.f32 "
        "{%0,%1,%2,%3}, {%4,%5,%6,%7}, {%8,%9}, {%0,%1,%2,%3};"
        : "+f"(c[0]), "+f"(c[1]), "+f"(c[2]), "+f"(c[3])
        : "r"(a[0]), "r"(a[1]), "r"(a[2]), "r"(a[3]), "r"(b[0]), "r"(b[1]));
}
__device__ __forceinline__ void ldsm_x4(uint32_t* r, uint32_t saddr) {
    asm volatile("ldmatrix.sync.aligned.m8n8.x4.shared.b16 {%0,%1,%2,%3}, [%4];"
                 : "=r"(r[0]), "=r"(r[1]), "=r"(r[2]), "=r"(r[3]) : "r"(saddr));
}
__device__ __forceinline__ void ldsm_x4_t(uint32_t* r, uint32_t saddr) {
    asm volatile("ldmatrix.sync.aligned.m8n8.x4.trans.shared.b16 {%0,%1,%2,%3}, [%4];"
                 : "=r"(r[0]), "=r"(r[1]), "=r"(r[2]), "=r"(r[3]) : "r"(saddr));
}
__device__ __forceinline__ uint32_t h2u(float x, float y) {
    __half2 h = __floats2half2_rn(x, y);
    return *(uint32_t*)&h;
}

// ======================= critical converter =======================
__global__ __launch_bounds__(256) void convert_crit(
    const float* in_w, const float* Qp_w, const float* Kp_w, const float* Vp_w,
    const float* src,
    const float* in_b, const float* Qp_b, const float* Kp_b, const float* Vp_b,
    const float* outp_b, const float* lam,
    __half* hw_pack, __half* src_h,
    float* bias_pack, float* bias_dense, float* sigbuf)
{
    const int bid = blockIdx.x, t = threadIdx.x;
    if (bid == 8320) {
        const float sig = 1.f / (1.f + __expf(-lam[0]));
        if (t == 0) sigbuf[0] = sig;
        for (int i = t; i < PROJN; i += 256) {
            float v;
            if      (i < 3 * DD)          v = in_b[i];
            else if (i < 3 * DD + RR)     v = Qp_b[i - 3 * DD];
            else if (i < 3 * DD + 2 * RR) v = Kp_b[i - 3 * DD - RR];
            else                          v = Vp_b[i - 3 * DD - 2 * RR];
            bias_pack[i] = v;
        }
        for (int i = t; i < DD; i += 256)
            bias_dense[i] = sig * outp_b[i];
        return;
    }
    const float* in; __half* out;
    if (bid < PROJN) {
        const int r = bid;
        if      (r < 3 * DD)          in = in_w + (long)r * DD;
        else if (r < 3 * DD + RR)     in = Qp_w + (long)(r - 3 * DD) * DD;
        else if (r < 3 * DD + 2 * RR) in = Kp_w + (long)(r - 3 * DD - RR) * DD;
        else                          in = Vp_w + (long)(r - 3 * DD - 2 * RR) * DD;
        out = hw_pack + (long)bid * DD;
    } else {
        in = src + (long)(bid - PROJN) * 1024;
        out = src_h + (long)(bid - PROJN) * 1024;
    }
    long i = t * 4;
    float4 v = *(const float4*)(in + i);
    *(__half2*)(out + i) = __floats2half2_rn(v.x, v.y);
    *(__half2*)(out + i + 2) = __floats2half2_rn(v.z, v.w);
}

// ======================= non-critical converter =======================
__global__ __launch_bounds__(256) void convert_rest(
    const float* outp_w, const float* ff1_w, const float* ff2_w,
    __half* hw_out, __half* hw_f1, __half* hw_f2)
{
    const int bid = blockIdx.x, t = threadIdx.x;
    const float* in; __half* out; long off;
    if      (bid < 1024) { in = outp_w; out = hw_out; off = (long)bid * 1024; }
    else if (bid < 5120) { in = ff1_w;  out = hw_f1;  off = (long)(bid - 1024) * 1024; }
    else                 { in = ff2_w;  out = hw_f2;  off = (long)(bid - 5120) * 1024; }
    long i = off + t * 4;
    float4 v = *(const float4*)(in + i);
    *(__half2*)(out + i) = __floats2half2_rn(v.x, v.y);
    *(__half2*)(out + i + 2) = __floats2half2_rn(v.z, v.w);
}

// ======================= fp16 warp-MMA GEMM, two K-segments, BKH=64 =======================
#define BM 256
#define BN 128
#define BKH 64     // halves per K chunk (4 k16 sub-steps)
#define KSTRH 36   // b32 row stride (32 data + 4 pad); 144B => conflict-free ldsm
#define A_B32 (BM * KSTRH)              // 9216
#define STG_B32 (A_B32 + BN * KSTRH)    // 13824
#define GEMM_SMEM (3 * STG_B32 * 4)     // 165888 B

__global__ __launch_bounds__(256) void hgemm_nt(
    const __half* __restrict__ A1, const __half* __restrict__ B1,
    int K1, int lda1, int ldb1, long sA1, long sB1,
    const __half* __restrict__ A2, const __half* __restrict__ B2,
    int K2, int lda2, int ldb2, long sA2, long sB2,
    const float* __restrict__ bias, void* __restrict__ Cout,
    int N, long sC, float alpha, int relu, int out_half)
{
    extern __shared__ uint32_t gsm[];

    const __half* A1g = A1 + (long)blockIdx.z * sA1;
    const __half* B1g = B1 + (long)blockIdx.z * sB1;
    const __half* A2g = A2 + (long)blockIdx.z * sA2;
    const __half* B2g = B2 + (long)blockIdx.z * sB2;

    const int t = threadIdx.x;
    const int wid = t >> 5, l = t & 31;
    const int wm = wid >> 1, wn = wid & 1;
    const int mbase = wm * 64, nbase = wn * 64;
    const int qr = l >> 2, qc = l & 3;
    const int row0 = blockIdx.y * BM, col0 = blockIdx.x * BN;

    const uint32_t s0 = smem_u32(gsm);

    const int lr8 = t >> 3;           // 0..31
    const int lc4 = (t & 7) * 4;      // b32 col 0..28

    const uint32_t a_lm = s0 + (uint32_t)(((mbase + (l & 15)) * KSTRH + (l >> 4) * 4) * 4);
    const uint32_t b_lm = s0 + (uint32_t)((A_B32 +
        (nbase + (l & 7) + ((l >> 4) << 3)) * KSTRH + (((l >> 3) & 1) * 4)) * 4);

    float acc[4][8][4];
#pragma unroll
    for (int i = 0; i < 4; i++)
#pragma unroll
        for (int j = 0; j < 8; j++)
#pragma unroll
            for (int q = 0; q < 4; q++) acc[i][j][q] = 0.f;

    const int nc1 = K1 / BKH;
    const int nc = nc1 + K2 / BKH;

    auto prefetch = [&](int cc) {
        const int st = cc % 3;
        const __half* Ax; const __half* Bx; int k0, la, lb;
        if (cc < nc1) { Ax = A1g; Bx = B1g; k0 = cc * BKH; la = lda1; lb = ldb1; }
        else          { Ax = A2g; Bx = B2g; k0 = (cc - nc1) * BKH; la = lda2; lb = ldb2; }
        const uint32_t sAs = s0 + st * STG_B32 * 4;
        const uint32_t sBs = sAs + A_B32 * 4;
#pragma unroll
        for (int j = 0; j < 8; j++) {
            int m = lr8 + j * 32;
            cp16(sAs + (m * KSTRH + lc4) * 4, &Ax[(long)(row0 + m) * la + k0 + lc4 * 2]);
        }
#pragma unroll
        for (int j = 0; j < 4; j++) {
            int n = lr8 + j * 32;
            cp16(sBs + (n * KSTRH + lc4) * 4, &Bx[(long)(col0 + n) * lb + k0 + lc4 * 2]);
        }
        CP_COMMIT();
    };

    prefetch(0);
    if (nc > 1) prefetch(1);

    for (int c = 0; c < nc; c++) {
        if (c + 2 < nc) { prefetch(c + 2); CP_WAIT2(); }
        else if (c + 1 < nc) { CP_WAIT1(); }
        else { CP_WAIT0(); }
        __syncthreads();

        const uint32_t stoff = (uint32_t)((c % 3) * STG_B32 * 4);
#pragma unroll
        for (int kk = 0; kk < 4; kk++) {
            const uint32_t koff = stoff + kk * 8 * 4;
            uint32_t af[4][4], bf[4][4];
#pragma unroll
            for (int mt = 0; mt < 4; mt++)
                ldsm_x4(af[mt], a_lm + koff + mt * 16 * KSTRH * 4);
#pragma unroll
            for (int np = 0; np < 4; np++)
                ldsm_x4(bf[np], b_lm + koff + np * 16 * KSTRH * 4);
#pragma unroll
            for (int mt = 0; mt < 4; mt++) {
#pragma unroll
                for (int nt = 0; nt < 8; nt++)
                    mma_f16(acc[mt][nt], af[mt], &bf[nt >> 1][(nt & 1) * 2]);
            }
        }
        __syncthreads();
    }

    // ---- epilogue ----
#pragma unroll
    for (int mt = 0; mt < 4; mt++) {
        const int r = row0 + mbase + mt * 16 + qr;
#pragma unroll
        for (int nt = 0; nt < 8; nt++) {
            const int cc = col0 + nbase + nt * 8 + qc * 2;
            float b0 = 0.f, b1 = 0.f;
            if (bias) { b0 = bias[cc]; b1 = bias[cc + 1]; }
            float v0 = acc[mt][nt][0] * alpha + b0;
            float v1 = acc[mt][nt][1] * alpha + b1;
            float v2 = acc[mt][nt][2] * alpha + b0;
            float v3 = acc[mt][nt][3] * alpha + b1;
            if (relu) {
                v0 = fmaxf(v0, 0.f); v1 = fmaxf(v1, 0.f);
                v2 = fmaxf(v2, 0.f); v3 = fmaxf(v3, 0.f);
            }
            if (out_half) {
                __half* C = (__half*)Cout + blockIdx.z * sC;
                *(__half2*)&C[(long)r * N + cc] = __floats2half2_rn(v0, v1);
                *(__half2*)&C[(long)(r + 8) * N + cc] = __floats2half2_rn(v2, v3);
            } else {
                float* C = (float*)Cout + blockIdx.z * sC;
                float2 p0 = {v0, v1}, p1 = {v2, v3};
                *(float2*)&C[(long)r * N + cc] = p0;
                *(float2*)&C[(long)(r + 8) * N + cc] = p1;
            }
        }
    }
}

// ======================= half transpose from proj (V cols) =======================
__global__ __launch_bounds__(256) void transpose_proj_kernel(const __half* __restrict__ proj,
                                                             __half* __restrict__ Vt)
{
    __shared__ __half tile[32][33];
    const __half* Pb = proj + (long)blockIdx.z * SS * PROJN + (3 * DD + 2 * RR);
    __half* Vtb = Vt + (long)blockIdx.z * DD * SS;
    const int s0 = blockIdx.x * 32, d0 = blockIdx.y * 32;
    const int tx = threadIdx.x & 31, ty0 = threadIdx.x >> 5;
#pragma unroll
    for (int i = 0; i < 4; i++) {
        int ty = ty0 + i * 8;
        tile[ty][tx] = Pb[(long)(s0 + ty) * PROJN + d0 + tx];
    }
    __syncthreads();
#pragma unroll
    for (int i = 0; i < 4; i++) {
        int ty = ty0 + i * 8;
        Vtb[(long)(d0 + ty) * SS + s0 + tx] = tile[tx][ty];
    }
}

// ======================= fp16 flash attention (ldmatrix + register P + cp.async db) =======================
#define VSTRH 72
#define VSTRB 144
#define FA_TILE (64 * VSTRH)
#define FA_BUF  (2 * FA_TILE)
#define FA_NT   (SS / 64)

__global__ __launch_bounds__(256) void flash_attn_kernel(const __half* __restrict__ proj,
                                                         const float* __restrict__ sigbuf,
                                                         __half* __restrict__ ctx)
{
    __shared__ __half sm[2 * FA_BUF];

    const int t = threadIdx.x, w = t >> 5, l = t & 31;
    const int qr = l >> 2, qc = l & 3;
    const int q0 = blockIdx.x * 128, h = blockIdx.y, b = blockIdx.z;
    const int wr = w * 16;

    const __half* Qg = proj + (long)(b * SS + q0) * PROJN + h * DH;
    const __half* Kg = proj + (long)(b * SS) * PROJN + DD + h * DH;
    const __half* Vg = proj + (long)(b * SS) * PROJN + 2 * DD + h * DH;

    const uint32_t smb = smem_u32(sm);

#pragma unroll
    for (int i = 0; i < 4; i++) {
        int idx = t + i * 256;
        int r = idx >> 3, c16 = idx & 7;
        *(float4*)&sm[r * VSTRH + c16 * 8] = *(const float4*)(Qg + (long)r * PROJN + c16 * 8);
    }
    __syncthreads();
    uint32_t qa[4][4];
    {
        const uint32_t q_lm = smb + (uint32_t)((wr + (l & 15)) * VSTRB + (l >> 4) * 16);
#pragma unroll
        for (int k = 0; k < 4; k++)
            ldsm_x4(qa[k], q_lm + k * 32);
    }
    __syncthreads();

    const uint32_t kb_off = (uint32_t)(((l & 7) + ((l >> 4) << 3)) * VSTRB + ((l >> 3) & 1) * 16);
    const uint32_t vb_off = (uint32_t)(((l & 7) + ((l >> 3) & 1) * 8) * VSTRB + ((l >> 4) & 1) * 16);

    const int pr0 = t >> 3, pc0 = (t & 7) * 8;
    const int pr1 = (t + 256) >> 3, pc1 = pc0;

    auto prefetch = [&](int ti) {
        const uint32_t kd = smb + (uint32_t)((ti & 1) * FA_BUF * 2);
        const uint32_t vd = kd + FA_TILE * 2;
        const long kt = (long)ti * 64;
        cp16(kd + (pr0 * VSTRH + pc0) * 2, Kg + (kt + pr0) * PROJN + pc0);
        cp16(kd + (pr1 * VSTRH + pc1) * 2, Kg + (kt + pr1) * PROJN + pc1);
        cp16(vd + (pr0 * VSTRH + pc0) * 2, Vg + (kt + pr0) * PROJN + pc0);
        cp16(vd + (pr1 * VSTRH + pc1) * 2, Vg + (kt + pr1) * PROJN + pc1);
        CP_COMMIT();
    };

    float m0 = -1e30f, m1 = -1e30f, l0 = 0.f, l1 = 0.f;
    float o[8][4];
#pragma unroll
    for (int n = 0; n < 8; n++)
#pragma unroll
        for (int i = 0; i < 4; i++) o[n][i] = 0.f;

    prefetch(0);

    for (int ti = 0; ti < FA_NT; ti++) {
        if (ti + 1 < FA_NT) { prefetch(ti + 1); CP_WAIT1(); }
        else { CP_WAIT0(); }
        __syncthreads();

        const uint32_t kbase = smb + (uint32_t)((ti & 1) * FA_BUF * 2);
        const uint32_t vbase = kbase + FA_TILE * 2;

        float sa[8][4];
#pragma unroll
        for (int n = 0; n < 8; n++)
#pragma unroll
            for (int i = 0; i < 4; i++) sa[n][i] = 0.f;
#pragma unroll
        for (int k = 0; k < 4; k++) {
            uint32_t kb[4][4];
#pragma unroll
            for (int ng = 0; ng < 4; ng++)
                ldsm_x4(kb[ng], kbase + kb_off + ng * 16 * VSTRB + k * 32);
#pragma unroll
            for (int n = 0; n < 8; n++)
                mma_f16(sa[n], qa[k], &kb[n >> 1][(n & 1) * 2]);
        }

        float rm0 = -1e30f, rm1 = -1e30f;
#pragma unroll
        for (int n = 0; n < 8; n++) {
            sa[n][0] *= 0.125f; sa[n][1] *= 0.125f;
            sa[n][2] *= 0.125f; sa[n][3] *= 0.125f;
            rm0 = fmaxf(rm0, fmaxf(sa[n][0], sa[n][1]));
            rm1 = fmaxf(rm1, fmaxf(sa[n][2], sa[n][3]));
        }
        rm0 = fmaxf(rm0, __shfl_xor_sync(0xffffffffu, rm0, 1));
        rm0 = fmaxf(rm0, __shfl_xor_sync(0xffffffffu, rm0, 2));
        rm1 = fmaxf(rm1, __shfl_xor_sync(0xffffffffu, rm1, 1));
        rm1 = fmaxf(rm1, __shfl_xor_sync(0xffffffffu, rm1, 2));

        const float nm0 = fmaxf(m0, rm0), nm1 = fmaxf(m1, rm1);
        const float c0 = __expf(m0 - nm0), c1 = __expf(m1 - nm1);
        float rs0 = 0.f, rs1 = 0.f;
#pragma unroll
        for (int n = 0; n < 8; n++) {
            sa[n][0] = __expf(sa[n][0] - nm0);
            sa[n][1] = __expf(sa[n][1] - nm0);
            sa[n][2] = __expf(sa[n][2] - nm1);
            sa[n][3] = __expf(sa[n][3] - nm1);
            rs0 += sa[n][0] + sa[n][1];
            rs1 += sa[n][2] + sa[n][3];
            o[n][0] *= c0; o[n][1] *= c0; o[n][2] *= c1; o[n][3] *= c1;
        }
        rs0 += __shfl_xor_sync(0xffffffffu, rs0, 1);
        rs0 += __shfl_xor_sync(0xffffffffu, rs0, 2);
        rs1 += __shfl_xor_sync(0xffffffffu, rs1, 1);
        rs1 += __shfl_xor_sync(0xffffffffu, rs1, 2);
        l0 = l0 * c0 + rs0; l1 = l1 * c1 + rs1;
        m0 = nm0; m1 = nm1;

#pragma unroll
        for (int k = 0; k < 4; k++) {
            uint32_t pa[4];
            pa[0] = h2u(sa[2 * k][0], sa[2 * k][1]);
            pa[1] = h2u(sa[2 * k][2], sa[2 * k][3]);
            pa[2] = h2u(sa[2 * k + 1][0], sa[2 * k + 1][1]);
            pa[3] = h2u(sa[2 * k + 1][2], sa[2 * k + 1][3]);
#pragma unroll
            for (int dg = 0; dg < 4; dg++) {
                uint32_t vb[4];
                ldsm_x4_t(vb, vbase + vb_off + k * 16 * VSTRB + dg * 32);
                mma_f16(o[dg * 2 + 0], pa, &vb[0]);
                mma_f16(o[dg * 2 + 1], pa, &vb[2]);
            }
        }
        __syncthreads();
    }

    const float sig = sigbuf[0];
    const float i0 = sig / l0, i1 = sig / l1;
    __half* Og = ctx + (long)(b * SS + q0 + wr) * DD + h * DH;
#pragma unroll
    for (int n = 0; n < 8; n++) {
        *(__half2*)&Og[(long)qr * DD + n * 8 + 2 * qc] = __floats2half2_rn(o[n][0] * i0, o[n][1] * i0);
        *(__half2*)&Og[(long)(qr + 8) * DD + n * 8 + 2 * qc] = __floats2half2_rn(o[n][2] * i1, o[n][3] * i1);
    }
}

// ======================= radix top-k + masked softmax -> half P =======================
__global__ __launch_bounds__(256) void topk_softmax_kernel(const float* __restrict__ P,
                                                           const float* __restrict__ sigbuf,
                                                           __half* __restrict__ Ph)
{
    const long base = (long)blockIdx.x * SS;
    __shared__ float vals[SS];
    __shared__ unsigned keys[SS];
    __shared__ unsigned hist[256];
    __shared__ float redA[8], redB[8];
    __shared__ unsigned s_prefix;
    __shared__ int s_need;

    const int t = threadIdx.x;
    const int w = t >> 5, lane = t & 31;

    float lmax = -1e30f;
#pragma unroll
    for (int i = 0; i < 4; i++) {
        float v = P[base + t + i * 256];
        vals[t + i * 256] = v;
        unsigned u = __float_as_uint(v);
        u ^= (u >> 31) ? 0xFFFFFFFFu : 0x80000000u;
        keys[t + i * 256] = u;
        lmax = fmaxf(lmax, v);
    }
#pragma unroll
    for (int o = 16; o > 0; o >>= 1)
        lmax = fmaxf(lmax, __shfl_xor_sync(0xffffffffu, lmax, o));
    if (lane == 0) redA[w] = lmax;
    __syncthreads();
    float mx = redA[0];
#pragma unroll
    for (int i = 1; i < 8; i++) mx = fmaxf(mx, redA[i]);

    unsigned prefix = 0;
    int need = KSEL;
#pragma unroll
    for (int pass = 0; pass < 4; pass++) {
        const int shift = 24 - 8 * pass;
        const unsigned hmask = pass ? (0xFFFFFFFFu << (shift + 8)) : 0u;
        hist[t] = 0;
        __syncthreads();
#pragma unroll
        for (int i = 0; i < 4; i++) {
            unsigned u = keys[t + i * 256];
            if ((u & hmask) == prefix)
                atomicAdd(&hist[(u >> shift) & 0xFFu], 1u);
        }
        __syncthreads();
        if (t == 0) {
            int cum = 0, bsel = 0;
            for (int bbin = 255; bbin >= 0; bbin--) {
                int hh = (int)hist[bbin];
                if (cum + hh >= need) { bsel = bbin; break; }
                cum += hh;
            }
            s_prefix = prefix | ((unsigned)bsel << shift);
            s_need = need - cum;
        }
        __syncthreads();
        prefix = s_prefix;
        need = s_need;
        __syncthreads();
    }
    const unsigned thr = prefix;

    float e[4];
    float sk = 0.f, sf = 0.f;
#pragma unroll
    for (int i = 0; i < 4; i++) {
        float v = vals[t + i * 256];
        float ef = __expf(v - mx);
        bool kp = keys[t + i * 256] >= thr;
        e[i] = kp ? ef : 0.f;
        sk += e[i];
        sf += ef;
    }
#pragma unroll
    for (int o = 16; o > 0; o >>= 1) {
        sk += __shfl_xor_sync(0xffffffffu, sk, o);
        sf += __shfl_xor_sync(0xffffffffu, sf, o);
    }
    if (lane == 0) { redA[w] = sk; redB[w] = sf; }
    __syncthreads();
    float tk = 0.f, tf = 0.f;
#pragma unroll
    for (int i = 0; i < 8; i++) { tk += redA[i]; tf += redB[i]; }
    const float inv = (1.f - sigbuf[0]) / (tk + 1e-9f * tf);
#pragma unroll
    for (int i = 0; i < 4; i++)
        Ph[base + t + i * 256] = __float2half(e[i] * inv);
}

// ======================= residual + LN1 (3 inputs) =======================
__global__ __launch_bounds__(256) void fuse_ln1_kernel(
    const float* __restrict__ src, const float* __restrict__ dense,
    const float* __restrict__ sparse,
    const float* __restrict__ g, const float* __restrict__ bb,
    float* __restrict__ x, __half* __restrict__ xh)
{
    const long row = (long)blockIdx.x * DD;
    __shared__ float buf[DD];
    __shared__ float r1[8], r2[8];

    float s1 = 0.f, s2 = 0.f;
    for (int d = threadIdx.x; d < DD; d += 256) {
        float v = src[row + d] + dense[row + d] + sparse[row + d];
        buf[d] = v; s1 += v; s2 += v * v;
    }
#pragma unroll
    for (int o = 16; o > 0; o >>= 1) {
        s1 += __shfl_xor_sync(0xffffffffu, s1, o);
        s2 += __shfl_xor_sync(0xffffffffu, s2, o);
    }
    const int w = threadIdx.x >> 5, lane = threadIdx.x & 31;
    if (lane == 0) { r1[w] = s1; r2[w] = s2; }
    __syncthreads();
    if (threadIdx.x == 0) {
        float a = 0.f, c = 0.f;
        for (int i = 0; i < 8; i++) { a += r1[i]; c += r2[i]; }
        r1[0] = a; r2[0] = c;
    }
    __syncthreads();
    const float mean = r1[0] * (1.f / DD);
    const float var = r2[0] * (1.f / DD) - mean * mean;
    const float rstd = rsqrtf(var + 1e-5f);
    for (int d = threadIdx.x; d < DD; d += 256) {
        float v = (buf[d] - mean) * rstd * g[d] + bb[d];
        x[row + d] = v;
        xh[row + d] = __float2half(v);
    }
}

// ======================= residual + LN2 -> out =======================
__global__ __launch_bounds__(256) void ln2_kernel(
    const float* __restrict__ x, const float* __restrict__ ff,
    const float* __restrict__ g, const float* __restrict__ bb,
    float* __restrict__ out)
{
    const long row = (long)blockIdx.x * DD;
    __shared__ float buf[DD];
    __shared__ float r1[8], r2[8];

    float s1 = 0.f, s2 = 0.f;
    for (int d = threadIdx.x; d < DD; d += 256) {
        float v = x[row + d] + ff[row + d];
        buf[d] = v; s1 += v; s2 += v * v;
    }
#pragma unroll
    for (int o = 16; o > 0; o >>= 1) {
        s1 += __shfl_xor_sync(0xffffffffu, s1, o);
        s2 += __shfl_xor_sync(0xffffffffu, s2, o);
    }
    const int w = threadIdx.x >> 5, lane = threadIdx.x & 31;
    if (lane == 0) { r1[w] = s1; r2[w] = s2; }
    __syncthreads();
    if (threadIdx.x == 0) {
        float a = 0.f, c = 0.f;
        for (int i = 0; i < 8; i++) { a += r1[i]; c += r2[i]; }
        r1[0] = a; r2[0] = c;
    }
    __syncthreads();
    const float mean = r1[0] * (1.f / DD);
    const float var = r2[0] * (1.f / DD) - mean * mean;
    const float rstd = rsqrtf(var + 1e-5f);
    for (int d = threadIdx.x; d < DD; d += 256)
        out[row + d] = (buf[d] - mean) * rstd * g[d] + bb[d];
}

// ======================= launch =======================
extern "C" void kernel_launch(void* const* d_in, const int* in_sizes, int n_in,
                              void* d_out, int out_size)
{
    (void)in_sizes; (void)n_in; (void)out_size;
    const float* src    = (const float*)d_in[0];
    const float* in_w   = (const float*)d_in[1];
    const float* in_b   = (const float*)d_in[2];
    const float* outp_w = (const float*)d_in[3];
    const float* outp_b = (const float*)d_in[4];
    const float* Qp_w   = (const float*)d_in[5];
    const float* Qp_b   = (const float*)d_in[6];
    const float* Kp_w   = (const float*)d_in[7];
    const float* Kp_b   = (const float*)d_in[8];
    const float* Vp_w   = (const float*)d_in[9];
    const float* Vp_b   = (const float*)d_in[10];
    const float* lam    = (const float*)d_in[11];
    const float* ff1_w  = (const float*)d_in[12];
    const float* ff1_b  = (const float*)d_in[13];
    const float* ff2_w  = (const float*)d_in[14];
    const float* ff2_b  = (const float*)d_in[15];
    const float* ln1_g  = (const float*)d_in[16];
    const float* ln1_b  = (const float*)d_in[17];
    const float* ln2_g  = (const float*)d_in[18];
    const float* ln2_b  = (const float*)d_in[19];
    float* out = (float*)d_out;

    __half *hw_pack, *hw_out, *hw_f1, *hw_f2;
    __half *src_h, *proj_h, *ctx_h, *Vt_h, *Ph, *x_h, *h1_h;
    float *bias_pack, *bias_dense, *sigbuf, *P, *dense, *sparse, *x, *ff;
    cudaGetSymbolAddress((void**)&hw_pack,    g_hw_pack);
    cudaGetSymbolAddress((void**)&hw_out,     g_hw_out);
    cudaGetSymbolAddress((void**)&hw_f1,      g_hw_f1);
    cudaGetSymbolAddress((void**)&hw_f2,      g_hw_f2);
    cudaGetSymbolAddress((void**)&bias_pack,  g_bias_pack);
    cudaGetSymbolAddress((void**)&bias_dense, g_bias_dense);
    cudaGetSymbolAddress((void**)&sigbuf,     g_sig);
    cudaGetSymbolAddress((void**)&src_h,      g_src_h);
    cudaGetSymbolAddress((void**)&proj_h,     g_proj_h);
    cudaGetSymbolAddress((void**)&ctx_h,      g_ctx_h);
    cudaGetSymbolAddress((void**)&Vt_h,       g_Vt_h);
    cudaGetSymbolAddress((void**)&Ph,         g_Ph);
    cudaGetSymbolAddress((void**)&x_h,        g_x_h);
    cudaGetSymbolAddress((void**)&h1_h,       g_h1_h);
    cudaGetSymbolAddress((void**)&P,          g_P);
    cudaGetSymbolAddress((void**)&dense,      g_dense);
    cudaGetSymbolAddress((void**)&sparse,     g_sparse);
    cudaGetSymbolAddress((void**)&x,          g_x);
    cudaGetSymbolAddress((void**)&ff,         g_ff);

    cudaFuncSetAttribute(hgemm_nt, cudaFuncAttributeMaxDynamicSharedMemorySize, GEMM_SMEM);

    static cudaStream_t sA = nullptr, sB = nullptr, sC = nullptr;
    static cudaEvent_t evC = nullptr, evA = nullptr, evB = nullptr, evT = nullptr;
    if (!sA) {
        cudaStreamCreateWithFlags(&sA, cudaStreamNonBlocking);
        cudaStreamCreateWithFlags(&sB, cudaStreamNonBlocking);
        cudaStreamCreateWithFlags(&sC, cudaStreamNonBlocking);
        cudaEventCreateWithFlags(&evC, cudaEventDisableTiming);
        cudaEventCreateWithFlags(&evA, cudaEventDisableTiming);
        cudaEventCreateWithFlags(&evB, cudaEventDisableTiming);
        cudaEventCreateWithFlags(&evT, cudaEventDisableTiming);
    }

    // sA: non-critical weight conversion, overlaps the critical path
    convert_rest<<<9216, 256, 0, sA>>>(outp_w, ff1_w, ff2_w, hw_out, hw_f1, hw_f2);

    // main: critical conversion then proj GEMM
    convert_crit<<<8321, 256>>>(in_w, Qp_w, Kp_w, Vp_w, src,
                                in_b, Qp_b, Kp_b, Vp_b, outp_b, lam,
                                hw_pack, src_h, bias_pack, bias_dense, sigbuf);
    hgemm_nt<<<dim3(PROJN / BN, NTOK / BM), 256, GEMM_SMEM>>>(
        src_h, hw_pack, DD, DD, DD, 0, 0,
        src_h, hw_pack, 0, DD, DD, 0, 0,
        bias_pack, proj_h, PROJN, 0, 1.f, 0, 1);
    cudaEventRecord(evC, 0);
    cudaStreamWaitEvent(sA, evC, 0);
    cudaStreamWaitEvent(sB, evC, 0);
    cudaStreamWaitEvent(sC, evC, 0);

    // ---- branch A: flash attention -> dense = sig*(ctx@out^T) + sig*b ----
    flash_attn_kernel<<<dim3(SS / 128, HH, BB), 256, 0, sA>>>(proj_h, sigbuf, ctx_h);
    hgemm_nt<<<dim3(DD / BN, NTOK / BM), 256, GEMM_SMEM, sA>>>(
        ctx_h, hw_out, DD, DD, DD, 0, 0,
        ctx_h, hw_out, 0, DD, DD, 0, 0,
        bias_dense, dense, DD, 0, 1.f, 0, 0);
    cudaEventRecord(evA, sA);

    // ---- branch C: V transpose ----
    transpose_proj_kernel<<<dim3(SS / 32, DD / 32, BB), 256, 0, sC>>>(proj_h, Vt_h);
    cudaEventRecord(evT, sC);

    // ---- branch B: scores -> topk -> sparse = (1-sig)*(P@V) ----
    hgemm_nt<<<dim3(SS / BN, SS / BM, BB), 256, GEMM_SMEM, sB>>>(
        proj_h + 3 * DD, proj_h + 3 * DD + RR, RR, PROJN, PROJN,
        (long)SS * PROJN, (long)SS * PROJN,
        proj_h, proj_h, 0, PROJN, PROJN, 0, 0,
        nullptr, P, SS, (long)SS * SS, 0.125f, 0, 0);
    topk_softmax_kernel<<<NTOK, 256, 0, sB>>>(P, sigbuf, Ph);
    cudaStreamWaitEvent(sB, evT, 0);
    hgemm_nt<<<dim3(DD / BN, SS / BM, BB), 256, GEMM_SMEM, sB>>>(
        Ph, Vt_h, SS, SS, SS, (long)SS * SS, (long)DD * SS,
        Ph, Vt_h, 0, SS, SS, 0, 0,
        nullptr, sparse, DD, (long)SS * DD, 1.f, 0, 0);
    cudaEventRecord(evB, sB);

    // ---- join ----
    cudaStreamWaitEvent(0, evA, 0);
    cudaStreamWaitEvent(0, evB, 0);

    // x = LN1(src + dense + sparse) -> f32 + half
    fuse_ln1_kernel<<<NTOK, 256>>>(src, dense, sparse, ln1_g, ln1_b, x, x_h);
    // h1 = relu(x @ ff1^T + b) -> half
    hgemm_nt<<<dim3(DFFN / BN, NTOK / BM), 256, GEMM_SMEM>>>(
        x_h, hw_f1, DD, DD, DD, 0, 0,
        x_h, hw_f1, 0, DD, DD, 0, 0,
        ff1_b, h1_h, DFFN, 0, 1.f, 1, 1);
    // ff = h1 @ ff2^T + b -> f32
    hgemm_nt<<<dim3(DD / BN, NTOK / BM), 256, GEMM_SMEM>>>(
        h1_h, hw_f2, DFFN, DFFN, DFFN, 0, 0,
        h1_h, hw_f2, 0, DFFN, DFFN, 0, 0,
        ff2_b, ff, DD, 0, 1.f, 0, 0);
    // out = LN2(x + ff)
    ln2_kernel<<<NTOK, 256>>>(x, ff, ln2_g, ln2_b, out);
}